// round 2
// baseline (speedup 1.0000x reference)
#include <cuda_runtime.h>
#include <math.h>
#include <stdint.h>

// Problem dims (fixed by the dataset)
#define NB 32      // batch
#define NS 128     // src seq len
#define NT 19      // decoder steps (T-1)
#define ND 512     // embed dim
#define NH 1024    // hidden
#define NG 4096    // 4*H
#define NK 100     // attn key dim
#define NV 32000   // vocab
#define PSTRIDE (NB*NG)   // per-part z stride

// ------------------------- scratch (device globals; no allocs) ---------------
__device__ float g_src_embed[NS*NB*ND];     // [s][b][d]
__device__ float g_ans_embed[NT*NB*ND];     // [t][b][d]
__device__ float g_xproj[NS*NB*NG];         // [s][b][4H]  (x@Wih + bih + bhh)
__device__ float g_dxe[NT*NB*NG];           // [t][b][4H]
__device__ float g_h[NB*NH];
__device__ float g_c[NB*NH];
__device__ float g_z[4*PSTRIDE];            // partial z sums (up to 4 parts)
__device__ float g_enc_out[NS*NB*NH];       // [s][b][h]
__device__ float g_qkey[NS*NB*NK];          // [s][b][k]
__device__ float g_qval[NS*NB*NH];          // [s][b][h]
__device__ float g_tmp[NB*2048];            // MLP intermediate
__device__ float g_ctx[NB*NH];
__device__ float g_feat[NT*NB*ND];          // [t][b][d]

__device__ __forceinline__ float sigmf_(float x) { return 1.0f/(1.0f+expf(-x)); }

// ------------------------- embedding gather ---------------------------------
// out[(step*NB+b)*ND + d] = embed[seq[b*seq_stride+step]*ND + d]
__global__ void k_gather(const int* __restrict__ seq, int seq_stride,
                         const float* __restrict__ embed, float* __restrict__ out)
{
    int row = blockIdx.x;          // step*NB + b
    int st  = row / NB;
    int b   = row % NB;
    int tok = seq[b*seq_stride + st];
    const float4* src = (const float4*)(embed + (size_t)tok*ND);
    float4*       dst = (float4*)(out + (size_t)row*ND);
    dst[threadIdx.x] = src[threadIdx.x];   // 128 threads x float4 = 512 floats
}

__global__ void k_init_hc()
{
    int i = blockIdx.x*blockDim.x + threadIdx.x;
    if (i < NB*NH) { g_h[i] = 0.0f; g_c[i] = 0.0f; }
}

// ------------------------- generic tiled SGEMM (C = act(A@W^T + b1 [+b2])) ---
// BM=64, BN=64, BK=16, 256 threads, 4x4 register tile.
// out_map==1 remaps row m=(t*32+b) -> (b*19+t)  (for final logits)
__global__ __launch_bounds__(256)
void k_sgemm(int M, int N, int K,
             const float* __restrict__ A, int lda,
             const float* __restrict__ W, int ldw,
             const float* __restrict__ bias1, const float* __restrict__ bias2,
             float* __restrict__ C, int ldc, int act, int out_map)
{
    __shared__ float As[16][68];
    __shared__ float Ws[16][68];
    int tid = threadIdx.x;
    int m0 = blockIdx.y*64, n0 = blockIdx.x*64;
    int lr = tid >> 2;           // 0..63
    int lc = (tid & 3) << 2;     // 0,4,8,12
    int ty = tid >> 4;           // 0..15 (m)
    int tx = tid & 15;           // 0..15 (n)
    float acc[4][4] = {};

    for (int k0 = 0; k0 < K; k0 += 16) {
        float4 a4 = make_float4(0.f,0.f,0.f,0.f);
        float4 w4 = make_float4(0.f,0.f,0.f,0.f);
        if (m0+lr < M) a4 = *(const float4*)(A + (size_t)(m0+lr)*lda + k0 + lc);
        if (n0+lr < N) w4 = *(const float4*)(W + (size_t)(n0+lr)*ldw + k0 + lc);
        __syncthreads();
        As[lc+0][lr]=a4.x; As[lc+1][lr]=a4.y; As[lc+2][lr]=a4.z; As[lc+3][lr]=a4.w;
        Ws[lc+0][lr]=w4.x; Ws[lc+1][lr]=w4.y; Ws[lc+2][lr]=w4.z; Ws[lc+3][lr]=w4.w;
        __syncthreads();
#pragma unroll
        for (int k = 0; k < 16; k++) {
            float4 av = *(const float4*)&As[k][ty*4];
            float4 wv = *(const float4*)&Ws[k][tx*4];
            float am[4] = {av.x, av.y, av.z, av.w};
            float wn[4] = {wv.x, wv.y, wv.z, wv.w};
#pragma unroll
            for (int i = 0; i < 4; i++)
#pragma unroll
                for (int j = 0; j < 4; j++)
                    acc[i][j] += am[i]*wn[j];
        }
    }

#pragma unroll
    for (int i = 0; i < 4; i++) {
        int m = m0 + ty*4 + i;
        if (m >= M) continue;
        int mo = m;
        if (out_map == 1) mo = (m % 32)*NT + (m / 32);
#pragma unroll
        for (int j = 0; j < 4; j++) {
            int n = n0 + tx*4 + j;
            if (n >= N) continue;
            float v = acc[i][j] + bias1[n];
            if (bias2) v += bias2[n];
            if (act == 1)      v = tanhf(v);
            else if (act == 2) v = fmaxf(v, 0.0f);
            C[(size_t)mo*ldc + n] = v;
        }
    }
}

// ------------------------- recurrent GEMM partials --------------------------
// Z[p][b][n] = sum_{k in half} A_term[b][k] * W_term[n][koff+k]
// grid = (N/32, nparts).  part p: term = p>>1, k-half = p&1 (K=1024 per term).
// M is always 32 (batch), BN=32, BK=32, 256 threads, 2x2 register tile.
__global__ __launch_bounds__(256)
void k_recgemm(const float* __restrict__ A1, int lda1,
               const float* __restrict__ W1, int ldw1, int koff1,
               const float* __restrict__ A2, int lda2,
               const float* __restrict__ W2, int ldw2, int koff2,
               int N, float* __restrict__ Z)
{
    __shared__ float As[32][34];
    __shared__ float Ws[32][34];
    int tid = threadIdx.x;
    int p = blockIdx.y;
    const float* A; const float* W; int lda, ldw, koff;
    if (p < 2) { A = A1; W = W1; lda = lda1; ldw = ldw1; koff = koff1; }
    else       { A = A2; W = W2; lda = lda2; ldw = ldw2; koff = koff2; }
    int kh = (p & 1) * 512;
    int n0 = blockIdx.x * 32;
    int lr = tid >> 3;          // 0..31
    int lc = (tid & 7) << 2;    // 0..28
    int ty = tid >> 4;          // 0..15 (m pairs)
    int tx = tid & 15;          // 0..15 (n pairs)
    float a00 = 0.f, a01 = 0.f, a10 = 0.f, a11 = 0.f;

    for (int k0 = 0; k0 < 512; k0 += 32) {
        float4 av = *(const float4*)(A + (size_t)lr*lda + kh + k0 + lc);
        float4 wv = *(const float4*)(W + (size_t)(n0+lr)*ldw + koff + kh + k0 + lc);
        __syncthreads();
        As[lc+0][lr]=av.x; As[lc+1][lr]=av.y; As[lc+2][lr]=av.z; As[lc+3][lr]=av.w;
        Ws[lc+0][lr]=wv.x; Ws[lc+1][lr]=wv.y; Ws[lc+2][lr]=wv.z; Ws[lc+3][lr]=wv.w;
        __syncthreads();
#pragma unroll
        for (int k = 0; k < 32; k++) {
            float2 a = *(const float2*)&As[k][ty*2];
            float2 w = *(const float2*)&Ws[k][tx*2];
            a00 += a.x*w.x; a01 += a.x*w.y;
            a10 += a.y*w.x; a11 += a.y*w.y;
        }
    }

    float* zp = Z + (size_t)p*PSTRIDE;
    int m = ty*2, n = n0 + tx*2;
    zp[(size_t)m*N + n]       = a00;
    zp[(size_t)m*N + n+1]     = a01;
    zp[(size_t)(m+1)*N + n]   = a10;
    zp[(size_t)(m+1)*N + n+1] = a11;
}

// ------------------------- LSTM cells ---------------------------------------
__global__ void k_enc_cell(int s, const int* __restrict__ lengths)
{
    int gid = blockIdx.x*256 + threadIdx.x;     // 0..32767
    int b = gid >> 10, k = gid & 1023;
    int base = b*NG + k;
    const float* xp = g_xproj + (size_t)(s*NB + b)*NG + k;
    float zi = g_z[base]        + g_z[PSTRIDE + base]        + xp[0];
    float zf = g_z[base+1024]   + g_z[PSTRIDE + base+1024]   + xp[1024];
    float zg = g_z[base+2048]   + g_z[PSTRIDE + base+2048]   + xp[2048];
    float zo = g_z[base+3072]   + g_z[PSTRIDE + base+3072]   + xp[3072];
    float c_old = g_c[gid], h_old = g_h[gid];
    float cn = sigmf_(zf)*c_old + sigmf_(zi)*tanhf(zg);
    float hn = sigmf_(zo)*tanhf(cn);
    bool m = s < lengths[b];
    g_h[gid] = m ? hn : h_old;
    g_c[gid] = m ? cn : c_old;
    g_enc_out[(size_t)(s*NB + b)*NH + k] = m ? hn : 0.0f;
}

__global__ void k_dec_cell(int t)
{
    int gid = blockIdx.x*256 + threadIdx.x;
    int b = gid >> 10, k = gid & 1023;
    int base = b*NG + k;
    const float* xp = g_dxe + (size_t)(t*NB + b)*NG + k;
    float zi = xp[0],   zf = xp[1024], zg = xp[2048], zo = xp[3072];
#pragma unroll
    for (int p = 0; p < 4; p++) {
        const float* zp = g_z + (size_t)p*PSTRIDE + base;
        zi += zp[0]; zf += zp[1024]; zg += zp[2048]; zo += zp[3072];
    }
    float cn = sigmf_(zf)*g_c[gid] + sigmf_(zi)*tanhf(zg);
    float hn = sigmf_(zo)*tanhf(cn);
    g_h[gid] = hn;
    g_c[gid] = cn;
}

// ------------------------- fused attention (per decoder step) ---------------
// block b: a_key = tanh(h@ak_W^T+ak_b); energy over S; masked softmax; context.
__global__ __launch_bounds__(256)
void k_attn(const float* __restrict__ ak_W, const float* __restrict__ ak_b,
            const int* __restrict__ lengths)
{
    int b = blockIdx.x;
    int tid = threadIdx.x;
    __shared__ float sh[NH];
    __shared__ float sak[NK];
    __shared__ float se[NS];
    __shared__ float sred[256];

    for (int i = tid; i < NH; i += 256) sh[i] = g_h[b*NH + i];
    __syncthreads();

    // a_key (100 dots over K=1024)
    if (tid < NK) {
        const float* wr = ak_W + (size_t)tid*NH;
        float acc0 = 0.f, acc1 = 0.f;
        for (int k = 0; k < NH; k += 8) {
            float4 w0 = *(const float4*)&wr[k];
            float4 w1 = *(const float4*)&wr[k+4];
            float4 h0 = *(const float4*)&sh[k];
            float4 h1 = *(const float4*)&sh[k+4];
            acc0 += w0.x*h0.x + w0.y*h0.y + w0.z*h0.z + w0.w*h0.w;
            acc1 += w1.x*h1.x + w1.y*h1.y + w1.z*h1.z + w1.w*h1.w;
        }
        sak[tid] = tanhf(acc0 + acc1 + ak_b[tid]);
    }
    __syncthreads();

    int len = lengths[b];
    // energy + mask
    if (tid < NS) {
        const float* qr = g_qkey + (size_t)(tid*NB + b)*NK;
        float acc = 0.f;
        for (int k = 0; k < NK; k++) acc += qr[k]*sak[k];
        se[tid] = (tid < len) ? acc : -INFINITY;
    }
    __syncthreads();

    // max reduce
    sred[tid] = (tid < NS) ? se[tid] : -INFINITY;
    __syncthreads();
    for (int off = 128; off >= 1; off >>= 1) {
        if (tid < off) sred[tid] = fmaxf(sred[tid], sred[tid+off]);
        __syncthreads();
    }
    float mx = sred[0];
    __syncthreads();

    // exp + sum reduce
    float ex = (tid < NS) ? expf(se[tid] - mx) : 0.0f;
    sred[tid] = ex;
    __syncthreads();
    for (int off = 128; off >= 1; off >>= 1) {
        if (tid < off) sred[tid] += sred[tid+off];
        __syncthreads();
    }
    float inv = 1.0f / sred[0];
    __syncthreads();
    if (tid < NS) se[tid] = ex * inv;
    __syncthreads();

    // context[b][h] = sum_s w[s] * q_value[s][b][h]
    for (int hh = tid; hh < NH; hh += 256) {
        float acc = 0.f;
        for (int s = 0; s < NS; s++)
            acc += se[s] * g_qval[(size_t)(s*NB + b)*NH + hh];
        g_ctx[b*NH + hh] = acc;
    }
}

// ------------------------- feat reduce: sum 4 partials + bias ---------------
__global__ void k_feat_sum(int t, const float* __restrict__ out_b)
{
    int gid = blockIdx.x*256 + threadIdx.x;   // 32*512
    int b = gid >> 9, n = gid & 511;
    float v = out_b[n];
#pragma unroll
    for (int p = 0; p < 4; p++)
        v += g_z[(size_t)p*PSTRIDE + b*ND + n];
    g_feat[(size_t)(t*NB + b)*ND + n] = v;
}

// =============================================================================
extern "C" void kernel_launch(void* const* d_in, const int* in_sizes, int n_in,
                              void* d_out, int out_size)
{
    const float* embed    = (const float*)d_in[0];
    const float* enc_Wih  = (const float*)d_in[1];
    const float* enc_Whh  = (const float*)d_in[2];
    const float* enc_bih  = (const float*)d_in[3];
    const float* enc_bhh  = (const float*)d_in[4];
    const float* dec_Wih  = (const float*)d_in[5];
    const float* dec_Whh  = (const float*)d_in[6];
    const float* dec_bih  = (const float*)d_in[7];
    const float* dec_bhh  = (const float*)d_in[8];
    const float* qk_W     = (const float*)d_in[9];
    const float* qk_b     = (const float*)d_in[10];
    const float* qv_W     = (const float*)d_in[11];
    const float* qv_b     = (const float*)d_in[12];
    const float* ak_W     = (const float*)d_in[13];
    const float* ak_b     = (const float*)d_in[14];
    const float* out_W    = (const float*)d_in[15];
    const float* out_b    = (const float*)d_in[16];
    const float* wd_b     = (const float*)d_in[17];
    const float* hfc1_W   = (const float*)d_in[18];
    const float* hfc1_b   = (const float*)d_in[19];
    const float* hfc2_W   = (const float*)d_in[20];
    const float* hfc2_b   = (const float*)d_in[21];
    const float* cfc1_W   = (const float*)d_in[22];
    const float* cfc1_b   = (const float*)d_in[23];
    const float* cfc2_W   = (const float*)d_in[24];
    const float* cfc2_b   = (const float*)d_in[25];
    const int*   src_seqs = (const int*)d_in[26];
    const int*   src_len  = (const int*)d_in[27];
    const int*   trg_seqs = (const int*)d_in[28];
    float* out = (float*)d_out;

    float *d_src_embed, *d_ans_embed, *d_xproj, *d_dxe, *d_h, *d_c, *d_z;
    float *d_enc_out, *d_qkey, *d_qval, *d_tmp, *d_ctx, *d_feat;
    cudaGetSymbolAddress((void**)&d_src_embed, g_src_embed);
    cudaGetSymbolAddress((void**)&d_ans_embed, g_ans_embed);
    cudaGetSymbolAddress((void**)&d_xproj,     g_xproj);
    cudaGetSymbolAddress((void**)&d_dxe,       g_dxe);
    cudaGetSymbolAddress((void**)&d_h,         g_h);
    cudaGetSymbolAddress((void**)&d_c,         g_c);
    cudaGetSymbolAddress((void**)&d_z,         g_z);
    cudaGetSymbolAddress((void**)&d_enc_out,   g_enc_out);
    cudaGetSymbolAddress((void**)&d_qkey,      g_qkey);
    cudaGetSymbolAddress((void**)&d_qval,      g_qval);
    cudaGetSymbolAddress((void**)&d_tmp,       g_tmp);
    cudaGetSymbolAddress((void**)&d_ctx,       g_ctx);
    cudaGetSymbolAddress((void**)&d_feat,      g_feat);

    // ---- precompute ----
    k_gather<<<NS*NB, 128>>>(src_seqs, NS, embed, d_src_embed);
    k_gather<<<NT*NB, 128>>>(trg_seqs, 20, embed, d_ans_embed);
    k_init_hc<<<(NB*NH + 255)/256, 256>>>();

    // x_proj = src_embed @ enc_Wih^T + enc_bih + enc_bhh   (4096 x 4096, K=512)
    k_sgemm<<<dim3(NG/64, (NS*NB)/64), 256>>>(NS*NB, NG, ND,
        d_src_embed, ND, enc_Wih, ND, enc_bih, enc_bhh, d_xproj, NG, 0, 0);
    // dxe = ans_embed @ dec_Wih[:, :512]^T + dec_bih + dec_bhh (608 x 4096, K=512)
    k_sgemm<<<dim3(NG/64, (NT*NB + 63)/64), 256>>>(NT*NB, NG, ND,
        d_ans_embed, ND, dec_Wih, ND + NH, dec_bih, dec_bhh, d_dxe, NG, 0, 0);

    // ---- encoder recurrence ----
    for (int s = 0; s < NS; s++) {
        k_recgemm<<<dim3(NG/32, 2), 256>>>(d_h, NH, enc_Whh, NH, 0,
                                           d_h, NH, enc_Whh, NH, 0, NG, d_z);
        k_enc_cell<<<(NB*NH)/256, 256>>>(s, src_len);
    }

    // ---- bridge MLPs: dh, dc ----
    k_sgemm<<<dim3(2048/64, 1), 256>>>(NB, 2048, NH, d_h, NH, hfc1_W, NH,
                                       hfc1_b, nullptr, d_tmp, 2048, 2, 0);
    k_sgemm<<<dim3(NH/64, 1), 256>>>(NB, NH, 2048, d_tmp, 2048, hfc2_W, 2048,
                                     hfc2_b, nullptr, d_h, NH, 0, 0);
    k_sgemm<<<dim3(2048/64, 1), 256>>>(NB, 2048, NH, d_c, NH, cfc1_W, NH,
                                       cfc1_b, nullptr, d_tmp, 2048, 2, 0);
    k_sgemm<<<dim3(NH/64, 1), 256>>>(NB, NH, 2048, d_tmp, 2048, cfc2_W, 2048,
                                     cfc2_b, nullptr, d_c, NH, 0, 0);

    // ---- attention precompute over all source positions ----
    k_sgemm<<<dim3((NK + 63)/64, (NS*NB)/64), 256>>>(NS*NB, NK, NH,
        d_enc_out, NH, qk_W, NH, qk_b, nullptr, d_qkey, NK, 1, 0);
    k_sgemm<<<dim3(NH/64, (NS*NB)/64), 256>>>(NS*NB, NH, NH,
        d_enc_out, NH, qv_W, NH, qv_b, nullptr, d_qval, NH, 0, 0);

    // ---- decoder recurrence ----
    for (int t = 0; t < NT; t++) {
        k_attn<<<NB, 256>>>(ak_W, ak_b, src_len);
        // z partials: term0 = ctx @ dec_Wih[:,512:]^T, term1 = h @ dec_Whh^T
        k_recgemm<<<dim3(NG/32, 4), 256>>>(d_ctx, NH, dec_Wih, ND + NH, ND,
                                           d_h,   NH, dec_Whh, NH, 0, NG, d_z);
        k_dec_cell<<<(NB*NH)/256, 256>>>(t);
        // feat partials: [h, ctx] @ out_W^T
        k_recgemm<<<dim3(ND/32, 4), 256>>>(d_h,   NH, out_W, 2*NH, 0,
                                           d_ctx, NH, out_W, 2*NH, NH, ND, d_z);
        k_feat_sum<<<(NB*ND)/256, 256>>>(t, out_b);
    }

    // ---- final logits: feat(608x512) @ embed^T(32000x512) + wd_b ----
    k_sgemm<<<dim3(NV/64, (NT*NB + 63)/64), 256>>>(NT*NB, NV, ND,
        d_feat, ND, embed, ND, wd_b, nullptr, out, NV, 0, 1);

    (void)in_sizes; (void)n_in; (void)out_size;
}

// round 3
// speedup vs baseline: 1.1137x; 1.1137x over previous
#include <cuda_runtime.h>
#include <math.h>
#include <stdint.h>

// Problem dims (fixed by the dataset)
#define NB 32      // batch
#define NS 128     // src seq len
#define NT 19      // decoder steps (T-1)
#define ND 512     // embed dim
#define NH 1024    // hidden
#define NG 4096    // 4*H
#define NK 100     // attn key dim
#define NV 32000   // vocab
#define PSTRIDE (NB*NG)   // per-part z stride
#define ENC_NBLK 128

// ------------------------- scratch (device globals; no allocs) ---------------
__device__ float g_src_embed[NS*NB*ND];     // [s][b][d]
__device__ float g_ans_embed[NT*NB*ND];     // [t][b][d]
__device__ float g_xproj[NS*NG*NB];         // [s][n][b]  (x@Wih + bih + bhh), transposed
__device__ float g_dxe[NT*NB*NG];           // [t][b][4H]
__device__ float g_h[NB*NH];
__device__ float g_c[NB*NH];
__device__ float g_hbuf[2*NB*NH];           // encoder h ping-pong
__device__ float g_z[4*PSTRIDE];            // partial z sums (up to 4 parts)
__device__ float g_enc_out[NS*NB*NH];       // [s][b][h]
__device__ float g_qkey[NS*NB*NK];          // [s][b][k]
__device__ float g_qval[NS*NB*NH];          // [s][b][h]
__device__ float g_tmp[NB*2048];            // MLP intermediate
__device__ float g_ctx[NB*NH];
__device__ float g_feat[NT*NB*ND];          // [t][b][d]

__device__ unsigned g_barcnt = 0;
__device__ unsigned g_bargen = 0;

__device__ __forceinline__ float sigmf_(float x) { return 1.0f/(1.0f+expf(-x)); }

// ------------------------- embedding gather ---------------------------------
__global__ void k_gather(const int* __restrict__ seq, int seq_stride,
                         const float* __restrict__ embed, float* __restrict__ out)
{
    int row = blockIdx.x;          // step*NB + b
    int st  = row / NB;
    int b   = row % NB;
    int tok = seq[b*seq_stride + st];
    const float4* src = (const float4*)(embed + (size_t)tok*ND);
    float4*       dst = (float4*)(out + (size_t)row*ND);
    dst[threadIdx.x] = src[threadIdx.x];   // 128 threads x float4 = 512 floats
}

// ------------------------- generic tiled SGEMM (C = act(A@W^T + b1 [+b2])) ---
// BM=64, BN=64, BK=16, 256 threads, 4x4 register tile.
// out_map==1 remaps row m=(t*32+b) -> (b*19+t)  (final logits)
// out_map==2 writes C[((m>>5)*NG + n)*32 + (m&31)]  (xproj transposed [s][n][b])
__global__ __launch_bounds__(256)
void k_sgemm(int M, int N, int K,
             const float* __restrict__ A, int lda,
             const float* __restrict__ W, int ldw,
             const float* __restrict__ bias1, const float* __restrict__ bias2,
             float* __restrict__ C, int ldc, int act, int out_map)
{
    __shared__ float As[16][68];
    __shared__ float Ws[16][68];
    int tid = threadIdx.x;
    int m0 = blockIdx.y*64, n0 = blockIdx.x*64;
    int lr = tid >> 2;           // 0..63
    int lc = (tid & 3) << 2;     // 0,4,8,12
    int ty = tid >> 4;           // 0..15 (m)
    int tx = tid & 15;           // 0..15 (n)
    float acc[4][4] = {};

    for (int k0 = 0; k0 < K; k0 += 16) {
        float4 a4 = make_float4(0.f,0.f,0.f,0.f);
        float4 w4 = make_float4(0.f,0.f,0.f,0.f);
        if (m0+lr < M) a4 = *(const float4*)(A + (size_t)(m0+lr)*lda + k0 + lc);
        if (n0+lr < N) w4 = *(const float4*)(W + (size_t)(n0+lr)*ldw + k0 + lc);
        __syncthreads();
        As[lc+0][lr]=a4.x; As[lc+1][lr]=a4.y; As[lc+2][lr]=a4.z; As[lc+3][lr]=a4.w;
        Ws[lc+0][lr]=w4.x; Ws[lc+1][lr]=w4.y; Ws[lc+2][lr]=w4.z; Ws[lc+3][lr]=w4.w;
        __syncthreads();
#pragma unroll
        for (int k = 0; k < 16; k++) {
            float4 av = *(const float4*)&As[k][ty*4];
            float4 wv = *(const float4*)&Ws[k][tx*4];
            float am[4] = {av.x, av.y, av.z, av.w};
            float wn[4] = {wv.x, wv.y, wv.z, wv.w};
#pragma unroll
            for (int i = 0; i < 4; i++)
#pragma unroll
                for (int j = 0; j < 4; j++)
                    acc[i][j] += am[i]*wn[j];
        }
    }

#pragma unroll
    for (int i = 0; i < 4; i++) {
        int m = m0 + ty*4 + i;
        if (m >= M) continue;
#pragma unroll
        for (int j = 0; j < 4; j++) {
            int n = n0 + tx*4 + j;
            if (n >= N) continue;
            float v = acc[i][j] + bias1[n];
            if (bias2) v += bias2[n];
            if (act == 1)      v = tanhf(v);
            else if (act == 2) v = fmaxf(v, 0.0f);
            if (out_map == 1)
                C[(size_t)((m % 32)*NT + (m / 32))*ldc + n] = v;
            else if (out_map == 2)
                C[((size_t)(m >> 5)*NG + n)*32 + (m & 31)] = v;
            else
                C[(size_t)m*ldc + n] = v;
        }
    }
}

// ------------------------- persistent encoder -------------------------------
// 128 blocks x 256 threads, 1 block/SM (smem-limited). Block j owns hidden
// units u in [j*8, j*8+8), i.e. 32 gate rows n = g*1024 + j*8 + uu.
// Whh slice transposed in SMEM (sWt[k][r], 147KB); h ping-pongs via g_hbuf.
// Thread map (GEMM role): rq=tid&7 (4 rows), bq=(tid>>3)&7 (4 batch), ks=tid>>6
// (4-way k split; warp-uniform). Cell role: cu=tid>>5 (unit), cb=tid&31 (batch).
__device__ __forceinline__ void gridbar()
{
    __syncthreads();
    if (threadIdx.x == 0) {
        __threadfence();
        volatile unsigned* vgen = &g_bargen;
        unsigned gen = *vgen;
        if (atomicAdd(&g_barcnt, 1u) == ENC_NBLK - 1) {
            g_barcnt = 0;
            __threadfence();
            atomicAdd(&g_bargen, 1u);
        } else {
            while (*vgen == gen) { __nanosleep(32); }
        }
        __threadfence();
    }
    __syncthreads();
}

__global__ void __launch_bounds__(256, 1)
k_enc_persist(const float* __restrict__ Whh, const int* __restrict__ lengths)
{
    extern __shared__ float sm[];
    float* sWt = sm;                        // [1024][36]
    float* sHs = sm + 1024*36;              // [128][36]
    float* sZs = sm + 1024*36 + 128*36;     // [4][32][33]

    int tid = threadIdx.x;
    int u0  = blockIdx.x * 8;

    // Load + transpose Whh slice into SMEM (once)
    for (int r = 0; r < 32; r++) {
        int n = (r >> 3)*NH + u0 + (r & 7);
        float4 w4 = *(const float4*)&Whh[(size_t)n*NH + 4*tid];
        sWt[(4*tid+0)*36 + r] = w4.x;
        sWt[(4*tid+1)*36 + r] = w4.y;
        sWt[(4*tid+2)*36 + r] = w4.z;
        sWt[(4*tid+3)*36 + r] = w4.w;
    }

    int cb = tid & 31;            // cell batch
    int cu = tid >> 5;            // cell unit (0..7)
    int mylen = lengths[cb];
    float creg = 0.0f;
    float hreg = 0.0f;

    // init read buffer (buf 0) to zero: each thread owns one (b,u) slot
    g_hbuf[cb*NH + u0 + cu] = 0.0f;

    int rq = tid & 7;
    int bq = (tid >> 3) & 7;
    int ks = tid >> 6;
    int lb = tid >> 3;            // loader batch row (0..31)
    int lq = tid & 7;             // loader k-quad

    gridbar();                    // all of buf0 initialized

    for (int s = 0; s < NS; s++) {
        const float* hin  = g_hbuf + (s & 1)*(NB*NH);
        float*       hout = g_hbuf + ((s & 1) ^ 1)*(NB*NH);

        float acc[4][4] = {};
        for (int kc = 0; kc < NH; kc += 128) {
            // load h chunk -> sHs[kk][b]  (L2 reads: cross-SM data)
            #pragma unroll
            for (int p = 0; p < 4; p++) {
                int kk = 4*(lq + 8*p);
                float4 h4 = __ldcg((const float4*)&hin[lb*NH + kc + kk]);
                sHs[(kk+0)*36 + lb] = h4.x;
                sHs[(kk+1)*36 + lb] = h4.y;
                sHs[(kk+2)*36 + lb] = h4.z;
                sHs[(kk+3)*36 + lb] = h4.w;
            }
            __syncthreads();
            for (int kb = 0; kb < 128; kb += 16) {
                int k = kb + 4*ks;
                #pragma unroll
                for (int kk2 = 0; kk2 < 4; kk2++) {
                    float4 wv = *(const float4*)&sWt[(kc+k+kk2)*36 + 4*rq];
                    float4 hv = *(const float4*)&sHs[(k+kk2)*36 + 4*bq];
                    float wa[4] = {wv.x, wv.y, wv.z, wv.w};
                    float hb[4] = {hv.x, hv.y, hv.z, hv.w};
                    #pragma unroll
                    for (int i = 0; i < 4; i++)
                        #pragma unroll
                        for (int j = 0; j < 4; j++)
                            acc[i][j] += wa[i]*hb[j];
                }
            }
            __syncthreads();
        }

        // stage z partials
        #pragma unroll
        for (int i = 0; i < 4; i++)
            #pragma unroll
            for (int j = 0; j < 4; j++)
                sZs[(ks*32 + 4*rq + i)*33 + 4*bq + j] = acc[i][j];
        __syncthreads();

        // LSTM cell for (cb, u0+cu); xproj layout [s][n][b]
        const float* xp = g_xproj + ((size_t)s*NG + u0 + cu)*32 + cb;
        float zg4[4];
        #pragma unroll
        for (int g = 0; g < 4; g++) {
            float v = xp[(size_t)g*NH*32];
            #pragma unroll
            for (int q = 0; q < 4; q++) v += sZs[(q*32 + g*8 + cu)*33 + cb];
            zg4[g] = v;
        }
        float cn = sigmf_(zg4[1])*creg + sigmf_(zg4[0])*tanhf(zg4[2]);
        float hn = sigmf_(zg4[3])*tanhf(cn);
        bool msk = (s < mylen);
        creg = msk ? cn : creg;
        hreg = msk ? hn : hreg;
        hout[cb*NH + u0 + cu] = hreg;
        g_enc_out[((size_t)(s*NB + cb))*NH + u0 + cu] = msk ? hreg : 0.0f;

        gridbar();
    }

    // export final h, c for the bridge MLPs
    g_h[cb*NH + u0 + cu] = hreg;
    g_c[cb*NH + u0 + cu] = creg;
}

// ------------------------- decoder recurrent GEMM partials ------------------
__global__ __launch_bounds__(256)
void k_recgemm(const float* __restrict__ A1, int lda1,
               const float* __restrict__ W1, int ldw1, int koff1,
               const float* __restrict__ A2, int lda2,
               const float* __restrict__ W2, int ldw2, int koff2,
               int N, float* __restrict__ Z)
{
    __shared__ float As[32][34];
    __shared__ float Ws[32][34];
    int tid = threadIdx.x;
    int p = blockIdx.y;
    const float* A; const float* W; int lda, ldw, koff;
    if (p < 2) { A = A1; W = W1; lda = lda1; ldw = ldw1; koff = koff1; }
    else       { A = A2; W = W2; lda = lda2; ldw = ldw2; koff = koff2; }
    int kh = (p & 1) * 512;
    int n0 = blockIdx.x * 32;
    int lr = tid >> 3;
    int lc = (tid & 7) << 2;
    int ty = tid >> 4;
    int tx = tid & 15;
    float a00 = 0.f, a01 = 0.f, a10 = 0.f, a11 = 0.f;

    for (int k0 = 0; k0 < 512; k0 += 32) {
        float4 av = *(const float4*)(A + (size_t)lr*lda + kh + k0 + lc);
        float4 wv = *(const float4*)(W + (size_t)(n0+lr)*ldw + koff + kh + k0 + lc);
        __syncthreads();
        As[lc+0][lr]=av.x; As[lc+1][lr]=av.y; As[lc+2][lr]=av.z; As[lc+3][lr]=av.w;
        Ws[lc+0][lr]=wv.x; Ws[lc+1][lr]=wv.y; Ws[lc+2][lr]=wv.z; Ws[lc+3][lr]=wv.w;
        __syncthreads();
#pragma unroll
        for (int k = 0; k < 32; k++) {
            float2 a = *(const float2*)&As[k][ty*2];
            float2 w = *(const float2*)&Ws[k][tx*2];
            a00 += a.x*w.x; a01 += a.x*w.y;
            a10 += a.y*w.x; a11 += a.y*w.y;
        }
    }

    float* zp = Z + (size_t)p*PSTRIDE;
    int m = ty*2, n = n0 + tx*2;
    zp[(size_t)m*N + n]       = a00;
    zp[(size_t)m*N + n+1]     = a01;
    zp[(size_t)(m+1)*N + n]   = a10;
    zp[(size_t)(m+1)*N + n+1] = a11;
}

__global__ void k_dec_cell(int t)
{
    int gid = blockIdx.x*256 + threadIdx.x;
    int b = gid >> 10, k = gid & 1023;
    int base = b*NG + k;
    const float* xp = g_dxe + (size_t)(t*NB + b)*NG + k;
    float zi = xp[0],   zf = xp[1024], zg = xp[2048], zo = xp[3072];
#pragma unroll
    for (int p = 0; p < 4; p++) {
        const float* zp = g_z + (size_t)p*PSTRIDE + base;
        zi += zp[0]; zf += zp[1024]; zg += zp[2048]; zo += zp[3072];
    }
    float cn = sigmf_(zf)*g_c[gid] + sigmf_(zi)*tanhf(zg);
    float hn = sigmf_(zo)*tanhf(cn);
    g_h[gid] = hn;
    g_c[gid] = cn;
}

// ------------------------- fused attention (per decoder step) ---------------
__global__ __launch_bounds__(256)
void k_attn(const float* __restrict__ ak_W, const float* __restrict__ ak_b,
            const int* __restrict__ lengths)
{
    int b = blockIdx.x;
    int tid = threadIdx.x;
    __shared__ float sh[NH];
    __shared__ float sak[NK];
    __shared__ float se[NS];
    __shared__ float sred[256];

    for (int i = tid; i < NH; i += 256) sh[i] = g_h[b*NH + i];
    __syncthreads();

    if (tid < NK) {
        const float* wr = ak_W + (size_t)tid*NH;
        float acc0 = 0.f, acc1 = 0.f;
        for (int k = 0; k < NH; k += 8) {
            float4 w0 = *(const float4*)&wr[k];
            float4 w1 = *(const float4*)&wr[k+4];
            float4 h0 = *(const float4*)&sh[k];
            float4 h1 = *(const float4*)&sh[k+4];
            acc0 += w0.x*h0.x + w0.y*h0.y + w0.z*h0.z + w0.w*h0.w;
            acc1 += w1.x*h1.x + w1.y*h1.y + w1.z*h1.z + w1.w*h1.w;
        }
        sak[tid] = tanhf(acc0 + acc1 + ak_b[tid]);
    }
    __syncthreads();

    int len = lengths[b];
    if (tid < NS) {
        const float* qr = g_qkey + (size_t)(tid*NB + b)*NK;
        float acc = 0.f;
        for (int k = 0; k < NK; k++) acc += qr[k]*sak[k];
        se[tid] = (tid < len) ? acc : -INFINITY;
    }
    __syncthreads();

    sred[tid] = (tid < NS) ? se[tid] : -INFINITY;
    __syncthreads();
    for (int off = 128; off >= 1; off >>= 1) {
        if (tid < off) sred[tid] = fmaxf(sred[tid], sred[tid+off]);
        __syncthreads();
    }
    float mx = sred[0];
    __syncthreads();

    float ex = (tid < NS) ? expf(se[tid] - mx) : 0.0f;
    sred[tid] = ex;
    __syncthreads();
    for (int off = 128; off >= 1; off >>= 1) {
        if (tid < off) sred[tid] += sred[tid+off];
        __syncthreads();
    }
    float inv = 1.0f / sred[0];
    __syncthreads();
    if (tid < NS) se[tid] = ex * inv;
    __syncthreads();

    for (int hh = tid; hh < NH; hh += 256) {
        float acc = 0.f;
        for (int s = 0; s < NS; s++)
            acc += se[s] * g_qval[(size_t)(s*NB + b)*NH + hh];
        g_ctx[b*NH + hh] = acc;
    }
}

__global__ void k_feat_sum(int t, const float* __restrict__ out_b)
{
    int gid = blockIdx.x*256 + threadIdx.x;   // 32*512
    int b = gid >> 9, n = gid & 511;
    float v = out_b[n];
#pragma unroll
    for (int p = 0; p < 4; p++)
        v += g_z[(size_t)p*PSTRIDE + b*ND + n];
    g_feat[(size_t)(t*NB + b)*ND + n] = v;
}

// =============================================================================
extern "C" void kernel_launch(void* const* d_in, const int* in_sizes, int n_in,
                              void* d_out, int out_size)
{
    const float* embed    = (const float*)d_in[0];
    const float* enc_Wih  = (const float*)d_in[1];
    const float* enc_Whh  = (const float*)d_in[2];
    const float* enc_bih  = (const float*)d_in[3];
    const float* enc_bhh  = (const float*)d_in[4];
    const float* dec_Wih  = (const float*)d_in[5];
    const float* dec_Whh  = (const float*)d_in[6];
    const float* dec_bih  = (const float*)d_in[7];
    const float* dec_bhh  = (const float*)d_in[8];
    const float* qk_W     = (const float*)d_in[9];
    const float* qk_b     = (const float*)d_in[10];
    const float* qv_W     = (const float*)d_in[11];
    const float* qv_b     = (const float*)d_in[12];
    const float* ak_W     = (const float*)d_in[13];
    const float* ak_b     = (const float*)d_in[14];
    const float* out_W    = (const float*)d_in[15];
    const float* out_b    = (const float*)d_in[16];
    const float* wd_b     = (const float*)d_in[17];
    const float* hfc1_W   = (const float*)d_in[18];
    const float* hfc1_b   = (const float*)d_in[19];
    const float* hfc2_W   = (const float*)d_in[20];
    const float* hfc2_b   = (const float*)d_in[21];
    const float* cfc1_W   = (const float*)d_in[22];
    const float* cfc1_b   = (const float*)d_in[23];
    const float* cfc2_W   = (const float*)d_in[24];
    const float* cfc2_b   = (const float*)d_in[25];
    const int*   src_seqs = (const int*)d_in[26];
    const int*   src_len  = (const int*)d_in[27];
    const int*   trg_seqs = (const int*)d_in[28];
    float* out = (float*)d_out;

    float *d_src_embed, *d_ans_embed, *d_xproj, *d_dxe, *d_h, *d_c, *d_z;
    float *d_enc_out, *d_qkey, *d_qval, *d_tmp, *d_ctx, *d_feat;
    cudaGetSymbolAddress((void**)&d_src_embed, g_src_embed);
    cudaGetSymbolAddress((void**)&d_ans_embed, g_ans_embed);
    cudaGetSymbolAddress((void**)&d_xproj,     g_xproj);
    cudaGetSymbolAddress((void**)&d_dxe,       g_dxe);
    cudaGetSymbolAddress((void**)&d_h,         g_h);
    cudaGetSymbolAddress((void**)&d_c,         g_c);
    cudaGetSymbolAddress((void**)&d_z,         g_z);
    cudaGetSymbolAddress((void**)&d_enc_out,   g_enc_out);
    cudaGetSymbolAddress((void**)&d_qkey,      g_qkey);
    cudaGetSymbolAddress((void**)&d_qval,      g_qval);
    cudaGetSymbolAddress((void**)&d_tmp,       g_tmp);
    cudaGetSymbolAddress((void**)&d_ctx,       g_ctx);
    cudaGetSymbolAddress((void**)&d_feat,      g_feat);

    // ---- precompute ----
    k_gather<<<NS*NB, 128>>>(src_seqs, NS, embed, d_src_embed);
    k_gather<<<NT*NB, 128>>>(trg_seqs, 20, embed, d_ans_embed);

    // x_proj (transposed [s][n][b]) = src_embed @ enc_Wih^T + enc_bih + enc_bhh
    k_sgemm<<<dim3(NG/64, (NS*NB)/64), 256>>>(NS*NB, NG, ND,
        d_src_embed, ND, enc_Wih, ND, enc_bih, enc_bhh, d_xproj, NG, 0, 2);
    // dxe = ans_embed @ dec_Wih[:, :512]^T + dec_bih + dec_bhh (608 x 4096)
    k_sgemm<<<dim3(NG/64, (NT*NB + 63)/64), 256>>>(NT*NB, NG, ND,
        d_ans_embed, ND, dec_Wih, ND + NH, dec_bih, dec_bhh, d_dxe, NG, 0, 0);

    // ---- encoder recurrence: one persistent kernel ----
    const int enc_smem = (1024*36 + 128*36 + 4*32*33) * (int)sizeof(float);
    cudaFuncSetAttribute(k_enc_persist,
                         cudaFuncAttributeMaxDynamicSharedMemorySize, enc_smem);
    k_enc_persist<<<ENC_NBLK, 256, enc_smem>>>(enc_Whh, src_len);

    // ---- bridge MLPs: dh, dc ----
    k_sgemm<<<dim3(2048/64, 1), 256>>>(NB, 2048, NH, d_h, NH, hfc1_W, NH,
                                       hfc1_b, nullptr, d_tmp, 2048, 2, 0);
    k_sgemm<<<dim3(NH/64, 1), 256>>>(NB, NH, 2048, d_tmp, 2048, hfc2_W, 2048,
                                     hfc2_b, nullptr, d_h, NH, 0, 0);
    k_sgemm<<<dim3(2048/64, 1), 256>>>(NB, 2048, NH, d_c, NH, cfc1_W, NH,
                                       cfc1_b, nullptr, d_tmp, 2048, 2, 0);
    k_sgemm<<<dim3(NH/64, 1), 256>>>(NB, NH, 2048, d_tmp, 2048, cfc2_W, 2048,
                                     cfc2_b, nullptr, d_c, NH, 0, 0);

    // ---- attention precompute over all source positions ----
    k_sgemm<<<dim3((NK + 63)/64, (NS*NB)/64), 256>>>(NS*NB, NK, NH,
        d_enc_out, NH, qk_W, NH, qk_b, nullptr, d_qkey, NK, 1, 0);
    k_sgemm<<<dim3(NH/64, (NS*NB)/64), 256>>>(NS*NB, NH, NH,
        d_enc_out, NH, qv_W, NH, qv_b, nullptr, d_qval, NH, 0, 0);

    // ---- decoder recurrence ----
    for (int t = 0; t < NT; t++) {
        k_attn<<<NB, 256>>>(ak_W, ak_b, src_len);
        k_recgemm<<<dim3(NG/32, 4), 256>>>(d_ctx, NH, dec_Wih, ND + NH, ND,
                                           d_h,   NH, dec_Whh, NH, 0, NG, d_z);
        k_dec_cell<<<(NB*NH)/256, 256>>>(t);
        k_recgemm<<<dim3(ND/32, 4), 256>>>(d_h,   NH, out_W, 2*NH, 0,
                                           d_ctx, NH, out_W, 2*NH, NH, ND, d_z);
        k_feat_sum<<<(NB*ND)/256, 256>>>(t, out_b);
    }

    // ---- final logits: feat(608x512) @ embed^T(32000x512) + wd_b ----
    k_sgemm<<<dim3(NV/64, (NT*NB + 63)/64), 256>>>(NT*NB, NV, ND,
        d_feat, ND, embed, ND, wd_b, nullptr, out, NV, 0, 1);

    (void)in_sizes; (void)n_in; (void)out_size;
}

// round 4
// speedup vs baseline: 1.1923x; 1.0706x over previous
#include <cuda_runtime.h>
#include <math.h>
#include <stdint.h>

// Problem dims (fixed by the dataset)
#define NB 32      // batch
#define NS 128     // src seq len
#define NT 19      // decoder steps (T-1)
#define ND 512     // embed dim
#define NH 1024    // hidden
#define NG 4096    // 4*H
#define NK 100     // attn key dim
#define NV 32000   // vocab
#define ENC_NBLK 128
#define DEC_NBLK 128

// ------------------------- scratch (device globals; no allocs) ---------------
__device__ float g_src_embed[NS*NB*ND];     // [s][b][d]
__device__ float g_ans_embed[NT*NB*ND];     // [t][b][d]
__device__ float g_xproj[NS*NG*NB];         // [s][n][b]  transposed
__device__ float g_dxe[NT*NG*NB];           // [t][n][b]  transposed
__device__ float g_h[NB*NH];
__device__ float g_c[NB*NH];
__device__ float g_hbuf[2*NB*NH];           // h ping-pong (enc + dec)
__device__ float g_enc_out[NS*NB*NH];       // [s][b][h]
__device__ float g_qkey[NS*NB*NK];          // [s][b][k]
__device__ float g_qval[NS*NB*NH];          // [s][b][h]
__device__ float g_tmp[NB*2048];            // MLP intermediate
__device__ float g_ctx[NB*NH];
__device__ float g_attw[NB*NS];             // softmax weights per step
__device__ float g_feat[NT*NB*ND];          // [(t*NB+b)][d]

__device__ unsigned g_barcnt = 0;
__device__ unsigned g_bargen = 0;

__device__ __forceinline__ float sigmf_(float x) { return 1.0f/(1.0f+expf(-x)); }

__device__ __forceinline__ void gridbar()
{
    __syncthreads();
    if (threadIdx.x == 0) {
        __threadfence();
        volatile unsigned* vgen = &g_bargen;
        unsigned gen = *vgen;
        if (atomicAdd(&g_barcnt, 1u) == ENC_NBLK - 1) {
            g_barcnt = 0;
            __threadfence();
            atomicAdd(&g_bargen, 1u);
        } else {
            while (*vgen == gen) { __nanosleep(16); }
        }
        __threadfence();
    }
    __syncthreads();
}

// ------------------------- embedding gather ---------------------------------
__global__ void k_gather(const int* __restrict__ seq, int seq_stride,
                         const float* __restrict__ embed, float* __restrict__ out)
{
    int row = blockIdx.x;          // step*NB + b
    int st  = row / NB;
    int b   = row % NB;
    int tok = seq[b*seq_stride + st];
    const float4* src = (const float4*)(embed + (size_t)tok*ND);
    float4*       dst = (float4*)(out + (size_t)row*ND);
    dst[threadIdx.x] = src[threadIdx.x];   // 128 threads x float4 = 512 floats
}

// ------------------------- generic tiled SGEMM (C = act(A@W^T + b1 [+b2])) ---
// BM=64, BN=64, BK=16, 256 threads, 4x4 register tile.
// out_map==1 remaps row m=(t*32+b) -> (b*NT+t)  (final logits)
// out_map==2 writes C[((m>>5)*NG + n)*32 + (m&31)] via staged coalesced stores
__global__ __launch_bounds__(256)
void k_sgemm(int M, int N, int K,
             const float* __restrict__ A, int lda,
             const float* __restrict__ W, int ldw,
             const float* __restrict__ bias1, const float* __restrict__ bias2,
             float* __restrict__ C, int ldc, int act, int out_map)
{
    __shared__ float As[16][68];
    __shared__ float Ws[16][68];
    __shared__ float Cs[64][68];
    int tid = threadIdx.x;
    int m0 = blockIdx.y*64, n0 = blockIdx.x*64;
    int lr = tid >> 2;           // 0..63
    int lc = (tid & 3) << 2;     // 0,4,8,12
    int ty = tid >> 4;           // 0..15 (m)
    int tx = tid & 15;           // 0..15 (n)
    float acc[4][4] = {};

    for (int k0 = 0; k0 < K; k0 += 16) {
        float4 a4 = make_float4(0.f,0.f,0.f,0.f);
        float4 w4 = make_float4(0.f,0.f,0.f,0.f);
        if (m0+lr < M) a4 = *(const float4*)(A + (size_t)(m0+lr)*lda + k0 + lc);
        if (n0+lr < N) w4 = *(const float4*)(W + (size_t)(n0+lr)*ldw + k0 + lc);
        __syncthreads();
        As[lc+0][lr]=a4.x; As[lc+1][lr]=a4.y; As[lc+2][lr]=a4.z; As[lc+3][lr]=a4.w;
        Ws[lc+0][lr]=w4.x; Ws[lc+1][lr]=w4.y; Ws[lc+2][lr]=w4.z; Ws[lc+3][lr]=w4.w;
        __syncthreads();
#pragma unroll
        for (int k = 0; k < 16; k++) {
            float4 av = *(const float4*)&As[k][ty*4];
            float4 wv = *(const float4*)&Ws[k][tx*4];
            float am[4] = {av.x, av.y, av.z, av.w};
            float wn[4] = {wv.x, wv.y, wv.z, wv.w};
#pragma unroll
            for (int i = 0; i < 4; i++)
#pragma unroll
                for (int j = 0; j < 4; j++)
                    acc[i][j] += am[i]*wn[j];
        }
    }

    if (out_map == 2) {
        // stage with bias applied, then coalesced float4 writes
#pragma unroll
        for (int i = 0; i < 4; i++) {
            int ml = ty*4 + i;
#pragma unroll
            for (int j = 0; j < 4; j++) {
                int nl = tx*4 + j;
                float v = acc[i][j] + bias1[n0+nl];
                if (bias2) v += bias2[n0+nl];
                Cs[nl][ml] = v;
            }
        }
        __syncthreads();
        for (int c = tid; c < 1024; c += 256) {
            int row = c >> 3;          // 0..127 : (nl, s_half)
            int nl  = row >> 1;
            int sh  = row & 1;
            int qb  = (c & 7) * 4;     // b offset
            int mgrp = m0 + sh*32;
            if (mgrp < M) {
                float4 v4 = *(const float4*)&Cs[nl][sh*32 + qb];
                *(float4*)&C[ ((size_t)(mgrp >> 5)*NG + n0 + nl)*32 + qb ] = v4;
            }
        }
        return;
    }

#pragma unroll
    for (int i = 0; i < 4; i++) {
        int m = m0 + ty*4 + i;
        if (m >= M) continue;
        size_t row = (out_map == 1) ? (size_t)((m & 31)*NT + (m >> 5)) : (size_t)m;
        int n = n0 + tx*4;
        float v[4];
#pragma unroll
        for (int j = 0; j < 4; j++) {
            float x = acc[i][j] + ((n+j < N) ? bias1[n+j] : 0.f);
            if (bias2 && n+j < N) x += bias2[n+j];
            if (act == 1)      x = tanhf(x);
            else if (act == 2) x = fmaxf(x, 0.0f);
            v[j] = x;
        }
        if (n + 3 < N) {
            *(float4*)&C[row*ldc + n] = make_float4(v[0], v[1], v[2], v[3]);
        } else {
#pragma unroll
            for (int j = 0; j < 4; j++)
                if (n + j < N) C[row*ldc + n + j] = v[j];
        }
    }
}

// ------------------------- persistent encoder -------------------------------
__global__ void __launch_bounds__(256, 1)
k_enc_persist(const float* __restrict__ Whh, const int* __restrict__ lengths)
{
    extern __shared__ float sm[];
    float* sWt = sm;                        // [1024][36]
    float* sHs = sm + 1024*36;              // [128][36]
    float* sZs = sm + 1024*36 + 128*36;     // [4][32][33]

    int tid = threadIdx.x;
    int u0  = blockIdx.x * 8;

    // Load + transpose Whh slice into SMEM (once)
    for (int r = 0; r < 32; r++) {
        int n = (r >> 3)*NH + u0 + (r & 7);
        float4 w4 = *(const float4*)&Whh[(size_t)n*NH + 4*tid];
        sWt[(4*tid+0)*36 + r] = w4.x;
        sWt[(4*tid+1)*36 + r] = w4.y;
        sWt[(4*tid+2)*36 + r] = w4.z;
        sWt[(4*tid+3)*36 + r] = w4.w;
    }

    int cb = tid & 31;            // cell batch
    int cu = tid >> 5;            // cell unit (0..7)
    int mylen = lengths[cb];
    float creg = 0.0f;
    float hreg = 0.0f;

    g_hbuf[cb*NH + u0 + cu] = 0.0f;

    int rq = tid & 7;
    int bq = (tid >> 3) & 7;
    int ks = tid >> 6;
    int lb = tid >> 3;
    int lq = tid & 7;

    gridbar();

    for (int s = 0; s < NS; s++) {
        const float* hin  = g_hbuf + (s & 1)*(NB*NH);
        float*       hout = g_hbuf + ((s & 1) ^ 1)*(NB*NH);

        float acc[4][4] = {};
        for (int kc = 0; kc < NH; kc += 128) {
            #pragma unroll
            for (int p = 0; p < 4; p++) {
                int kk = 4*(lq + 8*p);
                float4 h4 = __ldcg((const float4*)&hin[lb*NH + kc + kk]);
                sHs[(kk+0)*36 + lb] = h4.x;
                sHs[(kk+1)*36 + lb] = h4.y;
                sHs[(kk+2)*36 + lb] = h4.z;
                sHs[(kk+3)*36 + lb] = h4.w;
            }
            __syncthreads();
            for (int kb = 0; kb < 128; kb += 16) {
                int k = kb + 4*ks;
                #pragma unroll
                for (int kk2 = 0; kk2 < 4; kk2++) {
                    float4 wv = *(const float4*)&sWt[(kc+k+kk2)*36 + 4*rq];
                    float4 hv = *(const float4*)&sHs[(k+kk2)*36 + 4*bq];
                    float wa[4] = {wv.x, wv.y, wv.z, wv.w};
                    float hb[4] = {hv.x, hv.y, hv.z, hv.w};
                    #pragma unroll
                    for (int i = 0; i < 4; i++)
                        #pragma unroll
                        for (int j = 0; j < 4; j++)
                            acc[i][j] += wa[i]*hb[j];
                }
            }
            __syncthreads();
        }

        #pragma unroll
        for (int i = 0; i < 4; i++)
            #pragma unroll
            for (int j = 0; j < 4; j++)
                sZs[(ks*32 + 4*rq + i)*33 + 4*bq + j] = acc[i][j];
        __syncthreads();

        const float* xp = g_xproj + ((size_t)s*NG + u0 + cu)*32 + cb;
        float zg4[4];
        #pragma unroll
        for (int g = 0; g < 4; g++) {
            float v = xp[(size_t)g*NH*32];
            #pragma unroll
            for (int q = 0; q < 4; q++) v += sZs[(q*32 + g*8 + cu)*33 + cb];
            zg4[g] = v;
        }
        float cn = sigmf_(zg4[1])*creg + sigmf_(zg4[0])*tanhf(zg4[2]);
        float hn = sigmf_(zg4[3])*tanhf(cn);
        bool msk = (s < mylen);
        creg = msk ? cn : creg;
        hreg = msk ? hn : hreg;
        hout[cb*NH + u0 + cu] = hreg;
        g_enc_out[((size_t)(s*NB + cb))*NH + u0 + cu] = msk ? hreg : 0.0f;

        gridbar();
    }

    g_h[cb*NH + u0 + cu] = hreg;
    g_c[cb*NH + u0 + cu] = creg;
}

// ------------------------- persistent decoder helpers -----------------------
// feat(tt) = [h_new(tt), ctx(tt)] @ out_W^T + out_b ; block owns 4 rows fn0..+3
__device__ __forceinline__ void dec_feat(int tt, const float* __restrict__ hsrc,
    const float* __restrict__ out_W, const float* __restrict__ out_b,
    float* sW, float* sH, float* sZ, int fn0)
{
    int tid = threadIdx.x;
    int r   = tid >> 6;          // 0..3
    int fks = (tid >> 5) & 1;    // k-half
    int fb  = tid & 31;          // batch
    int lb  = tid >> 3;
    int lq  = tid & 7;
    float fa = 0.f;

    for (int ch = 0; ch < 16; ch++) {
        int koff = (ch & 7) * 128;
        const float* src = (ch < 8) ? hsrc : g_ctx;
        // weights: 4 rows x 128 k
        {
            int r2 = tid >> 6;
            int kk = tid & 63;
            const float* wrow = out_W + (size_t)(fn0 + r2)*(2*NH) + ch*128;
            sW[kk*4 + r2]        = __ldg(&wrow[kk]);
            sW[(kk+64)*4 + r2]   = __ldg(&wrow[kk+64]);
        }
        #pragma unroll
        for (int p = 0; p < 4; p++) {
            int kk = 4*(lq + 8*p);
            float4 h4 = __ldcg((const float4*)&src[lb*NH + koff + kk]);
            sH[(kk+0)*36 + lb] = h4.x;
            sH[(kk+1)*36 + lb] = h4.y;
            sH[(kk+2)*36 + lb] = h4.z;
            sH[(kk+3)*36 + lb] = h4.w;
        }
        __syncthreads();
        #pragma unroll 8
        for (int k = fks*64; k < fks*64 + 64; k++)
            fa += sW[k*4 + r] * sH[k*36 + fb];
        __syncthreads();
    }
    sZ[(r*2 + fks)*33 + fb] = fa;
    __syncthreads();
    if (tid < 128) {
        int rr = tid >> 5, bb = tid & 31;
        float v = sZ[(rr*2)*33 + bb] + sZ[(rr*2+1)*33 + bb] + __ldg(&out_b[fn0 + rr]);
        g_feat[((size_t)(tt*NB + bb))*ND + fn0 + rr] = v;
    }
    __syncthreads();
}

// attention weights for batch b (blocks 0..31). arrays carved out of sW region.
__device__ __forceinline__ void dec_attn(int b, int mylen,
    const float* __restrict__ hcur,
    const float* __restrict__ ak_W, const float* __restrict__ ak_b,
    float* sW)
{
    int tid = threadIdx.x;
    float* sh_ = sW;            // 1024
    float* sak = sW + 1024;     // 128
    float* se  = sW + 1152;     // 128
    float* sr  = sW + 1280;     // 256

    for (int i = tid; i < NH; i += 256) sh_[i] = __ldcg(&hcur[b*NH + i]);
    __syncthreads();

    if (tid < NK) {
        const float* wr = ak_W + (size_t)tid*NH;
        float acc0 = 0.f, acc1 = 0.f;
        for (int k = 0; k < NH; k += 8) {
            float4 w0 = *(const float4*)&wr[k];
            float4 w1 = *(const float4*)&wr[k+4];
            float4 h0 = *(const float4*)&sh_[k];
            float4 h1 = *(const float4*)&sh_[k+4];
            acc0 += w0.x*h0.x + w0.y*h0.y + w0.z*h0.z + w0.w*h0.w;
            acc1 += w1.x*h1.x + w1.y*h1.y + w1.z*h1.z + w1.w*h1.w;
        }
        sak[tid] = tanhf(acc0 + acc1 + ak_b[tid]);
    }
    __syncthreads();

    if (tid < NS) {
        const float* qr = g_qkey + ((size_t)(tid*NB + b))*NK;
        float acc = 0.f;
        for (int k = 0; k < NK; k++) acc += qr[k]*sak[k];
        se[tid] = (tid < mylen) ? acc : -INFINITY;
    }
    __syncthreads();

    sr[tid] = (tid < NS) ? se[tid] : -INFINITY;
    __syncthreads();
    for (int off = 128; off >= 1; off >>= 1) {
        if (tid < off) sr[tid] = fmaxf(sr[tid], sr[tid+off]);
        __syncthreads();
    }
    float mx = sr[0];
    __syncthreads();

    float ex = (tid < NS) ? expf(se[tid] - mx) : 0.0f;
    sr[tid] = ex;
    __syncthreads();
    for (int off = 128; off >= 1; off >>= 1) {
        if (tid < off) sr[tid] += sr[tid+off];
        __syncthreads();
    }
    float inv = 1.0f / sr[0];
    __syncthreads();
    if (tid < NS) g_attw[b*NS + tid] = ex * inv;
    __syncthreads();
}

// ------------------------- persistent decoder -------------------------------
// 128 blocks x 256 threads. Per step: [feat(t-1) + attn(t)] | bar | ctx | bar |
// z-gemm+cell | bar. Block owns 8 hidden units for z (32 gate rows) and 4 feat
// rows. c lives in registers; h ping-pongs through g_hbuf with __ldcg reads.
__global__ void __launch_bounds__(256, 1)
k_dec_persist(const float* __restrict__ dec_Wih, const float* __restrict__ dec_Whh,
              const float* __restrict__ ak_W,   const float* __restrict__ ak_b,
              const float* __restrict__ out_W,  const float* __restrict__ out_b,
              const int* __restrict__ lengths)
{
    extern __shared__ float sm[];
    float* sW = sm;                 // [128][36]
    float* sH = sm + 128*36;        // [128][36]
    float* sZ = sm + 2*128*36;      // [4][32][33]

    int tid = threadIdx.x;
    int blk = blockIdx.x;
    int u0  = blk * 8;
    int fn0 = blk * 4;

    int cb = tid & 31, cu = tid >> 5;
    float creg = g_c[cb*NH + u0 + cu];

    int rq = tid & 7;
    int bq = (tid >> 3) & 7;
    int ks = tid >> 6;
    int lb = tid >> 3;
    int lq = tid & 7;

    int mylen = (blk < 32) ? lengths[blk] : 0;

    for (int t = 0; t < NT; t++) {
        const float* hcur = (t == 0) ? g_h : (g_hbuf + ((t-1) & 1)*(NB*NH));
        float*       hnew = g_hbuf + (t & 1)*(NB*NH);

        // ---- phase C: feat(t-1) (all blocks) then attn(t) (blocks 0..31) ----
        if (t > 0)
            dec_feat(t-1, hcur, out_W, out_b, sW, sH, sZ, fn0);
        if (blk < 32)
            dec_attn(blk, mylen, hcur, ak_W, ak_b, sW);
        gridbar();

        // ---- phase 2: context. block -> (b, h-quarter) ----
        {
            int b  = blk & 31;
            int hq = blk >> 5;
            if (tid < NS) sZ[tid] = __ldcg(&g_attw[b*NS + tid]);
            __syncthreads();
            int hh = hq*256 + tid;
            float a0 = 0.f, a1 = 0.f, a2 = 0.f, a3 = 0.f;
            #pragma unroll 4
            for (int s = 0; s < NS; s += 4) {
                a0 += sZ[s+0]*__ldg(&g_qval[((size_t)((s+0)*NB + b))*NH + hh]);
                a1 += sZ[s+1]*__ldg(&g_qval[((size_t)((s+1)*NB + b))*NH + hh]);
                a2 += sZ[s+2]*__ldg(&g_qval[((size_t)((s+2)*NB + b))*NH + hh]);
                a3 += sZ[s+3]*__ldg(&g_qval[((size_t)((s+3)*NB + b))*NH + hh]);
            }
            g_ctx[b*NH + hh] = (a0 + a1) + (a2 + a3);
            __syncthreads();
        }
        gridbar();

        // ---- phase 3: z = h @ Whh^T + ctx @ Wih[:,512:]^T  (+cell) ----
        float acc[4][4] = {};
        for (int ch = 0; ch < 16; ch++) {
            int kc = (ch & 7) * 128;
            const float* asrc = (ch < 8) ? hcur : g_ctx;
            #pragma unroll
            for (int p = 0; p < 4; p++) {
                int kk = 4*(lq + 8*p);
                float4 h4 = __ldcg((const float4*)&asrc[lb*NH + kc + kk]);
                sH[(kk+0)*36 + lb] = h4.x;
                sH[(kk+1)*36 + lb] = h4.y;
                sH[(kk+2)*36 + lb] = h4.z;
                sH[(kk+3)*36 + lb] = h4.w;
            }
            {
                int wr_ = tid >> 3;   // row 0..31
                int n = (wr_ >> 3)*NH + u0 + (wr_ & 7);
                const float* wrow = (ch < 8)
                    ? (dec_Whh + (size_t)n*NH + kc)
                    : (dec_Wih + (size_t)n*(ND+NH) + ND + kc);
                #pragma unroll
                for (int p = 0; p < 4; p++) {
                    int kk = 4*(lq + 8*p);
                    float4 w4 = __ldg((const float4*)&wrow[kk]);
                    sW[(kk+0)*36 + wr_] = w4.x;
                    sW[(kk+1)*36 + wr_] = w4.y;
                    sW[(kk+2)*36 + wr_] = w4.z;
                    sW[(kk+3)*36 + wr_] = w4.w;
                }
            }
            __syncthreads();
            for (int kb = 0; kb < 128; kb += 16) {
                int k = kb + 4*ks;
                #pragma unroll
                for (int kk2 = 0; kk2 < 4; kk2++) {
                    float4 wv = *(const float4*)&sW[(k+kk2)*36 + 4*rq];
                    float4 hv = *(const float4*)&sH[(k+kk2)*36 + 4*bq];
                    float wa[4] = {wv.x, wv.y, wv.z, wv.w};
                    float hb[4] = {hv.x, hv.y, hv.z, hv.w};
                    #pragma unroll
                    for (int i = 0; i < 4; i++)
                        #pragma unroll
                        for (int j = 0; j < 4; j++)
                            acc[i][j] += wa[i]*hb[j];
                }
            }
            __syncthreads();
        }
        #pragma unroll
        for (int i = 0; i < 4; i++)
            #pragma unroll
            for (int j = 0; j < 4; j++)
                sZ[(ks*32 + 4*rq + i)*33 + 4*bq + j] = acc[i][j];
        __syncthreads();

        {
            const float* xp = g_dxe + ((size_t)t*NG + u0 + cu)*32 + cb;
            float zg4[4];
            #pragma unroll
            for (int g = 0; g < 4; g++) {
                float v = xp[(size_t)g*NH*32];
                #pragma unroll
                for (int q = 0; q < 4; q++) v += sZ[(q*32 + g*8 + cu)*33 + cb];
                zg4[g] = v;
            }
            float cn = sigmf_(zg4[1])*creg + sigmf_(zg4[0])*tanhf(zg4[2]);
            float hn = sigmf_(zg4[3])*tanhf(cn);
            creg = cn;
            hnew[cb*NH + u0 + cu] = hn;
        }
        __syncthreads();
        gridbar();
    }

    // trailing feat for the last step
    {
        const float* hlast = g_hbuf + ((NT-1) & 1)*(NB*NH);
        dec_feat(NT-1, hlast, out_W, out_b, sW, sH, sZ, fn0);
    }
}

// =============================================================================
extern "C" void kernel_launch(void* const* d_in, const int* in_sizes, int n_in,
                              void* d_out, int out_size)
{
    const float* embed    = (const float*)d_in[0];
    const float* enc_Wih  = (const float*)d_in[1];
    const float* enc_Whh  = (const float*)d_in[2];
    const float* enc_bih  = (const float*)d_in[3];
    const float* enc_bhh  = (const float*)d_in[4];
    const float* dec_Wih  = (const float*)d_in[5];
    const float* dec_Whh  = (const float*)d_in[6];
    const float* dec_bih  = (const float*)d_in[7];
    const float* dec_bhh  = (const float*)d_in[8];
    const float* qk_W     = (const float*)d_in[9];
    const float* qk_b     = (const float*)d_in[10];
    const float* qv_W     = (const float*)d_in[11];
    const float* qv_b     = (const float*)d_in[12];
    const float* ak_W     = (const float*)d_in[13];
    const float* ak_b     = (const float*)d_in[14];
    const float* out_W    = (const float*)d_in[15];
    const float* out_b    = (const float*)d_in[16];
    const float* wd_b     = (const float*)d_in[17];
    const float* hfc1_W   = (const float*)d_in[18];
    const float* hfc1_b   = (const float*)d_in[19];
    const float* hfc2_W   = (const float*)d_in[20];
    const float* hfc2_b   = (const float*)d_in[21];
    const float* cfc1_W   = (const float*)d_in[22];
    const float* cfc1_b   = (const float*)d_in[23];
    const float* cfc2_W   = (const float*)d_in[24];
    const float* cfc2_b   = (const float*)d_in[25];
    const int*   src_seqs = (const int*)d_in[26];
    const int*   src_len  = (const int*)d_in[27];
    const int*   trg_seqs = (const int*)d_in[28];
    float* out = (float*)d_out;

    float *d_src_embed, *d_ans_embed, *d_xproj, *d_dxe, *d_h, *d_c;
    float *d_enc_out, *d_qkey, *d_qval, *d_tmp, *d_feat;
    cudaGetSymbolAddress((void**)&d_src_embed, g_src_embed);
    cudaGetSymbolAddress((void**)&d_ans_embed, g_ans_embed);
    cudaGetSymbolAddress((void**)&d_xproj,     g_xproj);
    cudaGetSymbolAddress((void**)&d_dxe,       g_dxe);
    cudaGetSymbolAddress((void**)&d_h,         g_h);
    cudaGetSymbolAddress((void**)&d_c,         g_c);
    cudaGetSymbolAddress((void**)&d_enc_out,   g_enc_out);
    cudaGetSymbolAddress((void**)&d_qkey,      g_qkey);
    cudaGetSymbolAddress((void**)&d_qval,      g_qval);
    cudaGetSymbolAddress((void**)&d_tmp,       g_tmp);
    cudaGetSymbolAddress((void**)&d_feat,      g_feat);

    // ---- precompute ----
    k_gather<<<NS*NB, 128>>>(src_seqs, NS, embed, d_src_embed);
    k_gather<<<NT*NB, 128>>>(trg_seqs, 20, embed, d_ans_embed);

    // x_proj (transposed [s][n][b]) = src_embed @ enc_Wih^T + enc_bih + enc_bhh
    k_sgemm<<<dim3(NG/64, (NS*NB)/64), 256>>>(NS*NB, NG, ND,
        d_src_embed, ND, enc_Wih, ND, enc_bih, enc_bhh, d_xproj, NG, 0, 2);
    // dxe (transposed [t][n][b]) = ans_embed @ dec_Wih[:, :512]^T + biases
    k_sgemm<<<dim3(NG/64, (NT*NB + 63)/64), 256>>>(NT*NB, NG, ND,
        d_ans_embed, ND, dec_Wih, ND + NH, dec_bih, dec_bhh, d_dxe, NG, 0, 2);

    // ---- encoder recurrence: one persistent kernel ----
    const int enc_smem = (1024*36 + 128*36 + 4*32*33) * (int)sizeof(float);
    cudaFuncSetAttribute(k_enc_persist,
                         cudaFuncAttributeMaxDynamicSharedMemorySize, enc_smem);
    k_enc_persist<<<ENC_NBLK, 256, enc_smem>>>(enc_Whh, src_len);

    // ---- bridge MLPs: dh, dc ----
    k_sgemm<<<dim3(2048/64, 1), 256>>>(NB, 2048, NH, d_h, NH, hfc1_W, NH,
                                       hfc1_b, nullptr, d_tmp, 2048, 2, 0);
    k_sgemm<<<dim3(NH/64, 1), 256>>>(NB, NH, 2048, d_tmp, 2048, hfc2_W, 2048,
                                     hfc2_b, nullptr, d_h, NH, 0, 0);
    k_sgemm<<<dim3(2048/64, 1), 256>>>(NB, 2048, NH, d_c, NH, cfc1_W, NH,
                                       cfc1_b, nullptr, d_tmp, 2048, 2, 0);
    k_sgemm<<<dim3(NH/64, 1), 256>>>(NB, NH, 2048, d_tmp, 2048, cfc2_W, 2048,
                                     cfc2_b, nullptr, d_c, NH, 0, 0);

    // ---- attention precompute over all source positions ----
    k_sgemm<<<dim3((NK + 63)/64, (NS*NB)/64), 256>>>(NS*NB, NK, NH,
        d_enc_out, NH, qk_W, NH, qk_b, nullptr, d_qkey, NK, 1, 0);
    k_sgemm<<<dim3(NH/64, (NS*NB)/64), 256>>>(NS*NB, NH, NH,
        d_enc_out, NH, qv_W, NH, qv_b, nullptr, d_qval, NH, 0, 0);

    // ---- decoder recurrence: one persistent kernel ----
    const int dec_smem = (2*128*36 + 4*32*33) * (int)sizeof(float);
    cudaFuncSetAttribute(k_dec_persist,
                         cudaFuncAttributeMaxDynamicSharedMemorySize, dec_smem);
    k_dec_persist<<<DEC_NBLK, 256, dec_smem>>>(dec_Wih, dec_Whh, ak_W, ak_b,
                                               out_W, out_b, src_len);

    // ---- final logits: feat(608x512) @ embed^T(32000x512) + wd_b ----
    k_sgemm<<<dim3(NV/64, (NT*NB + 63)/64), 256>>>(NT*NB, NV, ND,
        d_feat, ND, embed, ND, wd_b, nullptr, out, NV, 0, 1);

    (void)in_sizes; (void)n_in; (void)out_size;
}

// round 5
// speedup vs baseline: 1.2793x; 1.0730x over previous
#include <cuda_runtime.h>
#include <math.h>
#include <stdint.h>

// Problem dims (fixed by the dataset)
#define NB 32      // batch
#define NS 128     // src seq len
#define NT 19      // decoder steps (T-1)
#define ND 512     // embed dim
#define NH 1024    // hidden
#define NG 4096    // 4*H
#define NK 100     // attn key dim
#define NV 32000   // vocab
#define NBLK 128

// ------------------------- scratch (device globals; no allocs) ---------------
__device__ float g_src_embed[NS*NB*ND];
__device__ float g_ans_embed[NT*NB*ND];
__device__ float g_xproj[NS*NG*NB];         // [s][n][b]
__device__ float g_dxe[NT*NG*NB];           // [t][n][b]
__device__ float g_h[NB*NH];
__device__ float g_c[NB*NH];
__device__ float g_hbuf[2*NB*NH];
__device__ float g_enc_out[NS*NB*NH];
__device__ float g_qkey[NS*NB*NK];
__device__ float g_qval[NS*NB*NH];
__device__ float g_tmp[NB*2048];
__device__ float g_ctx[NB*NH];
__device__ float g_attw[NB*NS];
__device__ float g_feat[NT*NB*ND];

__device__ unsigned g_barcnt = 0;
__device__ unsigned g_bargen = 0;

__device__ __forceinline__ float sigmf_(float x) { return 1.0f/(1.0f+expf(-x)); }

__device__ __forceinline__ void gridbar()
{
    __syncthreads();
    if (threadIdx.x == 0) {
        __threadfence();
        volatile unsigned* vgen = &g_bargen;
        unsigned gen = *vgen;
        if (atomicAdd(&g_barcnt, 1u) == NBLK - 1) {
            g_barcnt = 0;
            __threadfence();
            atomicAdd(&g_bargen, 1u);
        } else {
            while (*vgen == gen) { __nanosleep(16); }
        }
        __threadfence();
    }
    __syncthreads();
}

// helper: scatter 4 prefetched float4s (rows kk=4*(lq+8p)) into tile[k][row]
__device__ __forceinline__ void stash4(float* buf, int lq, int row,
                                       float4 p0, float4 p1, float4 p2, float4 p3)
{
    buf[(4*lq+0)*36+row]=p0.x; buf[(4*lq+1)*36+row]=p0.y;
    buf[(4*lq+2)*36+row]=p0.z; buf[(4*lq+3)*36+row]=p0.w;
    buf[(4*(lq+8)+0)*36+row]=p1.x; buf[(4*(lq+8)+1)*36+row]=p1.y;
    buf[(4*(lq+8)+2)*36+row]=p1.z; buf[(4*(lq+8)+3)*36+row]=p1.w;
    buf[(4*(lq+16)+0)*36+row]=p2.x; buf[(4*(lq+16)+1)*36+row]=p2.y;
    buf[(4*(lq+16)+2)*36+row]=p2.z; buf[(4*(lq+16)+3)*36+row]=p2.w;
    buf[(4*(lq+24)+0)*36+row]=p3.x; buf[(4*(lq+24)+1)*36+row]=p3.y;
    buf[(4*(lq+24)+2)*36+row]=p3.z; buf[(4*(lq+24)+3)*36+row]=p3.w;
}

// ------------------------- embedding gather ---------------------------------
__global__ void k_gather(const int* __restrict__ seq, int seq_stride,
                         const float* __restrict__ embed, float* __restrict__ out)
{
    int row = blockIdx.x;
    int st  = row / NB;
    int b   = row % NB;
    int tok = seq[b*seq_stride + st];
    const float4* src = (const float4*)(embed + (size_t)tok*ND);
    float4*       dst = (float4*)(out + (size_t)row*ND);
    dst[threadIdx.x] = src[threadIdx.x];
}

// ------------------------- tiled SGEMM, BM=128 BN=64 BK=16, 8x4 reg tile ----
__global__ __launch_bounds__(256)
void k_sgemm(int M, int N, int K,
             const float* __restrict__ A, int lda,
             const float* __restrict__ W, int ldw,
             const float* __restrict__ bias1, const float* __restrict__ bias2,
             float* __restrict__ C, int ldc, int act, int out_map)
{
    __shared__ float As[16][132];   // [k][m]
    __shared__ float Ws[16][68];    // [k][n]
    __shared__ float Cs[64][132];   // staging for out_map==2
    int tid = threadIdx.x;
    int m0 = blockIdx.y*128, n0 = blockIdx.x*64;
    int alr = tid & 127;           // A row
    int aq0 = (tid >> 7) * 4;      // A k offset (0 or 4); also +8
    int wlr = tid >> 2;            // W row 0..63
    int wlc = (tid & 3) << 2;      // W k offset
    int ty = tid >> 4;             // 0..15 -> 8 rows
    int tx = tid & 15;             // 0..15 -> 4 cols
    float acc[8][4] = {};

    for (int k0 = 0; k0 < K; k0 += 16) {
        float4 a0 = make_float4(0.f,0.f,0.f,0.f);
        float4 a1 = make_float4(0.f,0.f,0.f,0.f);
        float4 w4 = make_float4(0.f,0.f,0.f,0.f);
        if (m0+alr < M) {
            a0 = *(const float4*)(A + (size_t)(m0+alr)*lda + k0 + aq0);
            a1 = *(const float4*)(A + (size_t)(m0+alr)*lda + k0 + aq0 + 8);
        }
        if (n0+wlr < N) w4 = *(const float4*)(W + (size_t)(n0+wlr)*ldw + k0 + wlc);
        __syncthreads();
        As[aq0+0][alr] = a0.x; As[aq0+1][alr] = a0.y;
        As[aq0+2][alr] = a0.z; As[aq0+3][alr] = a0.w;
        As[aq0+8][alr] = a1.x; As[aq0+9][alr] = a1.y;
        As[aq0+10][alr] = a1.z; As[aq0+11][alr] = a1.w;
        Ws[wlc+0][wlr] = w4.x; Ws[wlc+1][wlr] = w4.y;
        Ws[wlc+2][wlr] = w4.z; Ws[wlc+3][wlr] = w4.w;
        __syncthreads();
#pragma unroll
        for (int k = 0; k < 16; k++) {
            float4 av0 = *(const float4*)&As[k][ty*8];
            float4 av1 = *(const float4*)&As[k][ty*8+4];
            float4 wv  = *(const float4*)&Ws[k][tx*4];
            float am[8] = {av0.x, av0.y, av0.z, av0.w, av1.x, av1.y, av1.z, av1.w};
            float wn[4] = {wv.x, wv.y, wv.z, wv.w};
#pragma unroll
            for (int i = 0; i < 8; i++)
#pragma unroll
                for (int j = 0; j < 4; j++)
                    acc[i][j] += am[i]*wn[j];
        }
    }

    if (out_map == 2) {
        __syncthreads();
#pragma unroll
        for (int i = 0; i < 8; i++) {
            int ml = ty*8 + i;
#pragma unroll
            for (int j = 0; j < 4; j++) {
                int nl = tx*4 + j;
                float v = acc[i][j] + bias1[n0+nl];
                if (bias2) v += bias2[n0+nl];
                Cs[nl][ml] = v;
            }
        }
        __syncthreads();
        for (int c = tid; c < 2048; c += 256) {
            int qb = (c & 7) * 4;
            int nl = (c >> 3) & 63;
            int sh = c >> 9;
            int mgrp = m0 + sh*32;
            if (mgrp < M) {
                float4 v4 = *(const float4*)&Cs[nl][sh*32 + qb];
                *(float4*)&C[((size_t)(mgrp >> 5)*NG + n0 + nl)*32 + qb] = v4;
            }
        }
        return;
    }

#pragma unroll
    for (int i = 0; i < 8; i++) {
        int m = m0 + ty*8 + i;
        if (m >= M) continue;
        size_t row = (out_map == 1) ? (size_t)((m & 31)*NT + (m >> 5)) : (size_t)m;
        int n = n0 + tx*4;
        float v[4];
#pragma unroll
        for (int j = 0; j < 4; j++) {
            float x = acc[i][j] + ((n+j < N) ? bias1[n+j] : 0.f);
            if (bias2 && n+j < N) x += bias2[n+j];
            if (act == 1)      x = tanhf(x);
            else if (act == 2) x = fmaxf(x, 0.0f);
            v[j] = x;
        }
        if (n + 3 < N) {
            *(float4*)&C[row*ldc + n] = make_float4(v[0], v[1], v[2], v[3]);
        } else {
#pragma unroll
            for (int j = 0; j < 4; j++)
                if (n + j < N) C[row*ldc + n + j] = v[j];
        }
    }
}

// ------------------------- persistent encoder -------------------------------
__global__ void __launch_bounds__(256, 1)
k_enc_persist(const float* __restrict__ Whh, const int* __restrict__ lengths)
{
    extern __shared__ float sm[];
    float* sWt = sm;                          // [1024][36]
    float* sHs = sm + 1024*36;                // 2 x [128][36]
    float* sZs = sm + 1024*36 + 2*128*36;     // [4][32][33]

    int tid = threadIdx.x;
    int u0  = blockIdx.x * 8;

    for (int r = 0; r < 32; r++) {
        int n = (r >> 3)*NH + u0 + (r & 7);
        float4 w4 = *(const float4*)&Whh[(size_t)n*NH + 4*tid];
        sWt[(4*tid+0)*36 + r] = w4.x;
        sWt[(4*tid+1)*36 + r] = w4.y;
        sWt[(4*tid+2)*36 + r] = w4.z;
        sWt[(4*tid+3)*36 + r] = w4.w;
    }

    int cb = tid & 31;
    int cu = tid >> 5;
    int mylen = lengths[cb];
    int len_hi = 0;
    for (int i = 16; i < 32; i++) len_hi = max(len_hi, lengths[i]);
    float creg = 0.0f, hreg = 0.0f;

    g_hbuf[cb*NH + u0 + cu] = 0.0f;

    int rq = tid & 7;
    int bq = (tid >> 3) & 7;
    int ks = tid >> 6;
    int lb = tid >> 3;
    int lq = tid & 7;
    bool oddwarp = (tid >> 5) & 1;   // compute covers batches 16-31
    bool hiload  = (tid >= 128);     // loads batch rows 16-31

    gridbar();

    for (int s = 0; s < NS; s++) {
        const float* hin  = g_hbuf + (s & 1)*(NB*NH);
        float*       hout = g_hbuf + ((s & 1) ^ 1)*(NB*NH);
        bool skip_hi = (s >= len_hi);
        bool doComp = !(oddwarp && skip_hi);
        bool doLoad = !(hiload && skip_hi);

        const float* xp = g_xproj + ((size_t)s*NG + u0 + cu)*32 + cb;
        float xg0 = __ldg(&xp[0]);
        float xg1 = __ldg(&xp[(size_t)NH*32]);
        float xg2 = __ldg(&xp[(size_t)2*NH*32]);
        float xg3 = __ldg(&xp[(size_t)3*NH*32]);

        float4 p0, p1, p2, p3;
        if (doLoad) {
            const float* hr = hin + lb*NH;
            p0 = __ldcg((const float4*)&hr[4*lq]);
            p1 = __ldcg((const float4*)&hr[4*(lq+8)]);
            p2 = __ldcg((const float4*)&hr[4*(lq+16)]);
            p3 = __ldcg((const float4*)&hr[4*(lq+24)]);
            stash4(sHs, lq, lb, p0, p1, p2, p3);
        }
        __syncthreads();

        float acc[4][4] = {};
        for (int ci = 0; ci < 8; ci++) {
            float* cur = sHs + (ci & 1)*(128*36);
            if (ci < 7 && doLoad) {
                const float* hr = hin + lb*NH + (ci+1)*128;
                p0 = __ldcg((const float4*)&hr[4*lq]);
                p1 = __ldcg((const float4*)&hr[4*(lq+8)]);
                p2 = __ldcg((const float4*)&hr[4*(lq+16)]);
                p3 = __ldcg((const float4*)&hr[4*(lq+24)]);
            }
            if (doComp) {
                int kc = ci*128;
                for (int kb = 0; kb < 128; kb += 16) {
                    int k = kb + 4*ks;
                    #pragma unroll
                    for (int kk2 = 0; kk2 < 4; kk2++) {
                        float4 wv = *(const float4*)&sWt[(kc+k+kk2)*36 + 4*rq];
                        float4 hv = *(const float4*)&cur[(k+kk2)*36 + 4*bq];
                        float wa[4] = {wv.x, wv.y, wv.z, wv.w};
                        float hb[4] = {hv.x, hv.y, hv.z, hv.w};
                        #pragma unroll
                        for (int i = 0; i < 4; i++)
                            #pragma unroll
                            for (int j = 0; j < 4; j++)
                                acc[i][j] += wa[i]*hb[j];
                    }
                }
            }
            if (ci < 7 && doLoad)
                stash4(sHs + ((ci & 1) ^ 1)*(128*36), lq, lb, p0, p1, p2, p3);
            __syncthreads();
        }

        #pragma unroll
        for (int i = 0; i < 4; i++)
            #pragma unroll
            for (int j = 0; j < 4; j++)
                sZs[(ks*32 + 4*rq + i)*33 + 4*bq + j] = acc[i][j];
        __syncthreads();

        float zg4[4] = {xg0, xg1, xg2, xg3};
        #pragma unroll
        for (int g = 0; g < 4; g++)
            #pragma unroll
            for (int q = 0; q < 4; q++) zg4[g] += sZs[(q*32 + g*8 + cu)*33 + cb];
        float cn = sigmf_(zg4[1])*creg + sigmf_(zg4[0])*tanhf(zg4[2]);
        float hn = sigmf_(zg4[3])*tanhf(cn);
        bool msk = (s < mylen);
        creg = msk ? cn : creg;
        hreg = msk ? hn : hreg;
        hout[cb*NH + u0 + cu] = hreg;
        g_enc_out[((size_t)(s*NB + cb))*NH + u0 + cu] = msk ? hreg : 0.0f;

        gridbar();
    }

    g_h[cb*NH + u0 + cu] = hreg;
    g_c[cb*NH + u0 + cu] = creg;
}

// ------------------------- persistent decoder helpers -----------------------
__device__ __forceinline__ void dec_feat(int tt, const float* __restrict__ hsrc,
    const float* __restrict__ out_W, const float* __restrict__ out_b,
    float* sH, float* sZ, int fn0)
{
    int tid = threadIdx.x;
    int r   = tid >> 6;
    int fks = (tid >> 5) & 1;
    int fb  = tid & 31;
    int lb  = tid >> 3;
    int lq  = tid & 7;
    const float* wrow = out_W + (size_t)(fn0 + r)*(2*NH);
    float fa = 0.f;

    float4 p0, p1, p2, p3;
    {
        const float* hr = hsrc + lb*NH;
        p0 = __ldcg((const float4*)&hr[4*lq]);
        p1 = __ldcg((const float4*)&hr[4*(lq+8)]);
        p2 = __ldcg((const float4*)&hr[4*(lq+16)]);
        p3 = __ldcg((const float4*)&hr[4*(lq+24)]);
        stash4(sH, lq, lb, p0, p1, p2, p3);
    }
    __syncthreads();

    for (int ch = 0; ch < 16; ch++) {
        float* cur = sH + (ch & 1)*(128*36);
        if (ch < 15) {
            int cn_ = ch + 1;
            const float* src = (cn_ < 8) ? hsrc : g_ctx;
            const float* hr = src + lb*NH + (cn_ & 7)*128;
            p0 = __ldcg((const float4*)&hr[4*lq]);
            p1 = __ldcg((const float4*)&hr[4*(lq+8)]);
            p2 = __ldcg((const float4*)&hr[4*(lq+16)]);
            p3 = __ldcg((const float4*)&hr[4*(lq+24)]);
        }
        const float* wc = wrow + ch*128 + fks*64;
        const float* hc = cur + fks*64*36 + fb;
        #pragma unroll 16
        for (int k = 0; k < 64; k++)
            fa += __ldg(&wc[k]) * hc[k*36];
        if (ch < 15)
            stash4(sH + ((ch & 1) ^ 1)*(128*36), lq, lb, p0, p1, p2, p3);
        __syncthreads();
    }
    sZ[(r*2 + fks)*33 + fb] = fa;
    __syncthreads();
    if (tid < 128) {
        int rr = tid >> 5, bb = tid & 31;
        float v = sZ[(rr*2)*33 + bb] + sZ[(rr*2+1)*33 + bb] + __ldg(&out_b[fn0 + rr]);
        g_feat[((size_t)(tt*NB + bb))*ND + fn0 + rr] = v;
    }
    __syncthreads();
}

__device__ __forceinline__ void dec_attn(int b, int mylen,
    const float* __restrict__ hcur,
    const float* __restrict__ ak_W, const float* __restrict__ ak_b,
    float* sW)
{
    int tid = threadIdx.x;
    float* sh_ = sW;
    float* sak = sW + 1024;
    float* se  = sW + 1152;
    float* sr  = sW + 1280;

    for (int i = tid; i < NH; i += 256) sh_[i] = __ldcg(&hcur[b*NH + i]);
    __syncthreads();

    if (tid < NK) {
        const float* wr = ak_W + (size_t)tid*NH;
        float acc0 = 0.f, acc1 = 0.f;
        for (int k = 0; k < NH; k += 8) {
            float4 w0 = *(const float4*)&wr[k];
            float4 w1 = *(const float4*)&wr[k+4];
            float4 h0 = *(const float4*)&sh_[k];
            float4 h1 = *(const float4*)&sh_[k+4];
            acc0 += w0.x*h0.x + w0.y*h0.y + w0.z*h0.z + w0.w*h0.w;
            acc1 += w1.x*h1.x + w1.y*h1.y + w1.z*h1.z + w1.w*h1.w;
        }
        sak[tid] = tanhf(acc0 + acc1 + ak_b[tid]);
    }
    __syncthreads();

    if (tid < NS) {
        const float* qr = g_qkey + ((size_t)(tid*NB + b))*NK;
        float acc = 0.f;
        for (int k = 0; k < NK; k++) acc += qr[k]*sak[k];
        se[tid] = (tid < mylen) ? acc : -INFINITY;
    }
    __syncthreads();

    sr[tid] = (tid < NS) ? se[tid] : -INFINITY;
    __syncthreads();
    for (int off = 128; off >= 1; off >>= 1) {
        if (tid < off) sr[tid] = fmaxf(sr[tid], sr[tid+off]);
        __syncthreads();
    }
    float mx = sr[0];
    __syncthreads();

    float ex = (tid < NS) ? expf(se[tid] - mx) : 0.0f;
    sr[tid] = ex;
    __syncthreads();
    for (int off = 128; off >= 1; off >>= 1) {
        if (tid < off) sr[tid] += sr[tid+off];
        __syncthreads();
    }
    float inv = 1.0f / sr[0];
    __syncthreads();
    if (tid < NS) g_attw[b*NS + tid] = ex * inv;
    __syncthreads();
}

// ------------------------- persistent decoder -------------------------------
__global__ void __launch_bounds__(256, 1)
k_dec_persist(const float* __restrict__ dec_Wih, const float* __restrict__ dec_Whh,
              const float* __restrict__ ak_W,   const float* __restrict__ ak_b,
              const float* __restrict__ out_W,  const float* __restrict__ out_b,
              const int* __restrict__ lengths)
{
    extern __shared__ float sm[];
    float* sW = sm;                     // 2 x [128][36]
    float* sH = sm + 2*128*36;          // 2 x [128][36]
    float* sZ = sm + 4*128*36;          // [4][32][33]

    int tid = threadIdx.x;
    int blk = blockIdx.x;
    int u0  = blk * 8;
    int fn0 = blk * 4;

    int cb = tid & 31, cu = tid >> 5;
    float creg = g_c[cb*NH + u0 + cu];

    int rq = tid & 7;
    int bq = (tid >> 3) & 7;
    int ks = tid >> 6;
    int lb = tid >> 3;
    int lq = tid & 7;
    int wr_ = tid >> 3;
    int wn_ = (wr_ >> 3)*NH + u0 + (wr_ & 7);

    int mylen = (blk < 32) ? lengths[blk] : 0;

    for (int t = 0; t < NT; t++) {
        const float* hcur = (t == 0) ? g_h : (g_hbuf + ((t-1) & 1)*(NB*NH));
        float*       hnew = g_hbuf + (t & 1)*(NB*NH);

        if (t > 0)
            dec_feat(t-1, hcur, out_W, out_b, sH, sZ, fn0);
        if (blk < 32)
            dec_attn(blk, mylen, hcur, ak_W, ak_b, sW);
        gridbar();

        // ---- context ----
        {
            int b  = blk & 31;
            int hq = blk >> 5;
            if (tid < NS) sZ[tid] = __ldcg(&g_attw[b*NS + tid]);
            __syncthreads();
            int hh = hq*256 + tid;
            float a0 = 0.f, a1 = 0.f, a2 = 0.f, a3 = 0.f;
            #pragma unroll 4
            for (int s = 0; s < NS; s += 4) {
                a0 += sZ[s+0]*__ldg(&g_qval[((size_t)((s+0)*NB + b))*NH + hh]);
                a1 += sZ[s+1]*__ldg(&g_qval[((size_t)((s+1)*NB + b))*NH + hh]);
                a2 += sZ[s+2]*__ldg(&g_qval[((size_t)((s+2)*NB + b))*NH + hh]);
                a3 += sZ[s+3]*__ldg(&g_qval[((size_t)((s+3)*NB + b))*NH + hh]);
            }
            g_ctx[b*NH + hh] = (a0 + a1) + (a2 + a3);
            __syncthreads();
        }
        gridbar();

        const float* xp = g_dxe + ((size_t)t*NG + u0 + cu)*32 + cb;
        float xg0 = __ldg(&xp[0]);
        float xg1 = __ldg(&xp[(size_t)NH*32]);
        float xg2 = __ldg(&xp[(size_t)2*NH*32]);
        float xg3 = __ldg(&xp[(size_t)3*NH*32]);

        // ---- z GEMM, double-buffered W and H ----
        float acc[4][4] = {};
        float4 pH0, pH1, pH2, pH3, pW0, pW1, pW2, pW3;
        {
            const float* hr = hcur + lb*NH;
            pH0 = __ldcg((const float4*)&hr[4*lq]);
            pH1 = __ldcg((const float4*)&hr[4*(lq+8)]);
            pH2 = __ldcg((const float4*)&hr[4*(lq+16)]);
            pH3 = __ldcg((const float4*)&hr[4*(lq+24)]);
            const float* wrow = dec_Whh + (size_t)wn_*NH;
            pW0 = __ldg((const float4*)&wrow[4*lq]);
            pW1 = __ldg((const float4*)&wrow[4*(lq+8)]);
            pW2 = __ldg((const float4*)&wrow[4*(lq+16)]);
            pW3 = __ldg((const float4*)&wrow[4*(lq+24)]);
            stash4(sH, lq, lb, pH0, pH1, pH2, pH3);
            stash4(sW, lq, wr_, pW0, pW1, pW2, pW3);
        }
        __syncthreads();

        for (int ch = 0; ch < 16; ch++) {
            float* curW = sW + (ch & 1)*(128*36);
            float* curH = sH + (ch & 1)*(128*36);
            if (ch < 15) {
                int cn_ = ch + 1;
                const float* asrc = (cn_ < 8) ? hcur : g_ctx;
                int kc = (cn_ & 7)*128;
                const float* hr = asrc + lb*NH + kc;
                pH0 = __ldcg((const float4*)&hr[4*lq]);
                pH1 = __ldcg((const float4*)&hr[4*(lq+8)]);
                pH2 = __ldcg((const float4*)&hr[4*(lq+16)]);
                pH3 = __ldcg((const float4*)&hr[4*(lq+24)]);
                const float* wrow = (cn_ < 8)
                    ? (dec_Whh + (size_t)wn_*NH + kc)
                    : (dec_Wih + (size_t)wn_*(ND+NH) + ND + kc);
                pW0 = __ldg((const float4*)&wrow[4*lq]);
                pW1 = __ldg((const float4*)&wrow[4*(lq+8)]);
                pW2 = __ldg((const float4*)&wrow[4*(lq+16)]);
                pW3 = __ldg((const float4*)&wrow[4*(lq+24)]);
            }
            for (int kb = 0; kb < 128; kb += 16) {
                int k = kb + 4*ks;
                #pragma unroll
                for (int kk2 = 0; kk2 < 4; kk2++) {
                    float4 wv = *(const float4*)&curW[(k+kk2)*36 + 4*rq];
                    float4 hv = *(const float4*)&curH[(k+kk2)*36 + 4*bq];
                    float wa[4] = {wv.x, wv.y, wv.z, wv.w};
                    float hb[4] = {hv.x, hv.y, hv.z, hv.w};
                    #pragma unroll
                    for (int i = 0; i < 4; i++)
                        #pragma unroll
                        for (int j = 0; j < 4; j++)
                            acc[i][j] += wa[i]*hb[j];
                }
            }
            if (ch < 15) {
                stash4(sH + ((ch & 1) ^ 1)*(128*36), lq, lb, pH0, pH1, pH2, pH3);
                stash4(sW + ((ch & 1) ^ 1)*(128*36), lq, wr_, pW0, pW1, pW2, pW3);
            }
            __syncthreads();
        }

        #pragma unroll
        for (int i = 0; i < 4; i++)
            #pragma unroll
            for (int j = 0; j < 4; j++)
                sZ[(ks*32 + 4*rq + i)*33 + 4*bq + j] = acc[i][j];
        __syncthreads();

        {
            float zg4[4] = {xg0, xg1, xg2, xg3};
            #pragma unroll
            for (int g = 0; g < 4; g++)
                #pragma unroll
                for (int q = 0; q < 4; q++) zg4[g] += sZ[(q*32 + g*8 + cu)*33 + cb];
            float cn = sigmf_(zg4[1])*creg + sigmf_(zg4[0])*tanhf(zg4[2]);
            float hn = sigmf_(zg4[3])*tanhf(cn);
            creg = cn;
            hnew[cb*NH + u0 + cu] = hn;
        }
        __syncthreads();
        gridbar();
    }

    {
        const float* hlast = g_hbuf + ((NT-1) & 1)*(NB*NH);
        dec_feat(NT-1, hlast, out_W, out_b, sH, sZ, fn0);
    }
}

// =============================================================================
extern "C" void kernel_launch(void* const* d_in, const int* in_sizes, int n_in,
                              void* d_out, int out_size)
{
    const float* embed    = (const float*)d_in[0];
    const float* enc_Wih  = (const float*)d_in[1];
    const float* enc_Whh  = (const float*)d_in[2];
    const float* enc_bih  = (const float*)d_in[3];
    const float* enc_bhh  = (const float*)d_in[4];
    const float* dec_Wih  = (const float*)d_in[5];
    const float* dec_Whh  = (const float*)d_in[6];
    const float* dec_bih  = (const float*)d_in[7];
    const float* dec_bhh  = (const float*)d_in[8];
    const float* qk_W     = (const float*)d_in[9];
    const float* qk_b     = (const float*)d_in[10];
    const float* qv_W     = (const float*)d_in[11];
    const float* qv_b     = (const float*)d_in[12];
    const float* ak_W     = (const float*)d_in[13];
    const float* ak_b     = (const float*)d_in[14];
    const float* out_W    = (const float*)d_in[15];
    const float* out_b    = (const float*)d_in[16];
    const float* wd_b     = (const float*)d_in[17];
    const float* hfc1_W   = (const float*)d_in[18];
    const float* hfc1_b   = (const float*)d_in[19];
    const float* hfc2_W   = (const float*)d_in[20];
    const float* hfc2_b   = (const float*)d_in[21];
    const float* cfc1_W   = (const float*)d_in[22];
    const float* cfc1_b   = (const float*)d_in[23];
    const float* cfc2_W   = (const float*)d_in[24];
    const float* cfc2_b   = (const float*)d_in[25];
    const int*   src_seqs = (const int*)d_in[26];
    const int*   src_len  = (const int*)d_in[27];
    const int*   trg_seqs = (const int*)d_in[28];
    float* out = (float*)d_out;

    float *d_src_embed, *d_ans_embed, *d_xproj, *d_dxe, *d_h, *d_c;
    float *d_enc_out, *d_qkey, *d_qval, *d_tmp, *d_feat;
    cudaGetSymbolAddress((void**)&d_src_embed, g_src_embed);
    cudaGetSymbolAddress((void**)&d_ans_embed, g_ans_embed);
    cudaGetSymbolAddress((void**)&d_xproj,     g_xproj);
    cudaGetSymbolAddress((void**)&d_dxe,       g_dxe);
    cudaGetSymbolAddress((void**)&d_h,         g_h);
    cudaGetSymbolAddress((void**)&d_c,         g_c);
    cudaGetSymbolAddress((void**)&d_enc_out,   g_enc_out);
    cudaGetSymbolAddress((void**)&d_qkey,      g_qkey);
    cudaGetSymbolAddress((void**)&d_qval,      g_qval);
    cudaGetSymbolAddress((void**)&d_tmp,       g_tmp);
    cudaGetSymbolAddress((void**)&d_feat,      g_feat);

    // ---- precompute ----
    k_gather<<<NS*NB, 128>>>(src_seqs, NS, embed, d_src_embed);
    k_gather<<<NT*NB, 128>>>(trg_seqs, 20, embed, d_ans_embed);

    k_sgemm<<<dim3(NG/64, (NS*NB)/128), 256>>>(NS*NB, NG, ND,
        d_src_embed, ND, enc_Wih, ND, enc_bih, enc_bhh, d_xproj, NG, 0, 2);
    k_sgemm<<<dim3(NG/64, (NT*NB + 127)/128), 256>>>(NT*NB, NG, ND,
        d_ans_embed, ND, dec_Wih, ND + NH, dec_bih, dec_bhh, d_dxe, NG, 0, 2);

    // ---- encoder recurrence ----
    const int enc_smem = (1024*36 + 2*128*36 + 4*32*33) * (int)sizeof(float);
    cudaFuncSetAttribute(k_enc_persist,
                         cudaFuncAttributeMaxDynamicSharedMemorySize, enc_smem);
    k_enc_persist<<<NBLK, 256, enc_smem>>>(enc_Whh, src_len);

    // ---- bridge MLPs ----
    k_sgemm<<<dim3(2048/64, 1), 256>>>(NB, 2048, NH, d_h, NH, hfc1_W, NH,
                                       hfc1_b, nullptr, d_tmp, 2048, 2, 0);
    k_sgemm<<<dim3(NH/64, 1), 256>>>(NB, NH, 2048, d_tmp, 2048, hfc2_W, 2048,
                                     hfc2_b, nullptr, d_h, NH, 0, 0);
    k_sgemm<<<dim3(2048/64, 1), 256>>>(NB, 2048, NH, d_c, NH, cfc1_W, NH,
                                       cfc1_b, nullptr, d_tmp, 2048, 2, 0);
    k_sgemm<<<dim3(NH/64, 1), 256>>>(NB, NH, 2048, d_tmp, 2048, cfc2_W, 2048,
                                     cfc2_b, nullptr, d_c, NH, 0, 0);

    // ---- attention precompute ----
    k_sgemm<<<dim3((NK + 63)/64, (NS*NB)/128), 256>>>(NS*NB, NK, NH,
        d_enc_out, NH, qk_W, NH, qk_b, nullptr, d_qkey, NK, 1, 0);
    k_sgemm<<<dim3(NH/64, (NS*NB)/128), 256>>>(NS*NB, NH, NH,
        d_enc_out, NH, qv_W, NH, qv_b, nullptr, d_qval, NH, 0, 0);

    // ---- decoder recurrence ----
    const int dec_smem = (4*128*36 + 4*32*33) * (int)sizeof(float);
    cudaFuncSetAttribute(k_dec_persist,
                         cudaFuncAttributeMaxDynamicSharedMemorySize, dec_smem);
    k_dec_persist<<<NBLK, 256, dec_smem>>>(dec_Wih, dec_Whh, ak_W, ak_b,
                                           out_W, out_b, src_len);

    // ---- final logits ----
    k_sgemm<<<dim3(NV/64, (NT*NB + 127)/128), 256>>>(NT*NB, NV, ND,
        d_feat, ND, embed, ND, wd_b, nullptr, out, NV, 0, 1);

    (void)in_sizes; (void)n_in; (void)out_size;
}

// round 6
// speedup vs baseline: 1.3955x; 1.0909x over previous
#include <cuda_runtime.h>
#include <math.h>
#include <stdint.h>

// Problem dims (fixed by the dataset)
#define NB 32      // batch
#define NS 128     // src seq len
#define NT 19      // decoder steps (T-1)
#define ND 512     // embed dim
#define NH 1024    // hidden
#define NG 4096    // 4*H
#define NK 100     // attn key dim
#define NV 32000   // vocab
#define NBLK 128

typedef unsigned long long ull_t;

// ------------------------- scratch (device globals; no allocs) ---------------
__device__ float g_src_embed[NS*NB*ND];
__device__ float g_ans_embed[NT*NB*ND];
__device__ float g_xproj[NS*NG*NB];         // [s][n][b]
__device__ float g_dxe[NT*NG*NB];           // [t][n][b]
__device__ float g_h[NB*NH];
__device__ float g_c[NB*NH];
__device__ float g_hbuf[2*NB*NH];
__device__ float g_enc_out[NS*NB*NH];
__device__ float g_qkey[NS*NB*NK];
__device__ float g_qval[NS*NB*NH];
__device__ float g_tmp[NB*2048];
__device__ float g_ctx[NB*NH];
__device__ float g_attw[NB*NS];
__device__ float g_feat[NT*NB*ND];

__device__ unsigned g_barcnt = 0;
__device__ unsigned g_bargen = 0;

__device__ __forceinline__ float sigmf_(float x) { return 1.0f/(1.0f+expf(-x)); }

// ---- packed f32x2 helpers (Blackwell FFMA2 path) ----
__device__ __forceinline__ void ffma2(ull_t& d, ull_t a, ull_t b)
{
    asm("fma.rn.f32x2 %0, %1, %2, %3;" : "=l"(d) : "l"(a), "l"(b), "l"(d));
}
__device__ __forceinline__ ull_t dup2(float x)
{
    ull_t r;
    asm("mov.b64 %0, {%1, %1};" : "=l"(r) : "f"(x));
    return r;
}
__device__ __forceinline__ float2 unpk(ull_t v)
{
    float2 r;
    asm("mov.b64 {%0, %1}, %2;" : "=f"(r.x), "=f"(r.y) : "l"(v));
    return r;
}

__device__ __forceinline__ void gridbar()
{
    __syncthreads();
    if (threadIdx.x == 0) {
        __threadfence();
        volatile unsigned* vgen = &g_bargen;
        unsigned gen = *vgen;
        if (atomicAdd(&g_barcnt, 1u) == NBLK - 1) {
            g_barcnt = 0;
            __threadfence();
            atomicAdd(&g_bargen, 1u);
        } else {
            while (*vgen == gen) { __nanosleep(16); }
        }
        __threadfence();
    }
    __syncthreads();
}

// helper: scatter 4 prefetched float4s (rows kk=4*(lq+8p)) into tile[k][row]
__device__ __forceinline__ void stash4(float* buf, int lq, int row,
                                       float4 p0, float4 p1, float4 p2, float4 p3)
{
    buf[(4*lq+0)*36+row]=p0.x; buf[(4*lq+1)*36+row]=p0.y;
    buf[(4*lq+2)*36+row]=p0.z; buf[(4*lq+3)*36+row]=p0.w;
    buf[(4*(lq+8)+0)*36+row]=p1.x; buf[(4*(lq+8)+1)*36+row]=p1.y;
    buf[(4*(lq+8)+2)*36+row]=p1.z; buf[(4*(lq+8)+3)*36+row]=p1.w;
    buf[(4*(lq+16)+0)*36+row]=p2.x; buf[(4*(lq+16)+1)*36+row]=p2.y;
    buf[(4*(lq+16)+2)*36+row]=p2.z; buf[(4*(lq+16)+3)*36+row]=p2.w;
    buf[(4*(lq+24)+0)*36+row]=p3.x; buf[(4*(lq+24)+1)*36+row]=p3.y;
    buf[(4*(lq+24)+2)*36+row]=p3.z; buf[(4*(lq+24)+3)*36+row]=p3.w;
}

// ------------------------- embedding gather ---------------------------------
__global__ void k_gather(const int* __restrict__ seq, int seq_stride,
                         const float* __restrict__ embed, float* __restrict__ out)
{
    int row = blockIdx.x;
    int st  = row / NB;
    int b   = row % NB;
    int tok = seq[b*seq_stride + st];
    const float4* src = (const float4*)(embed + (size_t)tok*ND);
    float4*       dst = (float4*)(out + (size_t)row*ND);
    dst[threadIdx.x] = src[threadIdx.x];
}

// ------------------------- tiled SGEMM, BM=128 BN=64 BK=16, f32x2 core -------
__global__ __launch_bounds__(256)
void k_sgemm(int M, int N, int K,
             const float* __restrict__ A, int lda,
             const float* __restrict__ W, int ldw,
             const float* __restrict__ bias1, const float* __restrict__ bias2,
             float* __restrict__ C, int ldc, int act, int out_map)
{
    __shared__ float As[16][132];   // [k][m]
    __shared__ float Ws[16][68];    // [k][n]
    __shared__ float Cs[64][132];   // staging for out_map==2
    int tid = threadIdx.x;
    int m0 = blockIdx.y*128, n0 = blockIdx.x*64;
    int alr = tid & 127;
    int aq0 = (tid >> 7) * 4;
    int wlr = tid >> 2;
    int wlc = (tid & 3) << 2;
    int ty = tid >> 4;
    int tx = tid & 15;
    ull_t acc2[4][4] = {};          // [m-pair][n]

    for (int k0 = 0; k0 < K; k0 += 16) {
        float4 a0 = make_float4(0.f,0.f,0.f,0.f);
        float4 a1 = make_float4(0.f,0.f,0.f,0.f);
        float4 w4 = make_float4(0.f,0.f,0.f,0.f);
        if (m0+alr < M) {
            a0 = *(const float4*)(A + (size_t)(m0+alr)*lda + k0 + aq0);
            a1 = *(const float4*)(A + (size_t)(m0+alr)*lda + k0 + aq0 + 8);
        }
        if (n0+wlr < N) w4 = *(const float4*)(W + (size_t)(n0+wlr)*ldw + k0 + wlc);
        __syncthreads();
        As[aq0+0][alr] = a0.x; As[aq0+1][alr] = a0.y;
        As[aq0+2][alr] = a0.z; As[aq0+3][alr] = a0.w;
        As[aq0+8][alr] = a1.x; As[aq0+9][alr] = a1.y;
        As[aq0+10][alr] = a1.z; As[aq0+11][alr] = a1.w;
        Ws[wlc+0][wlr] = w4.x; Ws[wlc+1][wlr] = w4.y;
        Ws[wlc+2][wlr] = w4.z; Ws[wlc+3][wlr] = w4.w;
        __syncthreads();
#pragma unroll
        for (int k = 0; k < 16; k++) {
            ulonglong2 a01 = *(const ulonglong2*)&As[k][ty*8];
            ulonglong2 a23 = *(const ulonglong2*)&As[k][ty*8+4];
            float4 wv  = *(const float4*)&Ws[k][tx*4];
            ull_t d0 = dup2(wv.x), d1 = dup2(wv.y), d2 = dup2(wv.z), d3 = dup2(wv.w);
            ffma2(acc2[0][0], a01.x, d0); ffma2(acc2[0][1], a01.x, d1);
            ffma2(acc2[0][2], a01.x, d2); ffma2(acc2[0][3], a01.x, d3);
            ffma2(acc2[1][0], a01.y, d0); ffma2(acc2[1][1], a01.y, d1);
            ffma2(acc2[1][2], a01.y, d2); ffma2(acc2[1][3], a01.y, d3);
            ffma2(acc2[2][0], a23.x, d0); ffma2(acc2[2][1], a23.x, d1);
            ffma2(acc2[2][2], a23.x, d2); ffma2(acc2[2][3], a23.x, d3);
            ffma2(acc2[3][0], a23.y, d0); ffma2(acc2[3][1], a23.y, d1);
            ffma2(acc2[3][2], a23.y, d2); ffma2(acc2[3][3], a23.y, d3);
        }
    }

    float acc[8][4];
#pragma unroll
    for (int mp = 0; mp < 4; mp++)
#pragma unroll
        for (int j = 0; j < 4; j++) {
            float2 t = unpk(acc2[mp][j]);
            acc[2*mp+0][j] = t.x;
            acc[2*mp+1][j] = t.y;
        }

    if (out_map == 2) {
        __syncthreads();
#pragma unroll
        for (int i = 0; i < 8; i++) {
            int ml = ty*8 + i;
#pragma unroll
            for (int j = 0; j < 4; j++) {
                int nl = tx*4 + j;
                float v = acc[i][j] + bias1[n0+nl];
                if (bias2) v += bias2[n0+nl];
                Cs[nl][ml] = v;
            }
        }
        __syncthreads();
        for (int c = tid; c < 2048; c += 256) {
            int qb = (c & 7) * 4;
            int nl = (c >> 3) & 63;
            int sh = c >> 9;
            int mgrp = m0 + sh*32;
            if (mgrp < M) {
                float4 v4 = *(const float4*)&Cs[nl][sh*32 + qb];
                *(float4*)&C[((size_t)(mgrp >> 5)*NG + n0 + nl)*32 + qb] = v4;
            }
        }
        return;
    }

#pragma unroll
    for (int i = 0; i < 8; i++) {
        int m = m0 + ty*8 + i;
        if (m >= M) continue;
        size_t row = (out_map == 1) ? (size_t)((m & 31)*NT + (m >> 5)) : (size_t)m;
        int n = n0 + tx*4;
        float v[4];
#pragma unroll
        for (int j = 0; j < 4; j++) {
            float x = acc[i][j] + ((n+j < N) ? bias1[n+j] : 0.f);
            if (bias2 && n+j < N) x += bias2[n+j];
            if (act == 1)      x = tanhf(x);
            else if (act == 2) x = fmaxf(x, 0.0f);
            v[j] = x;
        }
        if (n + 3 < N) {
            *(float4*)&C[row*ldc + n] = make_float4(v[0], v[1], v[2], v[3]);
        } else {
#pragma unroll
            for (int j = 0; j < 4; j++)
                if (n + j < N) C[row*ldc + n + j] = v[j];
        }
    }
}

// ------------------------- persistent encoder -------------------------------
// Thread map (GEMM): bq = tid>>5 (warp id -> 4-batch quad), ks = (tid>>3)&3,
// rq = tid&7 (4 gate rows). Warp-level skip when its batch quad is frozen.
__global__ void __launch_bounds__(256, 1)
k_enc_persist(const float* __restrict__ Whh, const int* __restrict__ lengths)
{
    extern __shared__ float sm[];
    float* sWt = sm;                          // [1024][36]
    float* sHs = sm + 1024*36;                // 2 x [128][36]
    float* sZs = sm + 1024*36 + 2*128*36;     // [4][32][33]

    int tid = threadIdx.x;
    int u0  = blockIdx.x * 8;

    for (int r = 0; r < 32; r++) {
        int n = (r >> 3)*NH + u0 + (r & 7);
        float4 w4 = *(const float4*)&Whh[(size_t)n*NH + 4*tid];
        sWt[(4*tid+0)*36 + r] = w4.x;
        sWt[(4*tid+1)*36 + r] = w4.y;
        sWt[(4*tid+2)*36 + r] = w4.z;
        sWt[(4*tid+3)*36 + r] = w4.w;
    }

    int cb = tid & 31;
    int cu = tid >> 5;
    int mylen = lengths[cb];
    int wq = tid >> 5;               // warp id == batch quad
    int qlen = 0;
    #pragma unroll
    for (int i = 0; i < 4; i++) qlen = max(qlen, lengths[4*wq + i]);
    float creg = 0.0f, hreg = 0.0f;

    g_hbuf[cb*NH + u0 + cu] = 0.0f;

    int rq = tid & 7;
    int bq = tid >> 5;               // 0..7, warp-uniform
    int ks = (tid >> 3) & 3;
    int lb = tid >> 3;               // loader batch row; warp covers 4w..4w+3
    int lq = tid & 7;

    gridbar();

    for (int s = 0; s < NS; s++) {
        const float* hin  = g_hbuf + (s & 1)*(NB*NH);
        float*       hout = g_hbuf + ((s & 1) ^ 1)*(NB*NH);
        bool active = (s < qlen);    // warp-uniform

        const float* xp = g_xproj + ((size_t)s*NG + u0 + cu)*32 + cb;
        float xg0 = __ldg(&xp[0]);
        float xg1 = __ldg(&xp[(size_t)NH*32]);
        float xg2 = __ldg(&xp[(size_t)2*NH*32]);
        float xg3 = __ldg(&xp[(size_t)3*NH*32]);

        float4 p0, p1, p2, p3;
        if (active) {
            const float* hr = hin + lb*NH;
            p0 = __ldcg((const float4*)&hr[4*lq]);
            p1 = __ldcg((const float4*)&hr[4*(lq+8)]);
            p2 = __ldcg((const float4*)&hr[4*(lq+16)]);
            p3 = __ldcg((const float4*)&hr[4*(lq+24)]);
            stash4(sHs, lq, lb, p0, p1, p2, p3);
        }
        __syncthreads();

        ull_t acc2[4][2] = {};       // [row][batch-pair]
        for (int ci = 0; ci < 8; ci++) {
            float* cur = sHs + (ci & 1)*(128*36);
            if (ci < 7 && active) {
                const float* hr = hin + lb*NH + (ci+1)*128;
                p0 = __ldcg((const float4*)&hr[4*lq]);
                p1 = __ldcg((const float4*)&hr[4*(lq+8)]);
                p2 = __ldcg((const float4*)&hr[4*(lq+16)]);
                p3 = __ldcg((const float4*)&hr[4*(lq+24)]);
            }
            if (active) {
                int kc = ci*128;
                for (int kb = 0; kb < 128; kb += 16) {
                    int k = kb + 4*ks;
                    #pragma unroll
                    for (int kk2 = 0; kk2 < 4; kk2++) {
                        float4 wv = *(const float4*)&sWt[(kc+k+kk2)*36 + 4*rq];
                        ulonglong2 hq = *(const ulonglong2*)&cur[(k+kk2)*36 + 4*bq];
                        ull_t d0 = dup2(wv.x), d1 = dup2(wv.y);
                        ull_t d2 = dup2(wv.z), d3 = dup2(wv.w);
                        ffma2(acc2[0][0], d0, hq.x); ffma2(acc2[0][1], d0, hq.y);
                        ffma2(acc2[1][0], d1, hq.x); ffma2(acc2[1][1], d1, hq.y);
                        ffma2(acc2[2][0], d2, hq.x); ffma2(acc2[2][1], d2, hq.y);
                        ffma2(acc2[3][0], d3, hq.x); ffma2(acc2[3][1], d3, hq.y);
                    }
                }
            }
            if (ci < 7 && active)
                stash4(sHs + ((ci & 1) ^ 1)*(128*36), lq, lb, p0, p1, p2, p3);
            __syncthreads();
        }

        #pragma unroll
        for (int i = 0; i < 4; i++) {
            float2 t0 = unpk(acc2[i][0]);
            float2 t1 = unpk(acc2[i][1]);
            float* zr = &sZs[(ks*32 + 4*rq + i)*33 + 4*bq];
            zr[0] = t0.x; zr[1] = t0.y; zr[2] = t1.x; zr[3] = t1.y;
        }
        __syncthreads();

        float zg4[4] = {xg0, xg1, xg2, xg3};
        #pragma unroll
        for (int g = 0; g < 4; g++)
            #pragma unroll
            for (int q = 0; q < 4; q++) zg4[g] += sZs[(q*32 + g*8 + cu)*33 + cb];
        float cn = sigmf_(zg4[1])*creg + sigmf_(zg4[0])*tanhf(zg4[2]);
        float hn = sigmf_(zg4[3])*tanhf(cn);
        bool msk = (s < mylen);
        creg = msk ? cn : creg;
        hreg = msk ? hn : hreg;
        hout[cb*NH + u0 + cu] = hreg;
        g_enc_out[((size_t)(s*NB + cb))*NH + u0 + cu] = msk ? hreg : 0.0f;

        gridbar();
    }

    g_h[cb*NH + u0 + cu] = hreg;
    g_c[cb*NH + u0 + cu] = creg;
}

// ------------------------- persistent decoder helpers -----------------------
__device__ __forceinline__ void dec_feat(int tt, const float* __restrict__ hsrc,
    const float* __restrict__ out_W, const float* __restrict__ out_b,
    float* sH, float* sZ, int fn0)
{
    int tid = threadIdx.x;
    int r   = tid >> 6;
    int fks = (tid >> 5) & 1;
    int fb  = tid & 31;
    int lb  = tid >> 3;
    int lq  = tid & 7;
    const float* wrow = out_W + (size_t)(fn0 + r)*(2*NH);
    float fa = 0.f;

    float4 p0, p1, p2, p3;
    {
        const float* hr = hsrc + lb*NH;
        p0 = __ldcg((const float4*)&hr[4*lq]);
        p1 = __ldcg((const float4*)&hr[4*(lq+8)]);
        p2 = __ldcg((const float4*)&hr[4*(lq+16)]);
        p3 = __ldcg((const float4*)&hr[4*(lq+24)]);
        stash4(sH, lq, lb, p0, p1, p2, p3);
    }
    __syncthreads();

    for (int ch = 0; ch < 16; ch++) {
        float* cur = sH + (ch & 1)*(128*36);
        if (ch < 15) {
            int cn_ = ch + 1;
            const float* src = (cn_ < 8) ? hsrc : g_ctx;
            const float* hr = src + lb*NH + (cn_ & 7)*128;
            p0 = __ldcg((const float4*)&hr[4*lq]);
            p1 = __ldcg((const float4*)&hr[4*(lq+8)]);
            p2 = __ldcg((const float4*)&hr[4*(lq+16)]);
            p3 = __ldcg((const float4*)&hr[4*(lq+24)]);
        }
        const float* wc = wrow + ch*128 + fks*64;
        const float* hc = cur + fks*64*36 + fb;
        #pragma unroll 16
        for (int k = 0; k < 64; k++)
            fa += __ldg(&wc[k]) * hc[k*36];
        if (ch < 15)
            stash4(sH + ((ch & 1) ^ 1)*(128*36), lq, lb, p0, p1, p2, p3);
        __syncthreads();
    }
    sZ[(r*2 + fks)*33 + fb] = fa;
    __syncthreads();
    if (tid < 128) {
        int rr = tid >> 5, bb = tid & 31;
        float v = sZ[(rr*2)*33 + bb] + sZ[(rr*2+1)*33 + bb] + __ldg(&out_b[fn0 + rr]);
        g_feat[((size_t)(tt*NB + bb))*ND + fn0 + rr] = v;
    }
    __syncthreads();
}

__device__ __forceinline__ void dec_attn(int b, int mylen,
    const float* __restrict__ hcur,
    const float* __restrict__ ak_W, const float* __restrict__ ak_b,
    float* sW)
{
    int tid = threadIdx.x;
    float* sh_ = sW;
    float* sak = sW + 1024;
    float* se  = sW + 1152;
    float* sr  = sW + 1280;

    for (int i = tid; i < NH; i += 256) sh_[i] = __ldcg(&hcur[b*NH + i]);
    __syncthreads();

    if (tid < NK) {
        const float* wr = ak_W + (size_t)tid*NH;
        float acc0 = 0.f, acc1 = 0.f;
        for (int k = 0; k < NH; k += 8) {
            float4 w0 = *(const float4*)&wr[k];
            float4 w1 = *(const float4*)&wr[k+4];
            float4 h0 = *(const float4*)&sh_[k];
            float4 h1 = *(const float4*)&sh_[k+4];
            acc0 += w0.x*h0.x + w0.y*h0.y + w0.z*h0.z + w0.w*h0.w;
            acc1 += w1.x*h1.x + w1.y*h1.y + w1.z*h1.z + w1.w*h1.w;
        }
        sak[tid] = tanhf(acc0 + acc1 + ak_b[tid]);
    }
    __syncthreads();

    if (tid < NS) {
        const float* qr = g_qkey + ((size_t)(tid*NB + b))*NK;
        float acc = 0.f;
        for (int k = 0; k < NK; k++) acc += qr[k]*sak[k];
        se[tid] = (tid < mylen) ? acc : -INFINITY;
    }
    __syncthreads();

    sr[tid] = (tid < NS) ? se[tid] : -INFINITY;
    __syncthreads();
    for (int off = 128; off >= 1; off >>= 1) {
        if (tid < off) sr[tid] = fmaxf(sr[tid], sr[tid+off]);
        __syncthreads();
    }
    float mx = sr[0];
    __syncthreads();

    float ex = (tid < NS) ? expf(se[tid] - mx) : 0.0f;
    sr[tid] = ex;
    __syncthreads();
    for (int off = 128; off >= 1; off >>= 1) {
        if (tid < off) sr[tid] += sr[tid+off];
        __syncthreads();
    }
    float inv = 1.0f / sr[0];
    __syncthreads();
    if (tid < NS) g_attw[b*NS + tid] = ex * inv;
    __syncthreads();
}

// ------------------------- persistent decoder -------------------------------
__global__ void __launch_bounds__(256, 1)
k_dec_persist(const float* __restrict__ dec_Wih, const float* __restrict__ dec_Whh,
              const float* __restrict__ ak_W,   const float* __restrict__ ak_b,
              const float* __restrict__ out_W,  const float* __restrict__ out_b,
              const int* __restrict__ lengths)
{
    extern __shared__ float sm[];
    float* sW = sm;                     // 2 x [128][36]
    float* sH = sm + 2*128*36;          // 2 x [128][36]
    float* sZ = sm + 4*128*36;          // [4][32][33]

    int tid = threadIdx.x;
    int blk = blockIdx.x;
    int u0  = blk * 8;
    int fn0 = blk * 4;

    int cb = tid & 31, cu = tid >> 5;
    float creg = g_c[cb*NH + u0 + cu];

    int rq = tid & 7;
    int bq = (tid >> 3) & 7;
    int ks = tid >> 6;
    int lb = tid >> 3;
    int lq = tid & 7;
    int wr_ = tid >> 3;
    int wn_ = (wr_ >> 3)*NH + u0 + (wr_ & 7);

    int mylen = (blk < 32) ? lengths[blk] : 0;

    for (int t = 0; t < NT; t++) {
        const float* hcur = (t == 0) ? g_h : (g_hbuf + ((t-1) & 1)*(NB*NH));
        float*       hnew = g_hbuf + (t & 1)*(NB*NH);

        if (t > 0)
            dec_feat(t-1, hcur, out_W, out_b, sH, sZ, fn0);
        if (blk < 32)
            dec_attn(blk, mylen, hcur, ak_W, ak_b, sW);
        gridbar();

        // ---- context ----
        {
            int b  = blk & 31;
            int hq = blk >> 5;
            if (tid < NS) sZ[tid] = __ldcg(&g_attw[b*NS + tid]);
            __syncthreads();
            int hh = hq*256 + tid;
            float a0 = 0.f, a1 = 0.f, a2 = 0.f, a3 = 0.f;
            #pragma unroll 4
            for (int s = 0; s < NS; s += 4) {
                a0 += sZ[s+0]*__ldg(&g_qval[((size_t)((s+0)*NB + b))*NH + hh]);
                a1 += sZ[s+1]*__ldg(&g_qval[((size_t)((s+1)*NB + b))*NH + hh]);
                a2 += sZ[s+2]*__ldg(&g_qval[((size_t)((s+2)*NB + b))*NH + hh]);
                a3 += sZ[s+3]*__ldg(&g_qval[((size_t)((s+3)*NB + b))*NH + hh]);
            }
            g_ctx[b*NH + hh] = (a0 + a1) + (a2 + a3);
            __syncthreads();
        }
        gridbar();

        const float* xp = g_dxe + ((size_t)t*NG + u0 + cu)*32 + cb;
        float xg0 = __ldg(&xp[0]);
        float xg1 = __ldg(&xp[(size_t)NH*32]);
        float xg2 = __ldg(&xp[(size_t)2*NH*32]);
        float xg3 = __ldg(&xp[(size_t)3*NH*32]);

        // ---- z GEMM, double-buffered W and H, f32x2 core ----
        ull_t acc2[4][2] = {};
        float4 pH0, pH1, pH2, pH3, pW0, pW1, pW2, pW3;
        {
            const float* hr = hcur + lb*NH;
            pH0 = __ldcg((const float4*)&hr[4*lq]);
            pH1 = __ldcg((const float4*)&hr[4*(lq+8)]);
            pH2 = __ldcg((const float4*)&hr[4*(lq+16)]);
            pH3 = __ldcg((const float4*)&hr[4*(lq+24)]);
            const float* wrow = dec_Whh + (size_t)wn_*NH;
            pW0 = __ldg((const float4*)&wrow[4*lq]);
            pW1 = __ldg((const float4*)&wrow[4*(lq+8)]);
            pW2 = __ldg((const float4*)&wrow[4*(lq+16)]);
            pW3 = __ldg((const float4*)&wrow[4*(lq+24)]);
            stash4(sH, lq, lb, pH0, pH1, pH2, pH3);
            stash4(sW, lq, wr_, pW0, pW1, pW2, pW3);
        }
        __syncthreads();

        for (int ch = 0; ch < 16; ch++) {
            float* curW = sW + (ch & 1)*(128*36);
            float* curH = sH + (ch & 1)*(128*36);
            if (ch < 15) {
                int cn_ = ch + 1;
                const float* asrc = (cn_ < 8) ? hcur : g_ctx;
                int kc = (cn_ & 7)*128;
                const float* hr = asrc + lb*NH + kc;
                pH0 = __ldcg((const float4*)&hr[4*lq]);
                pH1 = __ldcg((const float4*)&hr[4*(lq+8)]);
                pH2 = __ldcg((const float4*)&hr[4*(lq+16)]);
                pH3 = __ldcg((const float4*)&hr[4*(lq+24)]);
                const float* wrow = (cn_ < 8)
                    ? (dec_Whh + (size_t)wn_*NH + kc)
                    : (dec_Wih + (size_t)wn_*(ND+NH) + ND + kc);
                pW0 = __ldg((const float4*)&wrow[4*lq]);
                pW1 = __ldg((const float4*)&wrow[4*(lq+8)]);
                pW2 = __ldg((const float4*)&wrow[4*(lq+16)]);
                pW3 = __ldg((const float4*)&wrow[4*(lq+24)]);
            }
            for (int kb = 0; kb < 128; kb += 16) {
                int k = kb + 4*ks;
                #pragma unroll
                for (int kk2 = 0; kk2 < 4; kk2++) {
                    float4 wv = *(const float4*)&curW[(k+kk2)*36 + 4*rq];
                    ulonglong2 hq2 = *(const ulonglong2*)&curH[(k+kk2)*36 + 4*bq];
                    ull_t d0 = dup2(wv.x), d1 = dup2(wv.y);
                    ull_t d2 = dup2(wv.z), d3 = dup2(wv.w);
                    ffma2(acc2[0][0], d0, hq2.x); ffma2(acc2[0][1], d0, hq2.y);
                    ffma2(acc2[1][0], d1, hq2.x); ffma2(acc2[1][1], d1, hq2.y);
                    ffma2(acc2[2][0], d2, hq2.x); ffma2(acc2[2][1], d2, hq2.y);
                    ffma2(acc2[3][0], d3, hq2.x); ffma2(acc2[3][1], d3, hq2.y);
                }
            }
            if (ch < 15) {
                stash4(sH + ((ch & 1) ^ 1)*(128*36), lq, lb, pH0, pH1, pH2, pH3);
                stash4(sW + ((ch & 1) ^ 1)*(128*36), lq, wr_, pW0, pW1, pW2, pW3);
            }
            __syncthreads();
        }

        #pragma unroll
        for (int i = 0; i < 4; i++) {
            float2 t0 = unpk(acc2[i][0]);
            float2 t1 = unpk(acc2[i][1]);
            float* zr = &sZ[(ks*32 + 4*rq + i)*33 + 4*bq];
            zr[0] = t0.x; zr[1] = t0.y; zr[2] = t1.x; zr[3] = t1.y;
        }
        __syncthreads();

        {
            float zg4[4] = {xg0, xg1, xg2, xg3};
            #pragma unroll
            for (int g = 0; g < 4; g++)
                #pragma unroll
                for (int q = 0; q < 4; q++) zg4[g] += sZ[(q*32 + g*8 + cu)*33 + cb];
            float cn = sigmf_(zg4[1])*creg + sigmf_(zg4[0])*tanhf(zg4[2]);
            float hn = sigmf_(zg4[3])*tanhf(cn);
            creg = cn;
            hnew[cb*NH + u0 + cu] = hn;
        }
        __syncthreads();
        gridbar();
    }

    {
        const float* hlast = g_hbuf + ((NT-1) & 1)*(NB*NH);
        dec_feat(NT-1, hlast, out_W, out_b, sH, sZ, fn0);
    }
}

// =============================================================================
extern "C" void kernel_launch(void* const* d_in, const int* in_sizes, int n_in,
                              void* d_out, int out_size)
{
    const float* embed    = (const float*)d_in[0];
    const float* enc_Wih  = (const float*)d_in[1];
    const float* enc_Whh  = (const float*)d_in[2];
    const float* enc_bih  = (const float*)d_in[3];
    const float* enc_bhh  = (const float*)d_in[4];
    const float* dec_Wih  = (const float*)d_in[5];
    const float* dec_Whh  = (const float*)d_in[6];
    const float* dec_bih  = (const float*)d_in[7];
    const float* dec_bhh  = (const float*)d_in[8];
    const float* qk_W     = (const float*)d_in[9];
    const float* qk_b     = (const float*)d_in[10];
    const float* qv_W     = (const float*)d_in[11];
    const float* qv_b     = (const float*)d_in[12];
    const float* ak_W     = (const float*)d_in[13];
    const float* ak_b     = (const float*)d_in[14];
    const float* out_W    = (const float*)d_in[15];
    const float* out_b    = (const float*)d_in[16];
    const float* wd_b     = (const float*)d_in[17];
    const float* hfc1_W   = (const float*)d_in[18];
    const float* hfc1_b   = (const float*)d_in[19];
    const float* hfc2_W   = (const float*)d_in[20];
    const float* hfc2_b   = (const float*)d_in[21];
    const float* cfc1_W   = (const float*)d_in[22];
    const float* cfc1_b   = (const float*)d_in[23];
    const float* cfc2_W   = (const float*)d_in[24];
    const float* cfc2_b   = (const float*)d_in[25];
    const int*   src_seqs = (const int*)d_in[26];
    const int*   src_len  = (const int*)d_in[27];
    const int*   trg_seqs = (const int*)d_in[28];
    float* out = (float*)d_out;

    float *d_src_embed, *d_ans_embed, *d_xproj, *d_dxe, *d_h, *d_c;
    float *d_enc_out, *d_qkey, *d_qval, *d_tmp, *d_feat;
    cudaGetSymbolAddress((void**)&d_src_embed, g_src_embed);
    cudaGetSymbolAddress((void**)&d_ans_embed, g_ans_embed);
    cudaGetSymbolAddress((void**)&d_xproj,     g_xproj);
    cudaGetSymbolAddress((void**)&d_dxe,       g_dxe);
    cudaGetSymbolAddress((void**)&d_h,         g_h);
    cudaGetSymbolAddress((void**)&d_c,         g_c);
    cudaGetSymbolAddress((void**)&d_enc_out,   g_enc_out);
    cudaGetSymbolAddress((void**)&d_qkey,      g_qkey);
    cudaGetSymbolAddress((void**)&d_qval,      g_qval);
    cudaGetSymbolAddress((void**)&d_tmp,       g_tmp);
    cudaGetSymbolAddress((void**)&d_feat,      g_feat);

    // ---- precompute ----
    k_gather<<<NS*NB, 128>>>(src_seqs, NS, embed, d_src_embed);
    k_gather<<<NT*NB, 128>>>(trg_seqs, 20, embed, d_ans_embed);

    k_sgemm<<<dim3(NG/64, (NS*NB)/128), 256>>>(NS*NB, NG, ND,
        d_src_embed, ND, enc_Wih, ND, enc_bih, enc_bhh, d_xproj, NG, 0, 2);
    k_sgemm<<<dim3(NG/64, (NT*NB + 127)/128), 256>>>(NT*NB, NG, ND,
        d_ans_embed, ND, dec_Wih, ND + NH, dec_bih, dec_bhh, d_dxe, NG, 0, 2);

    // ---- encoder recurrence ----
    const int enc_smem = (1024*36 + 2*128*36 + 4*32*33) * (int)sizeof(float);
    cudaFuncSetAttribute(k_enc_persist,
                         cudaFuncAttributeMaxDynamicSharedMemorySize, enc_smem);
    k_enc_persist<<<NBLK, 256, enc_smem>>>(enc_Whh, src_len);

    // ---- bridge MLPs ----
    k_sgemm<<<dim3(2048/64, 1), 256>>>(NB, 2048, NH, d_h, NH, hfc1_W, NH,
                                       hfc1_b, nullptr, d_tmp, 2048, 2, 0);
    k_sgemm<<<dim3(NH/64, 1), 256>>>(NB, NH, 2048, d_tmp, 2048, hfc2_W, 2048,
                                     hfc2_b, nullptr, d_h, NH, 0, 0);
    k_sgemm<<<dim3(2048/64, 1), 256>>>(NB, 2048, NH, d_c, NH, cfc1_W, NH,
                                       cfc1_b, nullptr, d_tmp, 2048, 2, 0);
    k_sgemm<<<dim3(NH/64, 1), 256>>>(NB, NH, 2048, d_tmp, 2048, cfc2_W, 2048,
                                     cfc2_b, nullptr, d_c, NH, 0, 0);

    // ---- attention precompute ----
    k_sgemm<<<dim3((NK + 63)/64, (NS*NB)/128), 256>>>(NS*NB, NK, NH,
        d_enc_out, NH, qk_W, NH, qk_b, nullptr, d_qkey, NK, 1, 0);
    k_sgemm<<<dim3(NH/64, (NS*NB)/128), 256>>>(NS*NB, NH, NH,
        d_enc_out, NH, qv_W, NH, qv_b, nullptr, d_qval, NH, 0, 0);

    // ---- decoder recurrence ----
    const int dec_smem = (4*128*36 + 4*32*33) * (int)sizeof(float);
    cudaFuncSetAttribute(k_dec_persist,
                         cudaFuncAttributeMaxDynamicSharedMemorySize, dec_smem);
    k_dec_persist<<<NBLK, 256, dec_smem>>>(dec_Wih, dec_Whh, ak_W, ak_b,
                                           out_W, out_b, src_len);

    // ---- final logits ----
    k_sgemm<<<dim3(NV/64, (NT*NB + 127)/128), 256>>>(NT*NB, NV, ND,
        d_feat, ND, embed, ND, wd_b, nullptr, out, NV, 0, 1);

    (void)in_sizes; (void)n_in; (void)out_size;
}

// round 7
// speedup vs baseline: 1.6770x; 1.2017x over previous
#include <cuda_runtime.h>
#include <math.h>
#include <stdint.h>

// Problem dims (fixed by the dataset)
#define NB 32      // batch
#define NS 128     // src seq len
#define NT 19      // decoder steps (T-1)
#define ND 512     // embed dim
#define NH 1024    // hidden
#define NG 4096    // 4*H
#define NK 100     // attn key dim
#define NV 32000   // vocab
#define NBLK 128

typedef unsigned long long ull_t;

// ------------------------- scratch (device globals; no allocs) ---------------
__device__ float g_src_embed[NS*NB*ND];
__device__ float g_ans_embed[NT*NB*ND];
__device__ float g_xproj[NS*NG*NB];         // [s][n][b]
__device__ float g_dxe[NT*NG*NB];           // [t][n][b]
__device__ float g_h[NB*NH];
__device__ float g_c[NB*NH];
__device__ float g_hbuf[2*NB*NH];
__device__ float g_enc_out[NS*NB*NH];
__device__ float g_qkey[NS*NB*NK];
__device__ float g_qval[NS*NB*NH];
__device__ float g_tmp[NB*2048];
__device__ float g_ctx[NB*NH];
__device__ float g_attw[NB*NS];
__device__ float g_feat[NT*NB*ND];

__device__ unsigned g_barcnt = 0;
__device__ unsigned g_bargen = 0;

__device__ __forceinline__ float sigmf_(float x) { return 1.0f/(1.0f+expf(-x)); }

// ---- packed f32x2 helpers (Blackwell FFMA2 path, recurrent kernels) ----
__device__ __forceinline__ void ffma2(ull_t& d, ull_t a, ull_t b)
{
    asm("fma.rn.f32x2 %0, %1, %2, %3;" : "=l"(d) : "l"(a), "l"(b), "l"(d));
}
__device__ __forceinline__ ull_t dup2(float x)
{
    ull_t r;
    asm("mov.b64 %0, {%1, %1};" : "=l"(r) : "f"(x));
    return r;
}
__device__ __forceinline__ float2 unpk(ull_t v)
{
    float2 r;
    asm("mov.b64 {%0, %1}, %2;" : "=f"(r.x), "=f"(r.y) : "l"(v));
    return r;
}

// ---- tf32 tensor-core helpers ----
__device__ __forceinline__ uint32_t f2tf(float x)
{
    uint32_t r;
    asm("cvt.rna.tf32.f32 %0, %1;" : "=r"(r) : "f"(x));
    return r;
}
__device__ __forceinline__ uint32_t cvta_s(const void* p)
{
    uint32_t a;
    asm("{ .reg .u64 t; cvta.to.shared.u64 t, %1; cvt.u32.u64 %0, t; }"
        : "=r"(a) : "l"(p));
    return a;
}
__device__ __forceinline__ void ldsm_x4(uint32_t& r0, uint32_t& r1,
                                        uint32_t& r2, uint32_t& r3, uint32_t addr)
{
    asm volatile("ldmatrix.sync.aligned.m8n8.x4.b16 {%0,%1,%2,%3}, [%4];"
                 : "=r"(r0), "=r"(r1), "=r"(r2), "=r"(r3) : "r"(addr));
}
__device__ __forceinline__ void mma_tf32(float* d, uint32_t a0, uint32_t a1,
                                         uint32_t a2, uint32_t a3,
                                         uint32_t b0, uint32_t b1)
{
    asm volatile(
        "mma.sync.aligned.m16n8k8.row.col.f32.tf32.tf32.f32 "
        "{%0,%1,%2,%3}, {%4,%5,%6,%7}, {%8,%9}, {%0,%1,%2,%3};"
        : "+f"(d[0]), "+f"(d[1]), "+f"(d[2]), "+f"(d[3])
        : "r"(a0), "r"(a1), "r"(a2), "r"(a3), "r"(b0), "r"(b1));
}

__device__ __forceinline__ void gridbar()
{
    __syncthreads();
    if (threadIdx.x == 0) {
        __threadfence();
        volatile unsigned* vgen = &g_bargen;
        unsigned gen = *vgen;
        if (atomicAdd(&g_barcnt, 1u) == NBLK - 1) {
            g_barcnt = 0;
            __threadfence();
            atomicAdd(&g_bargen, 1u);
        } else {
            while (*vgen == gen) { __nanosleep(16); }
        }
        __threadfence();
    }
    __syncthreads();
}

// helper: scatter 4 prefetched float4s (rows kk=4*(lq+8p)) into tile[k][row]
__device__ __forceinline__ void stash4(float* buf, int lq, int row,
                                       float4 p0, float4 p1, float4 p2, float4 p3)
{
    buf[(4*lq+0)*36+row]=p0.x; buf[(4*lq+1)*36+row]=p0.y;
    buf[(4*lq+2)*36+row]=p0.z; buf[(4*lq+3)*36+row]=p0.w;
    buf[(4*(lq+8)+0)*36+row]=p1.x; buf[(4*(lq+8)+1)*36+row]=p1.y;
    buf[(4*(lq+8)+2)*36+row]=p1.z; buf[(4*(lq+8)+3)*36+row]=p1.w;
    buf[(4*(lq+16)+0)*36+row]=p2.x; buf[(4*(lq+16)+1)*36+row]=p2.y;
    buf[(4*(lq+16)+2)*36+row]=p2.z; buf[(4*(lq+16)+3)*36+row]=p2.w;
    buf[(4*(lq+24)+0)*36+row]=p3.x; buf[(4*(lq+24)+1)*36+row]=p3.y;
    buf[(4*(lq+24)+2)*36+row]=p3.z; buf[(4*(lq+24)+3)*36+row]=p3.w;
}

// ------------------------- embedding gather ---------------------------------
__global__ void k_gather(const int* __restrict__ seq, int seq_stride,
                         const float* __restrict__ embed, float* __restrict__ out)
{
    int row = blockIdx.x;
    int st  = row / NB;
    int b   = row % NB;
    int tok = seq[b*seq_stride + st];
    const float4* src = (const float4*)(embed + (size_t)tok*ND);
    float4*       dst = (float4*)(out + (size_t)row*ND);
    dst[threadIdx.x] = src[threadIdx.x];
}

// ------------------------- tf32 tensor-core GEMM ----------------------------
// C = act(A@W^T + b1 [+b2]).  BM=128 BN=64 BK=16, 8 warps (4m x 2n),
// warp tile 32x32 via mma.m16n8k8.tf32.  ldmatrix for A frags.
// out_map==1 remaps row m=(t*32+b) -> (b*NT+t)  (final logits)
// out_map==2 writes C[((m>>5)*NG + n)*32 + (m&31)]  (xproj/dxe transposed)
__global__ __launch_bounds__(256)
void k_sgemm(int M, int N, int K,
             const float* __restrict__ A, int lda,
             const float* __restrict__ W, int ldw,
             const float* __restrict__ bias1, const float* __restrict__ bias2,
             float* __restrict__ C, int ldc, int act, int out_map)
{
    __shared__ __align__(16) uint32_t smem_u[8704];   // 34816 B
    uint32_t* As = smem_u;              // [128][20] tf32  (2560 u32)
    uint32_t* Ws = smem_u + 2560;       // [64][20]  tf32  (1280 u32)
    float*    Cs = (float*)smem_u;      // [128][68] reuse after mainloop

    int tid  = threadIdx.x;
    int lane = tid & 31;
    int warp = tid >> 5;
    int wm   = warp & 3;                // m warp 0..3 (x32 rows)
    int wn   = warp >> 2;               // n warp 0..1 (x32 cols)
    int m0 = blockIdx.y*128, n0 = blockIdx.x*64;

    // loader indices
    int ra = tid >> 2;                  // 0..63
    int kc = (tid & 3) * 4;

    // ldmatrix source addresses (per k-half added later)
    uint32_t as_base = cvta_s(As);
    uint32_t ws_off  = (uint32_t)(wn*32 + (lane >> 2))*20 + (lane & 3);

    float acc[2][4][4] = {};

    for (int k0 = 0; k0 < K; k0 += 16) {
        float4 a0 = make_float4(0.f,0.f,0.f,0.f);
        float4 a1 = make_float4(0.f,0.f,0.f,0.f);
        float4 w4 = make_float4(0.f,0.f,0.f,0.f);
        if (m0 + ra < M)      a0 = *(const float4*)(A + (size_t)(m0+ra)*lda + k0 + kc);
        if (m0 + ra + 64 < M) a1 = *(const float4*)(A + (size_t)(m0+ra+64)*lda + k0 + kc);
        if (n0 + ra < N && ra < 64) w4 = *(const float4*)(W + (size_t)(n0+ra)*ldw + k0 + kc);
        __syncthreads();
        {
            uint4 u0 = make_uint4(f2tf(a0.x), f2tf(a0.y), f2tf(a0.z), f2tf(a0.w));
            uint4 u1 = make_uint4(f2tf(a1.x), f2tf(a1.y), f2tf(a1.z), f2tf(a1.w));
            *(uint4*)&As[ra*20 + kc]        = u0;
            *(uint4*)&As[(ra+64)*20 + kc]   = u1;
            if (ra < 64) {
                uint4 uw = make_uint4(f2tf(w4.x), f2tf(w4.y), f2tf(w4.z), f2tf(w4.w));
                *(uint4*)&Ws[ra*20 + kc] = uw;
            }
        }
        __syncthreads();

        #pragma unroll
        for (int ks = 0; ks < 16; ks += 8) {
            uint32_t afr[2][4];
            #pragma unroll
            for (int mi = 0; mi < 2; mi++) {
                uint32_t row = (uint32_t)(wm*32 + mi*16 + (lane & 15));
                uint32_t kof = (uint32_t)(ks + ((lane >> 4) << 2));
                uint32_t addr = as_base + (row*20 + kof)*4;
                ldsm_x4(afr[mi][0], afr[mi][1], afr[mi][2], afr[mi][3], addr);
            }
            uint32_t bfr[4][2];
            #pragma unroll
            for (int j = 0; j < 4; j++) {
                bfr[j][0] = Ws[ws_off + (uint32_t)(j*8)*20 + ks];
                bfr[j][1] = Ws[ws_off + (uint32_t)(j*8)*20 + ks + 4];
            }
            #pragma unroll
            for (int mi = 0; mi < 2; mi++)
                #pragma unroll
                for (int j = 0; j < 4; j++)
                    mma_tf32(acc[mi][j], afr[mi][0], afr[mi][1], afr[mi][2],
                             afr[mi][3], bfr[j][0], bfr[j][1]);
        }
    }
    __syncthreads();   // done reading As/Ws; Cs overwrites them

    // stage C with bias + activation: Cs[m][n], stride 68
    #pragma unroll
    for (int mi = 0; mi < 2; mi++) {
        int ml0 = wm*32 + mi*16 + (lane >> 2);
        #pragma unroll
        for (int j = 0; j < 4; j++) {
            int nl = wn*32 + j*8 + (lane & 3)*2;
            float b0v = 0.f, b1v = 0.f;
            if (n0 + nl < N) {
                b0v = bias1[n0+nl];
                if (bias2) b0v += bias2[n0+nl];
            }
            if (n0 + nl + 1 < N) {
                b1v = bias1[n0+nl+1];
                if (bias2) b1v += bias2[n0+nl+1];
            }
            float v0 = acc[mi][j][0] + b0v;
            float v1 = acc[mi][j][1] + b1v;
            float v2 = acc[mi][j][2] + b0v;
            float v3 = acc[mi][j][3] + b1v;
            if (act == 1) { v0=tanhf(v0); v1=tanhf(v1); v2=tanhf(v2); v3=tanhf(v3); }
            else if (act == 2) { v0=fmaxf(v0,0.f); v1=fmaxf(v1,0.f);
                                 v2=fmaxf(v2,0.f); v3=fmaxf(v3,0.f); }
            Cs[ml0*68 + nl]       = v0;
            Cs[ml0*68 + nl + 1]   = v1;
            Cs[(ml0+8)*68 + nl]   = v2;
            Cs[(ml0+8)*68 + nl+1] = v3;
        }
    }
    __syncthreads();

    if (out_map == 2) {
        for (int c = tid; c < 2048; c += 256) {
            int qb = (c & 7) * 4;
            int nl = (c >> 3) & 63;
            int sh = c >> 9;
            int mgrp = m0 + sh*32;
            if (mgrp >= M) continue;
            float4 v4 = make_float4(Cs[(sh*32+qb+0)*68 + nl],
                                    Cs[(sh*32+qb+1)*68 + nl],
                                    Cs[(sh*32+qb+2)*68 + nl],
                                    Cs[(sh*32+qb+3)*68 + nl]);
            *(float4*)&C[((size_t)(mgrp >> 5)*NG + n0 + nl)*32 + qb] = v4;
        }
        return;
    }

    for (int c = tid; c < 2048; c += 256) {
        int ml = c >> 4;
        int nl = (c & 15) * 4;
        int m = m0 + ml;
        if (m >= M) continue;
        size_t row = (out_map == 1) ? (size_t)((m & 31)*NT + (m >> 5)) : (size_t)m;
        int n = n0 + nl;
        if (n + 3 < N) {
            *(float4*)&C[row*ldc + n] = *(const float4*)&Cs[ml*68 + nl];
        } else {
            for (int j = 0; j < 4; j++)
                if (n + j < N) C[row*ldc + n + j] = Cs[ml*68 + nl + j];
        }
    }
}

// ------------------------- persistent encoder -------------------------------
__global__ void __launch_bounds__(256, 1)
k_enc_persist(const float* __restrict__ Whh, const int* __restrict__ lengths)
{
    extern __shared__ float sm[];
    float* sWt = sm;                          // [1024][36]
    float* sHs = sm + 1024*36;                // 2 x [128][36]
    float* sZs = sm + 1024*36 + 2*128*36;     // [4][32][33]

    int tid = threadIdx.x;
    int u0  = blockIdx.x * 8;

    for (int r = 0; r < 32; r++) {
        int n = (r >> 3)*NH + u0 + (r & 7);
        float4 w4 = *(const float4*)&Whh[(size_t)n*NH + 4*tid];
        sWt[(4*tid+0)*36 + r] = w4.x;
        sWt[(4*tid+1)*36 + r] = w4.y;
        sWt[(4*tid+2)*36 + r] = w4.z;
        sWt[(4*tid+3)*36 + r] = w4.w;
    }

    int cb = tid & 31;
    int cu = tid >> 5;
    int mylen = lengths[cb];
    int wq = tid >> 5;
    int qlen = 0;
    #pragma unroll
    for (int i = 0; i < 4; i++) qlen = max(qlen, lengths[4*wq + i]);
    float creg = 0.0f, hreg = 0.0f;

    g_hbuf[cb*NH + u0 + cu] = 0.0f;

    int rq = tid & 7;
    int bq = tid >> 5;
    int ks = (tid >> 3) & 3;
    int lb = tid >> 3;
    int lq = tid & 7;

    gridbar();

    for (int s = 0; s < NS; s++) {
        const float* hin  = g_hbuf + (s & 1)*(NB*NH);
        float*       hout = g_hbuf + ((s & 1) ^ 1)*(NB*NH);
        bool active = (s < qlen);

        const float* xp = g_xproj + ((size_t)s*NG + u0 + cu)*32 + cb;
        float xg0 = __ldg(&xp[0]);
        float xg1 = __ldg(&xp[(size_t)NH*32]);
        float xg2 = __ldg(&xp[(size_t)2*NH*32]);
        float xg3 = __ldg(&xp[(size_t)3*NH*32]);

        float4 p0, p1, p2, p3;
        if (active) {
            const float* hr = hin + lb*NH;
            p0 = __ldcg((const float4*)&hr[4*lq]);
            p1 = __ldcg((const float4*)&hr[4*(lq+8)]);
            p2 = __ldcg((const float4*)&hr[4*(lq+16)]);
            p3 = __ldcg((const float4*)&hr[4*(lq+24)]);
            stash4(sHs, lq, lb, p0, p1, p2, p3);
        }
        __syncthreads();

        ull_t acc2[4][2] = {};
        for (int ci = 0; ci < 8; ci++) {
            float* cur = sHs + (ci & 1)*(128*36);
            if (ci < 7 && active) {
                const float* hr = hin + lb*NH + (ci+1)*128;
                p0 = __ldcg((const float4*)&hr[4*lq]);
                p1 = __ldcg((const float4*)&hr[4*(lq+8)]);
                p2 = __ldcg((const float4*)&hr[4*(lq+16)]);
                p3 = __ldcg((const float4*)&hr[4*(lq+24)]);
            }
            if (active) {
                int kc = ci*128;
                for (int kb = 0; kb < 128; kb += 16) {
                    int k = kb + 4*ks;
                    #pragma unroll
                    for (int kk2 = 0; kk2 < 4; kk2++) {
                        float4 wv = *(const float4*)&sWt[(kc+k+kk2)*36 + 4*rq];
                        ulonglong2 hq = *(const ulonglong2*)&cur[(k+kk2)*36 + 4*bq];
                        ull_t d0 = dup2(wv.x), d1 = dup2(wv.y);
                        ull_t d2 = dup2(wv.z), d3 = dup2(wv.w);
                        ffma2(acc2[0][0], d0, hq.x); ffma2(acc2[0][1], d0, hq.y);
                        ffma2(acc2[1][0], d1, hq.x); ffma2(acc2[1][1], d1, hq.y);
                        ffma2(acc2[2][0], d2, hq.x); ffma2(acc2[2][1], d2, hq.y);
                        ffma2(acc2[3][0], d3, hq.x); ffma2(acc2[3][1], d3, hq.y);
                    }
                }
            }
            if (ci < 7 && active)
                stash4(sHs + ((ci & 1) ^ 1)*(128*36), lq, lb, p0, p1, p2, p3);
            __syncthreads();
        }

        #pragma unroll
        for (int i = 0; i < 4; i++) {
            float2 t0 = unpk(acc2[i][0]);
            float2 t1 = unpk(acc2[i][1]);
            float* zr = &sZs[(ks*32 + 4*rq + i)*33 + 4*bq];
            zr[0] = t0.x; zr[1] = t0.y; zr[2] = t1.x; zr[3] = t1.y;
        }
        __syncthreads();

        float zg4[4] = {xg0, xg1, xg2, xg3};
        #pragma unroll
        for (int g = 0; g < 4; g++)
            #pragma unroll
            for (int q = 0; q < 4; q++) zg4[g] += sZs[(q*32 + g*8 + cu)*33 + cb];
        float cn = sigmf_(zg4[1])*creg + sigmf_(zg4[0])*tanhf(zg4[2]);
        float hn = sigmf_(zg4[3])*tanhf(cn);
        bool msk = (s < mylen);
        creg = msk ? cn : creg;
        hreg = msk ? hn : hreg;
        hout[cb*NH + u0 + cu] = hreg;
        g_enc_out[((size_t)(s*NB + cb))*NH + u0 + cu] = msk ? hreg : 0.0f;

        gridbar();
    }

    g_h[cb*NH + u0 + cu] = hreg;
    g_c[cb*NH + u0 + cu] = creg;
}

// ------------------------- persistent decoder helpers -----------------------
__device__ __forceinline__ void dec_feat(int tt, const float* __restrict__ hsrc,
    const float* __restrict__ out_W, const float* __restrict__ out_b,
    float* sH, float* sZ, int fn0)
{
    int tid = threadIdx.x;
    int r   = tid >> 6;
    int fks = (tid >> 5) & 1;
    int fb  = tid & 31;
    int lb  = tid >> 3;
    int lq  = tid & 7;
    const float* wrow = out_W + (size_t)(fn0 + r)*(2*NH);
    float fa = 0.f;

    float4 p0, p1, p2, p3;
    {
        const float* hr = hsrc + lb*NH;
        p0 = __ldcg((const float4*)&hr[4*lq]);
        p1 = __ldcg((const float4*)&hr[4*(lq+8)]);
        p2 = __ldcg((const float4*)&hr[4*(lq+16)]);
        p3 = __ldcg((const float4*)&hr[4*(lq+24)]);
        stash4(sH, lq, lb, p0, p1, p2, p3);
    }
    __syncthreads();

    for (int ch = 0; ch < 16; ch++) {
        float* cur = sH + (ch & 1)*(128*36);
        if (ch < 15) {
            int cn_ = ch + 1;
            const float* src = (cn_ < 8) ? hsrc : g_ctx;
            const float* hr = src + lb*NH + (cn_ & 7)*128;
            p0 = __ldcg((const float4*)&hr[4*lq]);
            p1 = __ldcg((const float4*)&hr[4*(lq+8)]);
            p2 = __ldcg((const float4*)&hr[4*(lq+16)]);
            p3 = __ldcg((const float4*)&hr[4*(lq+24)]);
        }
        const float* wc = wrow + ch*128 + fks*64;
        const float* hc = cur + fks*64*36 + fb;
        #pragma unroll 16
        for (int k = 0; k < 64; k++)
            fa += __ldg(&wc[k]) * hc[k*36];
        if (ch < 15)
            stash4(sH + ((ch & 1) ^ 1)*(128*36), lq, lb, p0, p1, p2, p3);
        __syncthreads();
    }
    sZ[(r*2 + fks)*33 + fb] = fa;
    __syncthreads();
    if (tid < 128) {
        int rr = tid >> 5, bb = tid & 31;
        float v = sZ[(rr*2)*33 + bb] + sZ[(rr*2+1)*33 + bb] + __ldg(&out_b[fn0 + rr]);
        g_feat[((size_t)(tt*NB + bb))*ND + fn0 + rr] = v;
    }
    __syncthreads();
}

__device__ __forceinline__ void dec_attn(int b, int mylen,
    const float* __restrict__ hcur,
    const float* __restrict__ ak_W, const float* __restrict__ ak_b,
    float* sW)
{
    int tid = threadIdx.x;
    float* sh_ = sW;
    float* sak = sW + 1024;
    float* se  = sW + 1152;
    float* sr  = sW + 1280;

    for (int i = tid; i < NH; i += 256) sh_[i] = __ldcg(&hcur[b*NH + i]);
    __syncthreads();

    if (tid < NK) {
        const float* wr = ak_W + (size_t)tid*NH;
        float acc0 = 0.f, acc1 = 0.f;
        for (int k = 0; k < NH; k += 8) {
            float4 w0 = *(const float4*)&wr[k];
            float4 w1 = *(const float4*)&wr[k+4];
            float4 h0 = *(const float4*)&sh_[k];
            float4 h1 = *(const float4*)&sh_[k+4];
            acc0 += w0.x*h0.x + w0.y*h0.y + w0.z*h0.z + w0.w*h0.w;
            acc1 += w1.x*h1.x + w1.y*h1.y + w1.z*h1.z + w1.w*h1.w;
        }
        sak[tid] = tanhf(acc0 + acc1 + ak_b[tid]);
    }
    __syncthreads();

    if (tid < NS) {
        const float* qr = g_qkey + ((size_t)(tid*NB + b))*NK;
        float acc = 0.f;
        for (int k = 0; k < NK; k++) acc += qr[k]*sak[k];
        se[tid] = (tid < mylen) ? acc : -INFINITY;
    }
    __syncthreads();

    sr[tid] = (tid < NS) ? se[tid] : -INFINITY;
    __syncthreads();
    for (int off = 128; off >= 1; off >>= 1) {
        if (tid < off) sr[tid] = fmaxf(sr[tid], sr[tid+off]);
        __syncthreads();
    }
    float mx = sr[0];
    __syncthreads();

    float ex = (tid < NS) ? expf(se[tid] - mx) : 0.0f;
    sr[tid] = ex;
    __syncthreads();
    for (int off = 128; off >= 1; off >>= 1) {
        if (tid < off) sr[tid] += sr[tid+off];
        __syncthreads();
    }
    float inv = 1.0f / sr[0];
    __syncthreads();
    if (tid < NS) g_attw[b*NS + tid] = ex * inv;
    __syncthreads();
}

// ------------------------- persistent decoder -------------------------------
__global__ void __launch_bounds__(256, 1)
k_dec_persist(const float* __restrict__ dec_Wih, const float* __restrict__ dec_Whh,
              const float* __restrict__ ak_W,   const float* __restrict__ ak_b,
              const float* __restrict__ out_W,  const float* __restrict__ out_b,
              const int* __restrict__ lengths)
{
    extern __shared__ float sm[];
    float* sW = sm;                     // 2 x [128][36]
    float* sH = sm + 2*128*36;          // 2 x [128][36]
    float* sZ = sm + 4*128*36;          // [4][32][33]

    int tid = threadIdx.x;
    int blk = blockIdx.x;
    int u0  = blk * 8;
    int fn0 = blk * 4;

    int cb = tid & 31, cu = tid >> 5;
    float creg = g_c[cb*NH + u0 + cu];

    int rq = tid & 7;
    int bq = (tid >> 3) & 7;
    int ks = tid >> 6;
    int lb = tid >> 3;
    int lq = tid & 7;
    int wr_ = tid >> 3;
    int wn_ = (wr_ >> 3)*NH + u0 + (wr_ & 7);

    int mylen = (blk < 32) ? lengths[blk] : 0;

    for (int t = 0; t < NT; t++) {
        const float* hcur = (t == 0) ? g_h : (g_hbuf + ((t-1) & 1)*(NB*NH));
        float*       hnew = g_hbuf + (t & 1)*(NB*NH);

        if (t > 0)
            dec_feat(t-1, hcur, out_W, out_b, sH, sZ, fn0);
        if (blk < 32)
            dec_attn(blk, mylen, hcur, ak_W, ak_b, sW);
        gridbar();

        // ---- context ----
        {
            int b  = blk & 31;
            int hq = blk >> 5;
            if (tid < NS) sZ[tid] = __ldcg(&g_attw[b*NS + tid]);
            __syncthreads();
            int hh = hq*256 + tid;
            float a0 = 0.f, a1 = 0.f, a2 = 0.f, a3 = 0.f;
            #pragma unroll 4
            for (int s = 0; s < NS; s += 4) {
                a0 += sZ[s+0]*__ldg(&g_qval[((size_t)((s+0)*NB + b))*NH + hh]);
                a1 += sZ[s+1]*__ldg(&g_qval[((size_t)((s+1)*NB + b))*NH + hh]);
                a2 += sZ[s+2]*__ldg(&g_qval[((size_t)((s+2)*NB + b))*NH + hh]);
                a3 += sZ[s+3]*__ldg(&g_qval[((size_t)((s+3)*NB + b))*NH + hh]);
            }
            g_ctx[b*NH + hh] = (a0 + a1) + (a2 + a3);
            __syncthreads();
        }
        gridbar();

        const float* xp = g_dxe + ((size_t)t*NG + u0 + cu)*32 + cb;
        float xg0 = __ldg(&xp[0]);
        float xg1 = __ldg(&xp[(size_t)NH*32]);
        float xg2 = __ldg(&xp[(size_t)2*NH*32]);
        float xg3 = __ldg(&xp[(size_t)3*NH*32]);

        // ---- z GEMM, double-buffered W and H, f32x2 core ----
        ull_t acc2[4][2] = {};
        float4 pH0, pH1, pH2, pH3, pW0, pW1, pW2, pW3;
        {
            const float* hr = hcur + lb*NH;
            pH0 = __ldcg((const float4*)&hr[4*lq]);
            pH1 = __ldcg((const float4*)&hr[4*(lq+8)]);
            pH2 = __ldcg((const float4*)&hr[4*(lq+16)]);
            pH3 = __ldcg((const float4*)&hr[4*(lq+24)]);
            const float* wrow = dec_Whh + (size_t)wn_*NH;
            pW0 = __ldg((const float4*)&wrow[4*lq]);
            pW1 = __ldg((const float4*)&wrow[4*(lq+8)]);
            pW2 = __ldg((const float4*)&wrow[4*(lq+16)]);
            pW3 = __ldg((const float4*)&wrow[4*(lq+24)]);
            stash4(sH, lq, lb, pH0, pH1, pH2, pH3);
            stash4(sW, lq, wr_, pW0, pW1, pW2, pW3);
        }
        __syncthreads();

        for (int ch = 0; ch < 16; ch++) {
            float* curW = sW + (ch & 1)*(128*36);
            float* curH = sH + (ch & 1)*(128*36);
            if (ch < 15) {
                int cn_ = ch + 1;
                const float* asrc = (cn_ < 8) ? hcur : g_ctx;
                int kc = (cn_ & 7)*128;
                const float* hr = asrc + lb*NH + kc;
                pH0 = __ldcg((const float4*)&hr[4*lq]);
                pH1 = __ldcg((const float4*)&hr[4*(lq+8)]);
                pH2 = __ldcg((const float4*)&hr[4*(lq+16)]);
                pH3 = __ldcg((const float4*)&hr[4*(lq+24)]);
                const float* wrow = (cn_ < 8)
                    ? (dec_Whh + (size_t)wn_*NH + kc)
                    : (dec_Wih + (size_t)wn_*(ND+NH) + ND + kc);
                pW0 = __ldg((const float4*)&wrow[4*lq]);
                pW1 = __ldg((const float4*)&wrow[4*(lq+8)]);
                pW2 = __ldg((const float4*)&wrow[4*(lq+16)]);
                pW3 = __ldg((const float4*)&wrow[4*(lq+24)]);
            }
            for (int kb = 0; kb < 128; kb += 16) {
                int k = kb + 4*ks;
                #pragma unroll
                for (int kk2 = 0; kk2 < 4; kk2++) {
                    float4 wv = *(const float4*)&curW[(k+kk2)*36 + 4*rq];
                    ulonglong2 hq2 = *(const ulonglong2*)&curH[(k+kk2)*36 + 4*bq];
                    ull_t d0 = dup2(wv.x), d1 = dup2(wv.y);
                    ull_t d2 = dup2(wv.z), d3 = dup2(wv.w);
                    ffma2(acc2[0][0], d0, hq2.x); ffma2(acc2[0][1], d0, hq2.y);
                    ffma2(acc2[1][0], d1, hq2.x); ffma2(acc2[1][1], d1, hq2.y);
                    ffma2(acc2[2][0], d2, hq2.x); ffma2(acc2[2][1], d2, hq2.y);
                    ffma2(acc2[3][0], d3, hq2.x); ffma2(acc2[3][1], d3, hq2.y);
                }
            }
            if (ch < 15) {
                stash4(sH + ((ch & 1) ^ 1)*(128*36), lq, lb, pH0, pH1, pH2, pH3);
                stash4(sW + ((ch & 1) ^ 1)*(128*36), lq, wr_, pW0, pW1, pW2, pW3);
            }
            __syncthreads();
        }

        #pragma unroll
        for (int i = 0; i < 4; i++) {
            float2 t0 = unpk(acc2[i][0]);
            float2 t1 = unpk(acc2[i][1]);
            float* zr = &sZ[(ks*32 + 4*rq + i)*33 + 4*bq];
            zr[0] = t0.x; zr[1] = t0.y; zr[2] = t1.x; zr[3] = t1.y;
        }
        __syncthreads();

        {
            float zg4[4] = {xg0, xg1, xg2, xg3};
            #pragma unroll
            for (int g = 0; g < 4; g++)
                #pragma unroll
                for (int q = 0; q < 4; q++) zg4[g] += sZ[(q*32 + g*8 + cu)*33 + cb];
            float cn = sigmf_(zg4[1])*creg + sigmf_(zg4[0])*tanhf(zg4[2]);
            float hn = sigmf_(zg4[3])*tanhf(cn);
            creg = cn;
            hnew[cb*NH + u0 + cu] = hn;
        }
        __syncthreads();
        gridbar();
    }

    {
        const float* hlast = g_hbuf + ((NT-1) & 1)*(NB*NH);
        dec_feat(NT-1, hlast, out_W, out_b, sH, sZ, fn0);
    }
}

// =============================================================================
extern "C" void kernel_launch(void* const* d_in, const int* in_sizes, int n_in,
                              void* d_out, int out_size)
{
    const float* embed    = (const float*)d_in[0];
    const float* enc_Wih  = (const float*)d_in[1];
    const float* enc_Whh  = (const float*)d_in[2];
    const float* enc_bih  = (const float*)d_in[3];
    const float* enc_bhh  = (const float*)d_in[4];
    const float* dec_Wih  = (const float*)d_in[5];
    const float* dec_Whh  = (const float*)d_in[6];
    const float* dec_bih  = (const float*)d_in[7];
    const float* dec_bhh  = (const float*)d_in[8];
    const float* qk_W     = (const float*)d_in[9];
    const float* qk_b     = (const float*)d_in[10];
    const float* qv_W     = (const float*)d_in[11];
    const float* qv_b     = (const float*)d_in[12];
    const float* ak_W     = (const float*)d_in[13];
    const float* ak_b     = (const float*)d_in[14];
    const float* out_W    = (const float*)d_in[15];
    const float* out_b    = (const float*)d_in[16];
    const float* wd_b     = (const float*)d_in[17];
    const float* hfc1_W   = (const float*)d_in[18];
    const float* hfc1_b   = (const float*)d_in[19];
    const float* hfc2_W   = (const float*)d_in[20];
    const float* hfc2_b   = (const float*)d_in[21];
    const float* cfc1_W   = (const float*)d_in[22];
    const float* cfc1_b   = (const float*)d_in[23];
    const float* cfc2_W   = (const float*)d_in[24];
    const float* cfc2_b   = (const float*)d_in[25];
    const int*   src_seqs = (const int*)d_in[26];
    const int*   src_len  = (const int*)d_in[27];
    const int*   trg_seqs = (const int*)d_in[28];
    float* out = (float*)d_out;

    float *d_src_embed, *d_ans_embed, *d_xproj, *d_dxe, *d_h, *d_c;
    float *d_enc_out, *d_qkey, *d_qval, *d_tmp, *d_feat;
    cudaGetSymbolAddress((void**)&d_src_embed, g_src_embed);
    cudaGetSymbolAddress((void**)&d_ans_embed, g_ans_embed);
    cudaGetSymbolAddress((void**)&d_xproj,     g_xproj);
    cudaGetSymbolAddress((void**)&d_dxe,       g_dxe);
    cudaGetSymbolAddress((void**)&d_h,         g_h);
    cudaGetSymbolAddress((void**)&d_c,         g_c);
    cudaGetSymbolAddress((void**)&d_enc_out,   g_enc_out);
    cudaGetSymbolAddress((void**)&d_qkey,      g_qkey);
    cudaGetSymbolAddress((void**)&d_qval,      g_qval);
    cudaGetSymbolAddress((void**)&d_tmp,       g_tmp);
    cudaGetSymbolAddress((void**)&d_feat,      g_feat);

    // ---- precompute ----
    k_gather<<<NS*NB, 128>>>(src_seqs, NS, embed, d_src_embed);
    k_gather<<<NT*NB, 128>>>(trg_seqs, 20, embed, d_ans_embed);

    k_sgemm<<<dim3(NG/64, (NS*NB)/128), 256>>>(NS*NB, NG, ND,
        d_src_embed, ND, enc_Wih, ND, enc_bih, enc_bhh, d_xproj, NG, 0, 2);
    k_sgemm<<<dim3(NG/64, (NT*NB + 127)/128), 256>>>(NT*NB, NG, ND,
        d_ans_embed, ND, dec_Wih, ND + NH, dec_bih, dec_bhh, d_dxe, NG, 0, 2);

    // ---- encoder recurrence ----
    const int enc_smem = (1024*36 + 2*128*36 + 4*32*33) * (int)sizeof(float);
    cudaFuncSetAttribute(k_enc_persist,
                         cudaFuncAttributeMaxDynamicSharedMemorySize, enc_smem);
    k_enc_persist<<<NBLK, 256, enc_smem>>>(enc_Whh, src_len);

    // ---- bridge MLPs ----
    k_sgemm<<<dim3(2048/64, 1), 256>>>(NB, 2048, NH, d_h, NH, hfc1_W, NH,
                                       hfc1_b, nullptr, d_tmp, 2048, 2, 0);
    k_sgemm<<<dim3(NH/64, 1), 256>>>(NB, NH, 2048, d_tmp, 2048, hfc2_W, 2048,
                                     hfc2_b, nullptr, d_h, NH, 0, 0);
    k_sgemm<<<dim3(2048/64, 1), 256>>>(NB, 2048, NH, d_c, NH, cfc1_W, NH,
                                       cfc1_b, nullptr, d_tmp, 2048, 2, 0);
    k_sgemm<<<dim3(NH/64, 1), 256>>>(NB, NH, 2048, d_tmp, 2048, cfc2_W, 2048,
                                     cfc2_b, nullptr, d_c, NH, 0, 0);

    // ---- attention precompute ----
    k_sgemm<<<dim3((NK + 63)/64, (NS*NB)/128), 256>>>(NS*NB, NK, NH,
        d_enc_out, NH, qk_W, NH, qk_b, nullptr, d_qkey, NK, 1, 0);
    k_sgemm<<<dim3(NH/64, (NS*NB)/128), 256>>>(NS*NB, NH, NH,
        d_enc_out, NH, qv_W, NH, qv_b, nullptr, d_qval, NH, 0, 0);

    // ---- decoder recurrence ----
    const int dec_smem = (4*128*36 + 4*32*33) * (int)sizeof(float);
    cudaFuncSetAttribute(k_dec_persist,
                         cudaFuncAttributeMaxDynamicSharedMemorySize, dec_smem);
    k_dec_persist<<<NBLK, 256, dec_smem>>>(dec_Wih, dec_Whh, ak_W, ak_b,
                                           out_W, out_b, src_len);

    // ---- final logits ----
    k_sgemm<<<dim3(NV/64, (NT*NB + 127)/128), 256>>>(NT*NB, NV, ND,
        d_feat, ND, embed, ND, wd_b, nullptr, out, NV, 0, 1);

    (void)in_sizes; (void)n_in; (void)out_size;
}

// round 8
// speedup vs baseline: 1.8862x; 1.1248x over previous
#include <cuda_runtime.h>
#include <math.h>
#include <stdint.h>

// Problem dims (fixed by the dataset)
#define NB 32      // batch
#define NS 128     // src seq len
#define NT 19      // decoder steps (T-1)
#define ND 512     // embed dim
#define NH 1024    // hidden
#define NG 4096    // 4*H
#define NK 100     // attn key dim
#define NV 32000   // vocab
#define NBLK 128

typedef unsigned long long ull_t;

// ------------------------- scratch (device globals; no allocs) ---------------
__device__ float g_src_embed[NS*NB*ND];
__device__ float g_ans_embed[NT*NB*ND];
__device__ float g_xproj[NS*NG*NB];         // [s][n][b]
__device__ float g_dxe[NT*NG*NB];           // [t][n][b]
__device__ float g_h[NB*NH];
__device__ float g_c[NB*NH];
__device__ float g_hbuf[2*NB*NH];
__device__ float g_enc_out[NS*NB*NH];
__device__ float g_qkey[NS*NB*NK];
__device__ float g_qval[NS*NB*NH];
__device__ float g_tmp[NB*2048];
__device__ float g_ctx[NB*NH];
__device__ float g_attw[NB*NS];
__device__ float g_feat[NT*NB*ND];

__device__ unsigned g_barcnt = 0;
__device__ unsigned g_bargen = 0;

__device__ __forceinline__ float sigmf_(float x) { return 1.0f/(1.0f+expf(-x)); }

// ---- packed f32x2 helpers (decoder FFMA2 path) ----
__device__ __forceinline__ void ffma2(ull_t& d, ull_t a, ull_t b)
{
    asm("fma.rn.f32x2 %0, %1, %2, %3;" : "=l"(d) : "l"(a), "l"(b), "l"(d));
}
__device__ __forceinline__ ull_t dup2(float x)
{
    ull_t r;
    asm("mov.b64 %0, {%1, %1};" : "=l"(r) : "f"(x));
    return r;
}
__device__ __forceinline__ float2 unpk(ull_t v)
{
    float2 r;
    asm("mov.b64 {%0, %1}, %2;" : "=f"(r.x), "=f"(r.y) : "l"(v));
    return r;
}

// ---- tf32 tensor-core helpers ----
__device__ __forceinline__ uint32_t f2tf(float x)
{
    uint32_t r;
    asm("cvt.rna.tf32.f32 %0, %1;" : "=r"(r) : "f"(x));
    return r;
}
__device__ __forceinline__ uint32_t cvta_s(const void* p)
{
    uint32_t a;
    asm("{ .reg .u64 t; cvta.to.shared.u64 t, %1; cvt.u32.u64 %0, t; }"
        : "=r"(a) : "l"(p));
    return a;
}
__device__ __forceinline__ void ldsm_x4(uint32_t& r0, uint32_t& r1,
                                        uint32_t& r2, uint32_t& r3, uint32_t addr)
{
    asm volatile("ldmatrix.sync.aligned.m8n8.x4.b16 {%0,%1,%2,%3}, [%4];"
                 : "=r"(r0), "=r"(r1), "=r"(r2), "=r"(r3) : "r"(addr));
}
__device__ __forceinline__ void mma_tf32(float* d, uint32_t a0, uint32_t a1,
                                         uint32_t a2, uint32_t a3,
                                         uint32_t b0, uint32_t b1)
{
    asm volatile(
        "mma.sync.aligned.m16n8k8.row.col.f32.tf32.tf32.f32 "
        "{%0,%1,%2,%3}, {%4,%5,%6,%7}, {%8,%9}, {%0,%1,%2,%3};"
        : "+f"(d[0]), "+f"(d[1]), "+f"(d[2]), "+f"(d[3])
        : "r"(a0), "r"(a1), "r"(a2), "r"(a3), "r"(b0), "r"(b1));
}

__device__ __forceinline__ void gridbar()
{
    __syncthreads();
    if (threadIdx.x == 0) {
        __threadfence();
        volatile unsigned* vgen = &g_bargen;
        unsigned gen = *vgen;
        if (atomicAdd(&g_barcnt, 1u) == NBLK - 1) {
            g_barcnt = 0;
            __threadfence();
            atomicAdd(&g_bargen, 1u);
        } else {
            while (*vgen == gen) { __nanosleep(16); }
        }
        __threadfence();
    }
    __syncthreads();
}

// helper: scatter 4 prefetched float4s (rows kk=4*(lq+8p)) into tile[k][row]
__device__ __forceinline__ void stash4(float* buf, int lq, int row,
                                       float4 p0, float4 p1, float4 p2, float4 p3)
{
    buf[(4*lq+0)*36+row]=p0.x; buf[(4*lq+1)*36+row]=p0.y;
    buf[(4*lq+2)*36+row]=p0.z; buf[(4*lq+3)*36+row]=p0.w;
    buf[(4*(lq+8)+0)*36+row]=p1.x; buf[(4*(lq+8)+1)*36+row]=p1.y;
    buf[(4*(lq+8)+2)*36+row]=p1.z; buf[(4*(lq+8)+3)*36+row]=p1.w;
    buf[(4*(lq+16)+0)*36+row]=p2.x; buf[(4*(lq+16)+1)*36+row]=p2.y;
    buf[(4*(lq+16)+2)*36+row]=p2.z; buf[(4*(lq+16)+3)*36+row]=p2.w;
    buf[(4*(lq+24)+0)*36+row]=p3.x; buf[(4*(lq+24)+1)*36+row]=p3.y;
    buf[(4*(lq+24)+2)*36+row]=p3.z; buf[(4*(lq+24)+3)*36+row]=p3.w;
}

// ------------------------- embedding gather ---------------------------------
__global__ void k_gather(const int* __restrict__ seq, int seq_stride,
                         const float* __restrict__ embed, float* __restrict__ out)
{
    int row = blockIdx.x;
    int st  = row / NB;
    int b   = row % NB;
    int tok = seq[b*seq_stride + st];
    const float4* src = (const float4*)(embed + (size_t)tok*ND);
    float4*       dst = (float4*)(out + (size_t)row*ND);
    dst[threadIdx.x] = src[threadIdx.x];
}

// ------------------------- tf32 tensor-core GEMM ----------------------------
__global__ __launch_bounds__(256)
void k_sgemm(int M, int N, int K,
             const float* __restrict__ A, int lda,
             const float* __restrict__ W, int ldw,
             const float* __restrict__ bias1, const float* __restrict__ bias2,
             float* __restrict__ C, int ldc, int act, int out_map)
{
    __shared__ __align__(16) uint32_t smem_u[8704];   // 34816 B
    uint32_t* As = smem_u;              // [128][20] tf32
    uint32_t* Ws = smem_u + 2560;       // [64][20]  tf32
    float*    Cs = (float*)smem_u;      // [128][68] reuse after mainloop

    int tid  = threadIdx.x;
    int lane = tid & 31;
    int warp = tid >> 5;
    int wm   = warp & 3;
    int wn   = warp >> 2;
    int m0 = blockIdx.y*128, n0 = blockIdx.x*64;

    int ra = tid >> 2;
    int kc = (tid & 3) * 4;

    uint32_t as_base = cvta_s(As);
    uint32_t ws_off  = (uint32_t)(wn*32 + (lane >> 2))*20 + (lane & 3);

    float acc[2][4][4] = {};

    for (int k0 = 0; k0 < K; k0 += 16) {
        float4 a0 = make_float4(0.f,0.f,0.f,0.f);
        float4 a1 = make_float4(0.f,0.f,0.f,0.f);
        float4 w4 = make_float4(0.f,0.f,0.f,0.f);
        if (m0 + ra < M)      a0 = *(const float4*)(A + (size_t)(m0+ra)*lda + k0 + kc);
        if (m0 + ra + 64 < M) a1 = *(const float4*)(A + (size_t)(m0+ra+64)*lda + k0 + kc);
        if (n0 + ra < N && ra < 64) w4 = *(const float4*)(W + (size_t)(n0+ra)*ldw + k0 + kc);
        __syncthreads();
        {
            uint4 u0 = make_uint4(f2tf(a0.x), f2tf(a0.y), f2tf(a0.z), f2tf(a0.w));
            uint4 u1 = make_uint4(f2tf(a1.x), f2tf(a1.y), f2tf(a1.z), f2tf(a1.w));
            *(uint4*)&As[ra*20 + kc]        = u0;
            *(uint4*)&As[(ra+64)*20 + kc]   = u1;
            if (ra < 64) {
                uint4 uw = make_uint4(f2tf(w4.x), f2tf(w4.y), f2tf(w4.z), f2tf(w4.w));
                *(uint4*)&Ws[ra*20 + kc] = uw;
            }
        }
        __syncthreads();

        #pragma unroll
        for (int ks = 0; ks < 16; ks += 8) {
            uint32_t afr[2][4];
            #pragma unroll
            for (int mi = 0; mi < 2; mi++) {
                uint32_t row = (uint32_t)(wm*32 + mi*16 + (lane & 15));
                uint32_t kof = (uint32_t)(ks + ((lane >> 4) << 2));
                uint32_t addr = as_base + (row*20 + kof)*4;
                ldsm_x4(afr[mi][0], afr[mi][1], afr[mi][2], afr[mi][3], addr);
            }
            uint32_t bfr[4][2];
            #pragma unroll
            for (int j = 0; j < 4; j++) {
                bfr[j][0] = Ws[ws_off + (uint32_t)(j*8)*20 + ks];
                bfr[j][1] = Ws[ws_off + (uint32_t)(j*8)*20 + ks + 4];
            }
            #pragma unroll
            for (int mi = 0; mi < 2; mi++)
                #pragma unroll
                for (int j = 0; j < 4; j++)
                    mma_tf32(acc[mi][j], afr[mi][0], afr[mi][1], afr[mi][2],
                             afr[mi][3], bfr[j][0], bfr[j][1]);
        }
    }
    __syncthreads();

    #pragma unroll
    for (int mi = 0; mi < 2; mi++) {
        int ml0 = wm*32 + mi*16 + (lane >> 2);
        #pragma unroll
        for (int j = 0; j < 4; j++) {
            int nl = wn*32 + j*8 + (lane & 3)*2;
            float b0v = 0.f, b1v = 0.f;
            if (n0 + nl < N) {
                b0v = bias1[n0+nl];
                if (bias2) b0v += bias2[n0+nl];
            }
            if (n0 + nl + 1 < N) {
                b1v = bias1[n0+nl+1];
                if (bias2) b1v += bias2[n0+nl+1];
            }
            float v0 = acc[mi][j][0] + b0v;
            float v1 = acc[mi][j][1] + b1v;
            float v2 = acc[mi][j][2] + b0v;
            float v3 = acc[mi][j][3] + b1v;
            if (act == 1) { v0=tanhf(v0); v1=tanhf(v1); v2=tanhf(v2); v3=tanhf(v3); }
            else if (act == 2) { v0=fmaxf(v0,0.f); v1=fmaxf(v1,0.f);
                                 v2=fmaxf(v2,0.f); v3=fmaxf(v3,0.f); }
            Cs[ml0*68 + nl]       = v0;
            Cs[ml0*68 + nl + 1]   = v1;
            Cs[(ml0+8)*68 + nl]   = v2;
            Cs[(ml0+8)*68 + nl+1] = v3;
        }
    }
    __syncthreads();

    if (out_map == 2) {
        for (int c = tid; c < 2048; c += 256) {
            int qb = (c & 7) * 4;
            int nl = (c >> 3) & 63;
            int sh = c >> 9;
            int mgrp = m0 + sh*32;
            if (mgrp >= M) continue;
            float4 v4 = make_float4(Cs[(sh*32+qb+0)*68 + nl],
                                    Cs[(sh*32+qb+1)*68 + nl],
                                    Cs[(sh*32+qb+2)*68 + nl],
                                    Cs[(sh*32+qb+3)*68 + nl]);
            *(float4*)&C[((size_t)(mgrp >> 5)*NG + n0 + nl)*32 + qb] = v4;
        }
        return;
    }

    for (int c = tid; c < 2048; c += 256) {
        int ml = c >> 4;
        int nl = (c & 15) * 4;
        int m = m0 + ml;
        if (m >= M) continue;
        size_t row = (out_map == 1) ? (size_t)((m & 31)*NT + (m >> 5)) : (size_t)m;
        int n = n0 + nl;
        if (n + 3 < N) {
            *(float4*)&C[row*ldc + n] = *(const float4*)&Cs[ml*68 + nl];
        } else {
            for (int j = 0; j < 4; j++)
                if (n + j < N) C[row*ldc + n + j] = Cs[ml*68 + nl + j];
        }
    }
}

// ------------------------- tensor-core persistent encoder -------------------
// 128 blocks x 256 threads. Block owns 8 hidden units (32 gate rows).
// Whh slice lives as tf32 mma B-fragments in REGISTERS (loaded once).
// 8 warps split K (128 each). Per step: h -> SMEM [b][k] (tf32), ldmatrix A
// frags, 128x mma.m16n8k8 per warp, partials reduced via sZ[8][32][33].
#define HPITCH 1028
__global__ void __launch_bounds__(256, 1)
k_enc_persist(const float* __restrict__ Whh, const int* __restrict__ lengths)
{
    extern __shared__ float sm[];
    float* sH = sm;                          // [32][HPITCH] tf32 bits
    float* sZ = sm + 32*HPITCH;              // [8][32][33]

    int tid  = threadIdx.x;
    int lane = tid & 31;
    int warp = tid >> 5;
    int u0   = blockIdx.x * 8;

    // ---- load Whh slice as B fragments (once) ----
    uint32_t wf[4][16][2];
    {
        int nr  = lane >> 2;                 // 0..7 row within n-tile
        int kq  = lane & 3;                  // k offset
        #pragma unroll
        for (int nt = 0; nt < 4; nt++) {
            int n = nt*8 + nr;               // 0..31 local gate row
            const float* wrow = Whh + (size_t)((n >> 3)*NH + u0 + (n & 7))*NH
                                + warp*128 + kq;
            #pragma unroll
            for (int kt = 0; kt < 16; kt++) {
                wf[nt][kt][0] = f2tf(__ldg(&wrow[kt*8]));
                wf[nt][kt][1] = f2tf(__ldg(&wrow[kt*8 + 4]));
            }
        }
    }

    int cb = tid & 31;
    int cu = tid >> 5;
    int mylen = lengths[cb];
    int len_hi = 0;
    #pragma unroll
    for (int i = 16; i < 32; i++) len_hi = max(len_hi, lengths[i]);
    float creg = 0.0f, hreg = 0.0f;

    g_hbuf[cb*NH + u0 + cu] = 0.0f;

    int lr    = tid >> 3;                    // loader h row 0..31
    int lane8 = tid & 7;
    uint32_t sh_base = cvta_s(sH);

    gridbar();

    for (int s = 0; s < NS; s++) {
        const float* hin  = g_hbuf + (s & 1)*(NB*NH);
        float*       hout = g_hbuf + ((s & 1) ^ 1)*(NB*NH);
        bool act_hi = (s < len_hi);

        const float* xp = g_xproj + ((size_t)s*NG + u0 + cu)*32 + cb;
        float xg0 = __ldg(&xp[0]);
        float xg1 = __ldg(&xp[(size_t)NH*32]);
        float xg2 = __ldg(&xp[(size_t)2*NH*32]);
        float xg3 = __ldg(&xp[(size_t)3*NH*32]);

        // ---- load h into sH [b][k] with tf32 convert ----
        if (lr < 16 || act_hi) {
            const float* hr = hin + lr*NH;
            #pragma unroll 8
            for (int kk = 0; kk < 32; kk++) {
                int k4 = (lane8 + 8*kk)*4;
                float4 v = __ldcg((const float4*)&hr[k4]);
                uint4 u = make_uint4(f2tf(v.x), f2tf(v.y), f2tf(v.z), f2tf(v.w));
                *(uint4*)&sH[lr*HPITCH + k4] = u;
            }
        }
        __syncthreads();

        // ---- mma: warp handles K range [warp*128, +128) ----
        float acc[2][4][4] = {};
        int kbase = warp*128;
        #pragma unroll
        for (int kt = 0; kt < 16; kt++) {
            int kof = kbase + kt*8 + ((lane >> 4) << 2);
            {
                uint32_t a0, a1, a2, a3;
                uint32_t addr = sh_base + (uint32_t)(((lane & 15))*HPITCH + kof)*4;
                ldsm_x4(a0, a1, a2, a3, addr);
                #pragma unroll
                for (int nt = 0; nt < 4; nt++)
                    mma_tf32(acc[0][nt], a0, a1, a2, a3,
                             wf[nt][kt][0], wf[nt][kt][1]);
            }
            if (act_hi) {
                uint32_t a0, a1, a2, a3;
                uint32_t addr = sh_base + (uint32_t)((16 + (lane & 15))*HPITCH + kof)*4;
                ldsm_x4(a0, a1, a2, a3, addr);
                #pragma unroll
                for (int nt = 0; nt < 4; nt++)
                    mma_tf32(acc[1][nt], a0, a1, a2, a3,
                             wf[nt][kt][0], wf[nt][kt][1]);
            }
        }

        // ---- write partials: sZ[warp][n][m], pitch 33 ----
        {
            float* zw = sZ + warp*(32*33);
            int rr = lane >> 2;
            int cc = (lane & 3)*2;
            #pragma unroll
            for (int mi = 0; mi < 2; mi++) {
                if (mi == 1 && !act_hi) break;
                #pragma unroll
                for (int nt = 0; nt < 4; nt++) {
                    int col = nt*8 + cc;
                    int row = mi*16 + rr;
                    zw[col*33 + row]       = acc[mi][nt][0];
                    zw[(col+1)*33 + row]   = acc[mi][nt][1];
                    zw[col*33 + row + 8]   = acc[mi][nt][2];
                    zw[(col+1)*33 + row+8] = acc[mi][nt][3];
                }
            }
        }
        __syncthreads();

        // ---- LSTM cell for (cb, u0+cu) ----
        float zg4[4] = {xg0, xg1, xg2, xg3};
        #pragma unroll
        for (int g = 0; g < 4; g++) {
            int col = g*8 + cu;
            #pragma unroll
            for (int w = 0; w < 8; w++)
                zg4[g] += sZ[w*(32*33) + col*33 + cb];
        }
        float cn = sigmf_(zg4[1])*creg + sigmf_(zg4[0])*tanhf(zg4[2]);
        float hn = sigmf_(zg4[3])*tanhf(cn);
        bool msk = (s < mylen);
        creg = msk ? cn : creg;
        hreg = msk ? hn : hreg;
        hout[cb*NH + u0 + cu] = hreg;
        g_enc_out[((size_t)(s*NB + cb))*NH + u0 + cu] = msk ? hreg : 0.0f;

        gridbar();
    }

    g_h[cb*NH + u0 + cu] = hreg;
    g_c[cb*NH + u0 + cu] = creg;
}

// ------------------------- persistent decoder helpers -----------------------
__device__ __forceinline__ void dec_feat(int tt, const float* __restrict__ hsrc,
    const float* __restrict__ out_W, const float* __restrict__ out_b,
    float* sH, float* sZ, int fn0)
{
    int tid = threadIdx.x;
    int r   = tid >> 6;
    int fks = (tid >> 5) & 1;
    int fb  = tid & 31;
    int lb  = tid >> 3;
    int lq  = tid & 7;
    const float* wrow = out_W + (size_t)(fn0 + r)*(2*NH);
    float fa = 0.f;

    float4 p0, p1, p2, p3;
    {
        const float* hr = hsrc + lb*NH;
        p0 = __ldcg((const float4*)&hr[4*lq]);
        p1 = __ldcg((const float4*)&hr[4*(lq+8)]);
        p2 = __ldcg((const float4*)&hr[4*(lq+16)]);
        p3 = __ldcg((const float4*)&hr[4*(lq+24)]);
        stash4(sH, lq, lb, p0, p1, p2, p3);
    }
    __syncthreads();

    for (int ch = 0; ch < 16; ch++) {
        float* cur = sH + (ch & 1)*(128*36);
        if (ch < 15) {
            int cn_ = ch + 1;
            const float* src = (cn_ < 8) ? hsrc : g_ctx;
            const float* hr = src + lb*NH + (cn_ & 7)*128;
            p0 = __ldcg((const float4*)&hr[4*lq]);
            p1 = __ldcg((const float4*)&hr[4*(lq+8)]);
            p2 = __ldcg((const float4*)&hr[4*(lq+16)]);
            p3 = __ldcg((const float4*)&hr[4*(lq+24)]);
        }
        const float* wc = wrow + ch*128 + fks*64;
        const float* hc = cur + fks*64*36 + fb;
        #pragma unroll 16
        for (int k = 0; k < 64; k++)
            fa += __ldg(&wc[k]) * hc[k*36];
        if (ch < 15)
            stash4(sH + ((ch & 1) ^ 1)*(128*36), lq, lb, p0, p1, p2, p3);
        __syncthreads();
    }
    sZ[(r*2 + fks)*33 + fb] = fa;
    __syncthreads();
    if (tid < 128) {
        int rr = tid >> 5, bb = tid & 31;
        float v = sZ[(rr*2)*33 + bb] + sZ[(rr*2+1)*33 + bb] + __ldg(&out_b[fn0 + rr]);
        g_feat[((size_t)(tt*NB + bb))*ND + fn0 + rr] = v;
    }
    __syncthreads();
}

__device__ __forceinline__ void dec_attn(int b, int mylen,
    const float* __restrict__ hcur,
    const float* __restrict__ ak_W, const float* __restrict__ ak_b,
    float* sW)
{
    int tid = threadIdx.x;
    float* sh_ = sW;
    float* sak = sW + 1024;
    float* se  = sW + 1152;
    float* sr  = sW + 1280;

    for (int i = tid; i < NH; i += 256) sh_[i] = __ldcg(&hcur[b*NH + i]);
    __syncthreads();

    if (tid < NK) {
        const float* wr = ak_W + (size_t)tid*NH;
        float acc0 = 0.f, acc1 = 0.f;
        for (int k = 0; k < NH; k += 8) {
            float4 w0 = *(const float4*)&wr[k];
            float4 w1 = *(const float4*)&wr[k+4];
            float4 h0 = *(const float4*)&sh_[k];
            float4 h1 = *(const float4*)&sh_[k+4];
            acc0 += w0.x*h0.x + w0.y*h0.y + w0.z*h0.z + w0.w*h0.w;
            acc1 += w1.x*h1.x + w1.y*h1.y + w1.z*h1.z + w1.w*h1.w;
        }
        sak[tid] = tanhf(acc0 + acc1 + ak_b[tid]);
    }
    __syncthreads();

    if (tid < NS) {
        const float* qr = g_qkey + ((size_t)(tid*NB + b))*NK;
        float acc = 0.f;
        for (int k = 0; k < NK; k++) acc += qr[k]*sak[k];
        se[tid] = (tid < mylen) ? acc : -INFINITY;
    }
    __syncthreads();

    sr[tid] = (tid < NS) ? se[tid] : -INFINITY;
    __syncthreads();
    for (int off = 128; off >= 1; off >>= 1) {
        if (tid < off) sr[tid] = fmaxf(sr[tid], sr[tid+off]);
        __syncthreads();
    }
    float mx = sr[0];
    __syncthreads();

    float ex = (tid < NS) ? expf(se[tid] - mx) : 0.0f;
    sr[tid] = ex;
    __syncthreads();
    for (int off = 128; off >= 1; off >>= 1) {
        if (tid < off) sr[tid] += sr[tid+off];
        __syncthreads();
    }
    float inv = 1.0f / sr[0];
    __syncthreads();
    if (tid < NS) g_attw[b*NS + tid] = ex * inv;
    __syncthreads();
}

// ------------------------- persistent decoder -------------------------------
__global__ void __launch_bounds__(256, 1)
k_dec_persist(const float* __restrict__ dec_Wih, const float* __restrict__ dec_Whh,
              const float* __restrict__ ak_W,   const float* __restrict__ ak_b,
              const float* __restrict__ out_W,  const float* __restrict__ out_b,
              const int* __restrict__ lengths)
{
    extern __shared__ float sm[];
    float* sW = sm;                     // 2 x [128][36]
    float* sH = sm + 2*128*36;          // 2 x [128][36]
    float* sZ = sm + 4*128*36;          // [4][32][33]

    int tid = threadIdx.x;
    int blk = blockIdx.x;
    int u0  = blk * 8;
    int fn0 = blk * 4;

    int cb = tid & 31, cu = tid >> 5;
    float creg = g_c[cb*NH + u0 + cu];

    int rq = tid & 7;
    int bq = (tid >> 3) & 7;
    int ks = tid >> 6;
    int lb = tid >> 3;
    int lq = tid & 7;
    int wr_ = tid >> 3;
    int wn_ = (wr_ >> 3)*NH + u0 + (wr_ & 7);

    int mylen = (blk < 32) ? lengths[blk] : 0;

    for (int t = 0; t < NT; t++) {
        const float* hcur = (t == 0) ? g_h : (g_hbuf + ((t-1) & 1)*(NB*NH));
        float*       hnew = g_hbuf + (t & 1)*(NB*NH);

        if (t > 0)
            dec_feat(t-1, hcur, out_W, out_b, sH, sZ, fn0);
        if (blk < 32)
            dec_attn(blk, mylen, hcur, ak_W, ak_b, sW);
        gridbar();

        // ---- context ----
        {
            int b  = blk & 31;
            int hq = blk >> 5;
            if (tid < NS) sZ[tid] = __ldcg(&g_attw[b*NS + tid]);
            __syncthreads();
            int hh = hq*256 + tid;
            float a0 = 0.f, a1 = 0.f, a2 = 0.f, a3 = 0.f;
            #pragma unroll 4
            for (int s = 0; s < NS; s += 4) {
                a0 += sZ[s+0]*__ldg(&g_qval[((size_t)((s+0)*NB + b))*NH + hh]);
                a1 += sZ[s+1]*__ldg(&g_qval[((size_t)((s+1)*NB + b))*NH + hh]);
                a2 += sZ[s+2]*__ldg(&g_qval[((size_t)((s+2)*NB + b))*NH + hh]);
                a3 += sZ[s+3]*__ldg(&g_qval[((size_t)((s+3)*NB + b))*NH + hh]);
            }
            g_ctx[b*NH + hh] = (a0 + a1) + (a2 + a3);
            __syncthreads();
        }
        gridbar();

        const float* xp = g_dxe + ((size_t)t*NG + u0 + cu)*32 + cb;
        float xg0 = __ldg(&xp[0]);
        float xg1 = __ldg(&xp[(size_t)NH*32]);
        float xg2 = __ldg(&xp[(size_t)2*NH*32]);
        float xg3 = __ldg(&xp[(size_t)3*NH*32]);

        // ---- z GEMM, double-buffered W and H, f32x2 core ----
        ull_t acc2[4][2] = {};
        float4 pH0, pH1, pH2, pH3, pW0, pW1, pW2, pW3;
        {
            const float* hr = hcur + lb*NH;
            pH0 = __ldcg((const float4*)&hr[4*lq]);
            pH1 = __ldcg((const float4*)&hr[4*(lq+8)]);
            pH2 = __ldcg((const float4*)&hr[4*(lq+16)]);
            pH3 = __ldcg((const float4*)&hr[4*(lq+24)]);
            const float* wrow = dec_Whh + (size_t)wn_*NH;
            pW0 = __ldg((const float4*)&wrow[4*lq]);
            pW1 = __ldg((const float4*)&wrow[4*(lq+8)]);
            pW2 = __ldg((const float4*)&wrow[4*(lq+16)]);
            pW3 = __ldg((const float4*)&wrow[4*(lq+24)]);
            stash4(sH, lq, lb, pH0, pH1, pH2, pH3);
            stash4(sW, lq, wr_, pW0, pW1, pW2, pW3);
        }
        __syncthreads();

        for (int ch = 0; ch < 16; ch++) {
            float* curW = sW + (ch & 1)*(128*36);
            float* curH = sH + (ch & 1)*(128*36);
            if (ch < 15) {
                int cn_ = ch + 1;
                const float* asrc = (cn_ < 8) ? hcur : g_ctx;
                int kc = (cn_ & 7)*128;
                const float* hr = asrc + lb*NH + kc;
                pH0 = __ldcg((const float4*)&hr[4*lq]);
                pH1 = __ldcg((const float4*)&hr[4*(lq+8)]);
                pH2 = __ldcg((const float4*)&hr[4*(lq+16)]);
                pH3 = __ldcg((const float4*)&hr[4*(lq+24)]);
                const float* wrow = (cn_ < 8)
                    ? (dec_Whh + (size_t)wn_*NH + kc)
                    : (dec_Wih + (size_t)wn_*(ND+NH) + ND + kc);
                pW0 = __ldg((const float4*)&wrow[4*lq]);
                pW1 = __ldg((const float4*)&wrow[4*(lq+8)]);
                pW2 = __ldg((const float4*)&wrow[4*(lq+16)]);
                pW3 = __ldg((const float4*)&wrow[4*(lq+24)]);
            }
            for (int kb = 0; kb < 128; kb += 16) {
                int k = kb + 4*ks;
                #pragma unroll
                for (int kk2 = 0; kk2 < 4; kk2++) {
                    float4 wv = *(const float4*)&curW[(k+kk2)*36 + 4*rq];
                    ulonglong2 hq2 = *(const ulonglong2*)&curH[(k+kk2)*36 + 4*bq];
                    ull_t d0 = dup2(wv.x), d1 = dup2(wv.y);
                    ull_t d2 = dup2(wv.z), d3 = dup2(wv.w);
                    ffma2(acc2[0][0], d0, hq2.x); ffma2(acc2[0][1], d0, hq2.y);
                    ffma2(acc2[1][0], d1, hq2.x); ffma2(acc2[1][1], d1, hq2.y);
                    ffma2(acc2[2][0], d2, hq2.x); ffma2(acc2[2][1], d2, hq2.y);
                    ffma2(acc2[3][0], d3, hq2.x); ffma2(acc2[3][1], d3, hq2.y);
                }
            }
            if (ch < 15) {
                stash4(sH + ((ch & 1) ^ 1)*(128*36), lq, lb, pH0, pH1, pH2, pH3);
                stash4(sW + ((ch & 1) ^ 1)*(128*36), lq, wr_, pW0, pW1, pW2, pW3);
            }
            __syncthreads();
        }

        #pragma unroll
        for (int i = 0; i < 4; i++) {
            float2 t0 = unpk(acc2[i][0]);
            float2 t1 = unpk(acc2[i][1]);
            float* zr = &sZ[(ks*32 + 4*rq + i)*33 + 4*bq];
            zr[0] = t0.x; zr[1] = t0.y; zr[2] = t1.x; zr[3] = t1.y;
        }
        __syncthreads();

        {
            float zg4[4] = {xg0, xg1, xg2, xg3};
            #pragma unroll
            for (int g = 0; g < 4; g++)
                #pragma unroll
                for (int q = 0; q < 4; q++) zg4[g] += sZ[(q*32 + g*8 + cu)*33 + cb];
            float cn = sigmf_(zg4[1])*creg + sigmf_(zg4[0])*tanhf(zg4[2]);
            float hn = sigmf_(zg4[3])*tanhf(cn);
            creg = cn;
            hnew[cb*NH + u0 + cu] = hn;
        }
        __syncthreads();
        gridbar();
    }

    {
        const float* hlast = g_hbuf + ((NT-1) & 1)*(NB*NH);
        dec_feat(NT-1, hlast, out_W, out_b, sH, sZ, fn0);
    }
}

// =============================================================================
extern "C" void kernel_launch(void* const* d_in, const int* in_sizes, int n_in,
                              void* d_out, int out_size)
{
    const float* embed    = (const float*)d_in[0];
    const float* enc_Wih  = (const float*)d_in[1];
    const float* enc_Whh  = (const float*)d_in[2];
    const float* enc_bih  = (const float*)d_in[3];
    const float* enc_bhh  = (const float*)d_in[4];
    const float* dec_Wih  = (const float*)d_in[5];
    const float* dec_Whh  = (const float*)d_in[6];
    const float* dec_bih  = (const float*)d_in[7];
    const float* dec_bhh  = (const float*)d_in[8];
    const float* qk_W     = (const float*)d_in[9];
    const float* qk_b     = (const float*)d_in[10];
    const float* qv_W     = (const float*)d_in[11];
    const float* qv_b     = (const float*)d_in[12];
    const float* ak_W     = (const float*)d_in[13];
    const float* ak_b     = (const float*)d_in[14];
    const float* out_W    = (const float*)d_in[15];
    const float* out_b    = (const float*)d_in[16];
    const float* wd_b     = (const float*)d_in[17];
    const float* hfc1_W   = (const float*)d_in[18];
    const float* hfc1_b   = (const float*)d_in[19];
    const float* hfc2_W   = (const float*)d_in[20];
    const float* hfc2_b   = (const float*)d_in[21];
    const float* cfc1_W   = (const float*)d_in[22];
    const float* cfc1_b   = (const float*)d_in[23];
    const float* cfc2_W   = (const float*)d_in[24];
    const float* cfc2_b   = (const float*)d_in[25];
    const int*   src_seqs = (const int*)d_in[26];
    const int*   src_len  = (const int*)d_in[27];
    const int*   trg_seqs = (const int*)d_in[28];
    float* out = (float*)d_out;

    float *d_src_embed, *d_ans_embed, *d_xproj, *d_dxe, *d_h, *d_c;
    float *d_enc_out, *d_qkey, *d_qval, *d_tmp, *d_feat;
    cudaGetSymbolAddress((void**)&d_src_embed, g_src_embed);
    cudaGetSymbolAddress((void**)&d_ans_embed, g_ans_embed);
    cudaGetSymbolAddress((void**)&d_xproj,     g_xproj);
    cudaGetSymbolAddress((void**)&d_dxe,       g_dxe);
    cudaGetSymbolAddress((void**)&d_h,         g_h);
    cudaGetSymbolAddress((void**)&d_c,         g_c);
    cudaGetSymbolAddress((void**)&d_enc_out,   g_enc_out);
    cudaGetSymbolAddress((void**)&d_qkey,      g_qkey);
    cudaGetSymbolAddress((void**)&d_qval,      g_qval);
    cudaGetSymbolAddress((void**)&d_tmp,       g_tmp);
    cudaGetSymbolAddress((void**)&d_feat,      g_feat);

    // ---- precompute ----
    k_gather<<<NS*NB, 128>>>(src_seqs, NS, embed, d_src_embed);
    k_gather<<<NT*NB, 128>>>(trg_seqs, 20, embed, d_ans_embed);

    k_sgemm<<<dim3(NG/64, (NS*NB)/128), 256>>>(NS*NB, NG, ND,
        d_src_embed, ND, enc_Wih, ND, enc_bih, enc_bhh, d_xproj, NG, 0, 2);
    k_sgemm<<<dim3(NG/64, (NT*NB + 127)/128), 256>>>(NT*NB, NG, ND,
        d_ans_embed, ND, dec_Wih, ND + NH, dec_bih, dec_bhh, d_dxe, NG, 0, 2);

    // ---- encoder recurrence: tensor-core persistent kernel ----
    const int enc_smem = (32*HPITCH + 8*32*33) * (int)sizeof(float);
    cudaFuncSetAttribute(k_enc_persist,
                         cudaFuncAttributeMaxDynamicSharedMemorySize, enc_smem);
    k_enc_persist<<<NBLK, 256, enc_smem>>>(enc_Whh, src_len);

    // ---- bridge MLPs ----
    k_sgemm<<<dim3(2048/64, 1), 256>>>(NB, 2048, NH, d_h, NH, hfc1_W, NH,
                                       hfc1_b, nullptr, d_tmp, 2048, 2, 0);
    k_sgemm<<<dim3(NH/64, 1), 256>>>(NB, NH, 2048, d_tmp, 2048, hfc2_W, 2048,
                                     hfc2_b, nullptr, d_h, NH, 0, 0);
    k_sgemm<<<dim3(2048/64, 1), 256>>>(NB, 2048, NH, d_c, NH, cfc1_W, NH,
                                       cfc1_b, nullptr, d_tmp, 2048, 2, 0);
    k_sgemm<<<dim3(NH/64, 1), 256>>>(NB, NH, 2048, d_tmp, 2048, cfc2_W, 2048,
                                     cfc2_b, nullptr, d_c, NH, 0, 0);

    // ---- attention precompute ----
    k_sgemm<<<dim3((NK + 63)/64, (NS*NB)/128), 256>>>(NS*NB, NK, NH,
        d_enc_out, NH, qk_W, NH, qk_b, nullptr, d_qkey, NK, 1, 0);
    k_sgemm<<<dim3(NH/64, (NS*NB)/128), 256>>>(NS*NB, NH, NH,
        d_enc_out, NH, qv_W, NH, qv_b, nullptr, d_qval, NH, 0, 0);

    // ---- decoder recurrence ----
    const int dec_smem = (4*128*36 + 4*32*33) * (int)sizeof(float);
    cudaFuncSetAttribute(k_dec_persist,
                         cudaFuncAttributeMaxDynamicSharedMemorySize, dec_smem);
    k_dec_persist<<<NBLK, 256, dec_smem>>>(dec_Wih, dec_Whh, ak_W, ak_b,
                                           out_W, out_b, src_len);

    // ---- final logits ----
    k_sgemm<<<dim3(NV/64, (NT*NB + 127)/128), 256>>>(NT*NB, NV, ND,
        d_feat, ND, embed, ND, wd_b, nullptr, out, NV, 0, 1);

    (void)in_sizes; (void)n_in; (void)out_size;
}

// round 9
// speedup vs baseline: 2.0405x; 1.0818x over previous
#include <cuda_runtime.h>
#include <math.h>
#include <stdint.h>

// Problem dims (fixed by the dataset)
#define NB 32      // batch
#define NS 128     // src seq len
#define NT 19      // decoder steps (T-1)
#define ND 512     // embed dim
#define NH 1024    // hidden
#define NG 4096    // 4*H
#define NK 100     // attn key dim
#define NV 32000   // vocab
#define NBLK 128

typedef unsigned long long ull_t;

// ------------------------- scratch (device globals; no allocs) ---------------
__device__ float g_src_embed[NS*NB*ND];
__device__ float g_ans_embed[NT*NB*ND];
__device__ float g_xproj[NS*NG*NB];         // [s][n][b]
__device__ float g_dxe[NT*NG*NB];           // [t][n][b]
__device__ float g_h[NB*NH];
__device__ float g_c[NB*NH];
__device__ float g_hbuf[2*NB*NH];
__device__ float g_enc_out[NS*NB*NH];
__device__ float g_qkey[NS*NB*NK];
__device__ float g_qval[NS*NB*NH];
__device__ float g_tmp[NB*2048];
__device__ float g_ctx[NB*NH];
__device__ float g_attw[NB*NS];
__device__ float g_feat[NT*NB*ND];

__device__ unsigned g_barcnt = 0;
__device__ unsigned g_bargen = 0;

__device__ __forceinline__ float sigmf_(float x) { return 1.0f/(1.0f+expf(-x)); }

// ---- packed f32x2 helpers (decoder FFMA2 path) ----
__device__ __forceinline__ void ffma2(ull_t& d, ull_t a, ull_t b)
{
    asm("fma.rn.f32x2 %0, %1, %2, %3;" : "=l"(d) : "l"(a), "l"(b), "l"(d));
}
__device__ __forceinline__ ull_t dup2(float x)
{
    ull_t r;
    asm("mov.b64 %0, {%1, %1};" : "=l"(r) : "f"(x));
    return r;
}
__device__ __forceinline__ float2 unpk(ull_t v)
{
    float2 r;
    asm("mov.b64 {%0, %1}, %2;" : "=f"(r.x), "=f"(r.y) : "l"(v));
    return r;
}

// ---- tf32 tensor-core helpers ----
__device__ __forceinline__ uint32_t f2tf(float x)
{
    uint32_t r;
    asm("cvt.rna.tf32.f32 %0, %1;" : "=r"(r) : "f"(x));
    return r;
}
__device__ __forceinline__ uint32_t cvta_s(const void* p)
{
    uint32_t a;
    asm("{ .reg .u64 t; cvta.to.shared.u64 t, %1; cvt.u32.u64 %0, t; }"
        : "=r"(a) : "l"(p));
    return a;
}
__device__ __forceinline__ void ldsm_x4(uint32_t& r0, uint32_t& r1,
                                        uint32_t& r2, uint32_t& r3, uint32_t addr)
{
    asm volatile("ldmatrix.sync.aligned.m8n8.x4.b16 {%0,%1,%2,%3}, [%4];"
                 : "=r"(r0), "=r"(r1), "=r"(r2), "=r"(r3) : "r"(addr));
}
__device__ __forceinline__ void mma_tf32(float* d, uint32_t a0, uint32_t a1,
                                         uint32_t a2, uint32_t a3,
                                         uint32_t b0, uint32_t b1)
{
    asm volatile(
        "mma.sync.aligned.m16n8k8.row.col.f32.tf32.tf32.f32 "
        "{%0,%1,%2,%3}, {%4,%5,%6,%7}, {%8,%9}, {%0,%1,%2,%3};"
        : "+f"(d[0]), "+f"(d[1]), "+f"(d[2]), "+f"(d[3])
        : "r"(a0), "r"(a1), "r"(a2), "r"(a3), "r"(b0), "r"(b1));
}

__device__ __forceinline__ void gridbar()
{
    __syncthreads();
    if (threadIdx.x == 0) {
        __threadfence();
        volatile unsigned* vgen = &g_bargen;
        unsigned gen = *vgen;
        if (atomicAdd(&g_barcnt, 1u) == NBLK - 1) {
            g_barcnt = 0;
            __threadfence();
            atomicAdd(&g_bargen, 1u);
        } else {
            while (*vgen == gen) { __nanosleep(16); }
        }
        __threadfence();
    }
    __syncthreads();
}

// helper: scatter 4 prefetched float4s (rows kk=4*(lq+8p)) into tile[k][row]
__device__ __forceinline__ void stash4(float* buf, int lq, int row,
                                       float4 p0, float4 p1, float4 p2, float4 p3)
{
    buf[(4*lq+0)*36+row]=p0.x; buf[(4*lq+1)*36+row]=p0.y;
    buf[(4*lq+2)*36+row]=p0.z; buf[(4*lq+3)*36+row]=p0.w;
    buf[(4*(lq+8)+0)*36+row]=p1.x; buf[(4*(lq+8)+1)*36+row]=p1.y;
    buf[(4*(lq+8)+2)*36+row]=p1.z; buf[(4*(lq+8)+3)*36+row]=p1.w;
    buf[(4*(lq+16)+0)*36+row]=p2.x; buf[(4*(lq+16)+1)*36+row]=p2.y;
    buf[(4*(lq+16)+2)*36+row]=p2.z; buf[(4*(lq+16)+3)*36+row]=p2.w;
    buf[(4*(lq+24)+0)*36+row]=p3.x; buf[(4*(lq+24)+1)*36+row]=p3.y;
    buf[(4*(lq+24)+2)*36+row]=p3.z; buf[(4*(lq+24)+3)*36+row]=p3.w;
}

// ------------------------- embedding gather ---------------------------------
__global__ void k_gather(const int* __restrict__ seq, int seq_stride,
                         const float* __restrict__ embed, float* __restrict__ out)
{
    int row = blockIdx.x;
    int st  = row / NB;
    int b   = row % NB;
    int tok = seq[b*seq_stride + st];
    const float4* src = (const float4*)(embed + (size_t)tok*ND);
    float4*       dst = (float4*)(out + (size_t)row*ND);
    dst[threadIdx.x] = src[threadIdx.x];
}

// ------------------------- tf32 tensor-core GEMM (pipelined) -----------------
// Double-buffered smem stages + register prefetch of global loads: one
// __syncthreads per 16-k iteration, global latency hidden under mma.
// swap_grid: m0 from blockIdx.x (adjacent blocks share W n-tile via L2).
__global__ __launch_bounds__(256)
void k_sgemm(int M, int N, int K,
             const float* __restrict__ A, int lda,
             const float* __restrict__ W, int ldw,
             const float* __restrict__ bias1, const float* __restrict__ bias2,
             float* __restrict__ C, int ldc, int act, int out_map, int swap_grid)
{
    __shared__ __align__(16) uint32_t smem_u[8704];   // 34816 B
    // stage layout: As[s]=2560 u32, Ws[s]=1280 u32; stage stride 3840
    float* Cs = (float*)smem_u;                       // [128][68] reuse at end

    int tid  = threadIdx.x;
    int lane = tid & 31;
    int warp = tid >> 5;
    int wm   = warp & 3;
    int wn   = warp >> 2;
    int m0, n0;
    if (swap_grid) { m0 = blockIdx.x*128; n0 = blockIdx.y*64; }
    else           { m0 = blockIdx.y*128; n0 = blockIdx.x*64; }

    int ra = tid >> 2;
    int kc = (tid & 3) * 4;

    uint32_t as_base0 = cvta_s(smem_u);
    uint32_t as_base1 = cvta_s(smem_u + 3840);
    uint32_t ws_row   = (uint32_t)(wn*32 + (lane >> 2))*20 + (lane & 3);

    float acc[2][4][4] = {};

    bool a0v = (m0 + ra < M);
    bool a1v = (m0 + ra + 64 < M);
    bool wv_ = (n0 + ra < N) && (ra < 64);
    const float* Arow0 = A + (size_t)(m0+ra)*lda + kc;
    const float* Arow1 = A + (size_t)(m0+ra+64)*lda + kc;
    const float* Wrow  = W + (size_t)(n0+ra)*ldw + kc;

    float4 a0 = make_float4(0.f,0.f,0.f,0.f);
    float4 a1 = make_float4(0.f,0.f,0.f,0.f);
    float4 w4 = make_float4(0.f,0.f,0.f,0.f);
    if (a0v) a0 = *(const float4*)Arow0;
    if (a1v) a1 = *(const float4*)Arow1;
    if (wv_) w4 = *(const float4*)Wrow;

    int nit = K >> 4;
    // store stage 0
    {
        uint32_t* As = smem_u;
        uint32_t* Ws = smem_u + 2560;
        *(uint4*)&As[ra*20 + kc]      = make_uint4(f2tf(a0.x), f2tf(a0.y), f2tf(a0.z), f2tf(a0.w));
        *(uint4*)&As[(ra+64)*20 + kc] = make_uint4(f2tf(a1.x), f2tf(a1.y), f2tf(a1.z), f2tf(a1.w));
        if (ra < 64)
            *(uint4*)&Ws[ra*20 + kc]  = make_uint4(f2tf(w4.x), f2tf(w4.y), f2tf(w4.z), f2tf(w4.w));
    }
    __syncthreads();

    for (int it = 0; it < nit; it++) {
        int cur = it & 1;
        if (it + 1 < nit) {
            int k0 = (it + 1) << 4;
            a0 = make_float4(0.f,0.f,0.f,0.f);
            a1 = make_float4(0.f,0.f,0.f,0.f);
            w4 = make_float4(0.f,0.f,0.f,0.f);
            if (a0v) a0 = *(const float4*)(Arow0 + k0);
            if (a1v) a1 = *(const float4*)(Arow1 + k0);
            if (wv_) w4 = *(const float4*)(Wrow  + k0);
        }

        uint32_t as_base = cur ? as_base1 : as_base0;
        uint32_t* Ws = smem_u + cur*3840 + 2560;
        #pragma unroll
        for (int ks = 0; ks < 16; ks += 8) {
            uint32_t afr[2][4];
            #pragma unroll
            for (int mi = 0; mi < 2; mi++) {
                uint32_t row = (uint32_t)(wm*32 + mi*16 + (lane & 15));
                uint32_t kof = (uint32_t)(ks + ((lane >> 4) << 2));
                uint32_t addr = as_base + (row*20 + kof)*4;
                ldsm_x4(afr[mi][0], afr[mi][1], afr[mi][2], afr[mi][3], addr);
            }
            uint32_t bfr[4][2];
            #pragma unroll
            for (int j = 0; j < 4; j++) {
                bfr[j][0] = Ws[ws_row + (uint32_t)(j*8)*20 + ks];
                bfr[j][1] = Ws[ws_row + (uint32_t)(j*8)*20 + ks + 4];
            }
            #pragma unroll
            for (int mi = 0; mi < 2; mi++)
                #pragma unroll
                for (int j = 0; j < 4; j++)
                    mma_tf32(acc[mi][j], afr[mi][0], afr[mi][1], afr[mi][2],
                             afr[mi][3], bfr[j][0], bfr[j][1]);
        }

        if (it + 1 < nit) {
            uint32_t* As2 = smem_u + (cur ^ 1)*3840;
            uint32_t* Ws2 = smem_u + (cur ^ 1)*3840 + 2560;
            *(uint4*)&As2[ra*20 + kc]      = make_uint4(f2tf(a0.x), f2tf(a0.y), f2tf(a0.z), f2tf(a0.w));
            *(uint4*)&As2[(ra+64)*20 + kc] = make_uint4(f2tf(a1.x), f2tf(a1.y), f2tf(a1.z), f2tf(a1.w));
            if (ra < 64)
                *(uint4*)&Ws2[ra*20 + kc]  = make_uint4(f2tf(w4.x), f2tf(w4.y), f2tf(w4.z), f2tf(w4.w));
        }
        __syncthreads();
    }

    // stage C with bias + activation: Cs[m][n], stride 68
    #pragma unroll
    for (int mi = 0; mi < 2; mi++) {
        int ml0 = wm*32 + mi*16 + (lane >> 2);
        #pragma unroll
        for (int j = 0; j < 4; j++) {
            int nl = wn*32 + j*8 + (lane & 3)*2;
            float b0v = 0.f, b1v = 0.f;
            if (n0 + nl < N) {
                b0v = bias1[n0+nl];
                if (bias2) b0v += bias2[n0+nl];
            }
            if (n0 + nl + 1 < N) {
                b1v = bias1[n0+nl+1];
                if (bias2) b1v += bias2[n0+nl+1];
            }
            float v0 = acc[mi][j][0] + b0v;
            float v1 = acc[mi][j][1] + b1v;
            float v2 = acc[mi][j][2] + b0v;
            float v3 = acc[mi][j][3] + b1v;
            if (act == 1) { v0=tanhf(v0); v1=tanhf(v1); v2=tanhf(v2); v3=tanhf(v3); }
            else if (act == 2) { v0=fmaxf(v0,0.f); v1=fmaxf(v1,0.f);
                                 v2=fmaxf(v2,0.f); v3=fmaxf(v3,0.f); }
            Cs[ml0*68 + nl]       = v0;
            Cs[ml0*68 + nl + 1]   = v1;
            Cs[(ml0+8)*68 + nl]   = v2;
            Cs[(ml0+8)*68 + nl+1] = v3;
        }
    }
    __syncthreads();

    if (out_map == 2) {
        for (int c = tid; c < 2048; c += 256) {
            int qb = (c & 7) * 4;
            int nl = (c >> 3) & 63;
            int sh = c >> 9;
            int mgrp = m0 + sh*32;
            if (mgrp >= M) continue;
            float4 v4 = make_float4(Cs[(sh*32+qb+0)*68 + nl],
                                    Cs[(sh*32+qb+1)*68 + nl],
                                    Cs[(sh*32+qb+2)*68 + nl],
                                    Cs[(sh*32+qb+3)*68 + nl]);
            *(float4*)&C[((size_t)(mgrp >> 5)*NG + n0 + nl)*32 + qb] = v4;
        }
        return;
    }

    for (int c = tid; c < 2048; c += 256) {
        int ml = c >> 4;
        int nl = (c & 15) * 4;
        int m = m0 + ml;
        if (m >= M) continue;
        size_t row = (out_map == 1) ? (size_t)((m & 31)*NT + (m >> 5)) : (size_t)m;
        int n = n0 + nl;
        if (n + 3 < N) {
            *(float4*)&C[row*ldc + n] = *(const float4*)&Cs[ml*68 + nl];
        } else {
            for (int j = 0; j < 4; j++)
                if (n + j < N) C[row*ldc + n + j] = Cs[ml*68 + nl + j];
        }
    }
}

// ------------------------- tensor-core persistent encoder -------------------
#define HPITCH 1028
__global__ void __launch_bounds__(256, 1)
k_enc_persist(const float* __restrict__ Whh, const int* __restrict__ lengths)
{
    extern __shared__ float sm[];
    float* sH = sm;                          // [32][HPITCH] tf32 bits
    float* sZ = sm + 32*HPITCH;              // [8][32][33]

    int tid  = threadIdx.x;
    int lane = tid & 31;
    int warp = tid >> 5;
    int u0   = blockIdx.x * 8;

    // ---- load Whh slice as B fragments (once) ----
    uint32_t wf[4][16][2];
    {
        int nr  = lane >> 2;
        int kq  = lane & 3;
        #pragma unroll
        for (int nt = 0; nt < 4; nt++) {
            int n = nt*8 + nr;
            const float* wrow = Whh + (size_t)((n >> 3)*NH + u0 + (n & 7))*NH
                                + warp*128 + kq;
            #pragma unroll
            for (int kt = 0; kt < 16; kt++) {
                wf[nt][kt][0] = f2tf(__ldg(&wrow[kt*8]));
                wf[nt][kt][1] = f2tf(__ldg(&wrow[kt*8 + 4]));
            }
        }
    }

    int cb = tid & 31;
    int cu = tid >> 5;
    int mylen = lengths[cb];
    int len_hi = 0;
    #pragma unroll
    for (int i = 16; i < 32; i++) len_hi = max(len_hi, lengths[i]);
    float creg = 0.0f, hreg = 0.0f;

    g_hbuf[cb*NH + u0 + cu] = 0.0f;

    int lr    = tid >> 3;
    int lane8 = tid & 7;
    uint32_t sh_base = cvta_s(sH);

    gridbar();

    for (int s = 0; s < NS; s++) {
        const float* hin  = g_hbuf + (s & 1)*(NB*NH);
        float*       hout = g_hbuf + ((s & 1) ^ 1)*(NB*NH);
        bool act_hi = (s < len_hi);

        const float* xp = g_xproj + ((size_t)s*NG + u0 + cu)*32 + cb;
        float xg0 = __ldg(&xp[0]);
        float xg1 = __ldg(&xp[(size_t)NH*32]);
        float xg2 = __ldg(&xp[(size_t)2*NH*32]);
        float xg3 = __ldg(&xp[(size_t)3*NH*32]);

        if (lr < 16 || act_hi) {
            const float* hr = hin + lr*NH;
            #pragma unroll 8
            for (int kk = 0; kk < 32; kk++) {
                int k4 = (lane8 + 8*kk)*4;
                float4 v = __ldcg((const float4*)&hr[k4]);
                uint4 u = make_uint4(f2tf(v.x), f2tf(v.y), f2tf(v.z), f2tf(v.w));
                *(uint4*)&sH[lr*HPITCH + k4] = u;
            }
        }
        __syncthreads();

        float acc[2][4][4] = {};
        int kbase = warp*128;
        #pragma unroll
        for (int kt = 0; kt < 16; kt++) {
            int kof = kbase + kt*8 + ((lane >> 4) << 2);
            {
                uint32_t a0, a1, a2, a3;
                uint32_t addr = sh_base + (uint32_t)(((lane & 15))*HPITCH + kof)*4;
                ldsm_x4(a0, a1, a2, a3, addr);
                #pragma unroll
                for (int nt = 0; nt < 4; nt++)
                    mma_tf32(acc[0][nt], a0, a1, a2, a3,
                             wf[nt][kt][0], wf[nt][kt][1]);
            }
            if (act_hi) {
                uint32_t a0, a1, a2, a3;
                uint32_t addr = sh_base + (uint32_t)((16 + (lane & 15))*HPITCH + kof)*4;
                ldsm_x4(a0, a1, a2, a3, addr);
                #pragma unroll
                for (int nt = 0; nt < 4; nt++)
                    mma_tf32(acc[1][nt], a0, a1, a2, a3,
                             wf[nt][kt][0], wf[nt][kt][1]);
            }
        }

        {
            float* zw = sZ + warp*(32*33);
            int rr = lane >> 2;
            int cc = (lane & 3)*2;
            #pragma unroll
            for (int mi = 0; mi < 2; mi++) {
                if (mi == 1 && !act_hi) break;
                #pragma unroll
                for (int nt = 0; nt < 4; nt++) {
                    int col = nt*8 + cc;
                    int row = mi*16 + rr;
                    zw[col*33 + row]       = acc[mi][nt][0];
                    zw[(col+1)*33 + row]   = acc[mi][nt][1];
                    zw[col*33 + row + 8]   = acc[mi][nt][2];
                    zw[(col+1)*33 + row+8] = acc[mi][nt][3];
                }
            }
        }
        __syncthreads();

        float zg4[4] = {xg0, xg1, xg2, xg3};
        #pragma unroll
        for (int g = 0; g < 4; g++) {
            int col = g*8 + cu;
            #pragma unroll
            for (int w = 0; w < 8; w++)
                zg4[g] += sZ[w*(32*33) + col*33 + cb];
        }
        float cn = sigmf_(zg4[1])*creg + sigmf_(zg4[0])*tanhf(zg4[2]);
        float hn = sigmf_(zg4[3])*tanhf(cn);
        bool msk = (s < mylen);
        creg = msk ? cn : creg;
        hreg = msk ? hn : hreg;
        hout[cb*NH + u0 + cu] = hreg;
        g_enc_out[((size_t)(s*NB + cb))*NH + u0 + cu] = msk ? hreg : 0.0f;

        gridbar();
    }

    g_h[cb*NH + u0 + cu] = hreg;
    g_c[cb*NH + u0 + cu] = creg;
}

// ------------------------- persistent decoder helpers -----------------------
__device__ __forceinline__ void dec_feat(int tt, const float* __restrict__ hsrc,
    const float* __restrict__ out_W, const float* __restrict__ out_b,
    float* sH, float* sZ, int fn0)
{
    int tid = threadIdx.x;
    int r   = tid >> 6;
    int fks = (tid >> 5) & 1;
    int fb  = tid & 31;
    int lb  = tid >> 3;
    int lq  = tid & 7;
    const float* wrow = out_W + (size_t)(fn0 + r)*(2*NH);
    float fa = 0.f;

    float4 p0, p1, p2, p3;
    {
        const float* hr = hsrc + lb*NH;
        p0 = __ldcg((const float4*)&hr[4*lq]);
        p1 = __ldcg((const float4*)&hr[4*(lq+8)]);
        p2 = __ldcg((const float4*)&hr[4*(lq+16)]);
        p3 = __ldcg((const float4*)&hr[4*(lq+24)]);
        stash4(sH, lq, lb, p0, p1, p2, p3);
    }
    __syncthreads();

    for (int ch = 0; ch < 16; ch++) {
        float* cur = sH + (ch & 1)*(128*36);
        if (ch < 15) {
            int cn_ = ch + 1;
            const float* src = (cn_ < 8) ? hsrc : g_ctx;
            const float* hr = src + lb*NH + (cn_ & 7)*128;
            p0 = __ldcg((const float4*)&hr[4*lq]);
            p1 = __ldcg((const float4*)&hr[4*(lq+8)]);
            p2 = __ldcg((const float4*)&hr[4*(lq+16)]);
            p3 = __ldcg((const float4*)&hr[4*(lq+24)]);
        }
        const float* wc = wrow + ch*128 + fks*64;
        const float* hc = cur + fks*64*36 + fb;
        #pragma unroll 16
        for (int k = 0; k < 64; k++)
            fa += __ldg(&wc[k]) * hc[k*36];
        if (ch < 15)
            stash4(sH + ((ch & 1) ^ 1)*(128*36), lq, lb, p0, p1, p2, p3);
        __syncthreads();
    }
    sZ[(r*2 + fks)*33 + fb] = fa;
    __syncthreads();
    if (tid < 128) {
        int rr = tid >> 5, bb = tid & 31;
        float v = sZ[(rr*2)*33 + bb] + sZ[(rr*2+1)*33 + bb] + __ldg(&out_b[fn0 + rr]);
        g_feat[((size_t)(tt*NB + bb))*ND + fn0 + rr] = v;
    }
    __syncthreads();
}

__device__ __forceinline__ void dec_attn(int b, int mylen,
    const float* __restrict__ hcur,
    const float* __restrict__ ak_W, const float* __restrict__ ak_b,
    float* sW)
{
    int tid = threadIdx.x;
    float* sh_ = sW;
    float* sak = sW + 1024;
    float* se  = sW + 1152;
    float* sr  = sW + 1280;

    for (int i = tid; i < NH; i += 256) sh_[i] = __ldcg(&hcur[b*NH + i]);
    __syncthreads();

    if (tid < NK) {
        const float* wr = ak_W + (size_t)tid*NH;
        float acc0 = 0.f, acc1 = 0.f;
        for (int k = 0; k < NH; k += 8) {
            float4 w0 = *(const float4*)&wr[k];
            float4 w1 = *(const float4*)&wr[k+4];
            float4 h0 = *(const float4*)&sh_[k];
            float4 h1 = *(const float4*)&sh_[k+4];
            acc0 += w0.x*h0.x + w0.y*h0.y + w0.z*h0.z + w0.w*h0.w;
            acc1 += w1.x*h1.x + w1.y*h1.y + w1.z*h1.z + w1.w*h1.w;
        }
        sak[tid] = tanhf(acc0 + acc1 + ak_b[tid]);
    }
    __syncthreads();

    if (tid < NS) {
        const float* qr = g_qkey + ((size_t)(tid*NB + b))*NK;
        float acc = 0.f;
        for (int k = 0; k < NK; k++) acc += qr[k]*sak[k];
        se[tid] = (tid < mylen) ? acc : -INFINITY;
    }
    __syncthreads();

    sr[tid] = (tid < NS) ? se[tid] : -INFINITY;
    __syncthreads();
    for (int off = 128; off >= 1; off >>= 1) {
        if (tid < off) sr[tid] = fmaxf(sr[tid], sr[tid+off]);
        __syncthreads();
    }
    float mx = sr[0];
    __syncthreads();

    float ex = (tid < NS) ? expf(se[tid] - mx) : 0.0f;
    sr[tid] = ex;
    __syncthreads();
    for (int off = 128; off >= 1; off >>= 1) {
        if (tid < off) sr[tid] += sr[tid+off];
        __syncthreads();
    }
    float inv = 1.0f / sr[0];
    __syncthreads();
    if (tid < NS) g_attw[b*NS + tid] = ex * inv;
    __syncthreads();
}

// ------------------------- persistent decoder -------------------------------
__global__ void __launch_bounds__(256, 1)
k_dec_persist(const float* __restrict__ dec_Wih, const float* __restrict__ dec_Whh,
              const float* __restrict__ ak_W,   const float* __restrict__ ak_b,
              const float* __restrict__ out_W,  const float* __restrict__ out_b,
              const int* __restrict__ lengths)
{
    extern __shared__ float sm[];
    float* sW = sm;                     // 2 x [128][36]
    float* sH = sm + 2*128*36;          // 2 x [128][36]
    float* sZ = sm + 4*128*36;          // [4][32][33]

    int tid = threadIdx.x;
    int blk = blockIdx.x;
    int u0  = blk * 8;
    int fn0 = blk * 4;

    int cb = tid & 31, cu = tid >> 5;
    float creg = g_c[cb*NH + u0 + cu];

    int rq = tid & 7;
    int bq = (tid >> 3) & 7;
    int ks = tid >> 6;
    int lb = tid >> 3;
    int lq = tid & 7;
    int wr_ = tid >> 3;
    int wn_ = (wr_ >> 3)*NH + u0 + (wr_ & 7);

    int mylen = (blk < 32) ? lengths[blk] : 0;

    for (int t = 0; t < NT; t++) {
        const float* hcur = (t == 0) ? g_h : (g_hbuf + ((t-1) & 1)*(NB*NH));
        float*       hnew = g_hbuf + (t & 1)*(NB*NH);

        if (t > 0)
            dec_feat(t-1, hcur, out_W, out_b, sH, sZ, fn0);
        if (blk < 32)
            dec_attn(blk, mylen, hcur, ak_W, ak_b, sW);
        gridbar();

        // ---- context ----
        {
            int b  = blk & 31;
            int hq = blk >> 5;
            if (tid < NS) sZ[tid] = __ldcg(&g_attw[b*NS + tid]);
            __syncthreads();
            int hh = hq*256 + tid;
            float a0 = 0.f, a1 = 0.f, a2 = 0.f, a3 = 0.f;
            #pragma unroll 4
            for (int s = 0; s < NS; s += 4) {
                a0 += sZ[s+0]*__ldg(&g_qval[((size_t)((s+0)*NB + b))*NH + hh]);
                a1 += sZ[s+1]*__ldg(&g_qval[((size_t)((s+1)*NB + b))*NH + hh]);
                a2 += sZ[s+2]*__ldg(&g_qval[((size_t)((s+2)*NB + b))*NH + hh]);
                a3 += sZ[s+3]*__ldg(&g_qval[((size_t)((s+3)*NB + b))*NH + hh]);
            }
            g_ctx[b*NH + hh] = (a0 + a1) + (a2 + a3);
            __syncthreads();
        }
        gridbar();

        const float* xp = g_dxe + ((size_t)t*NG + u0 + cu)*32 + cb;
        float xg0 = __ldg(&xp[0]);
        float xg1 = __ldg(&xp[(size_t)NH*32]);
        float xg2 = __ldg(&xp[(size_t)2*NH*32]);
        float xg3 = __ldg(&xp[(size_t)3*NH*32]);

        // ---- z GEMM, double-buffered W and H, f32x2 core ----
        ull_t acc2[4][2] = {};
        float4 pH0, pH1, pH2, pH3, pW0, pW1, pW2, pW3;
        {
            const float* hr = hcur + lb*NH;
            pH0 = __ldcg((const float4*)&hr[4*lq]);
            pH1 = __ldcg((const float4*)&hr[4*(lq+8)]);
            pH2 = __ldcg((const float4*)&hr[4*(lq+16)]);
            pH3 = __ldcg((const float4*)&hr[4*(lq+24)]);
            const float* wrow = dec_Whh + (size_t)wn_*NH;
            pW0 = __ldg((const float4*)&wrow[4*lq]);
            pW1 = __ldg((const float4*)&wrow[4*(lq+8)]);
            pW2 = __ldg((const float4*)&wrow[4*(lq+16)]);
            pW3 = __ldg((const float4*)&wrow[4*(lq+24)]);
            stash4(sH, lq, lb, pH0, pH1, pH2, pH3);
            stash4(sW, lq, wr_, pW0, pW1, pW2, pW3);
        }
        __syncthreads();

        for (int ch = 0; ch < 16; ch++) {
            float* curW = sW + (ch & 1)*(128*36);
            float* curH = sH + (ch & 1)*(128*36);
            if (ch < 15) {
                int cn_ = ch + 1;
                const float* asrc = (cn_ < 8) ? hcur : g_ctx;
                int kc = (cn_ & 7)*128;
                const float* hr = asrc + lb*NH + kc;
                pH0 = __ldcg((const float4*)&hr[4*lq]);
                pH1 = __ldcg((const float4*)&hr[4*(lq+8)]);
                pH2 = __ldcg((const float4*)&hr[4*(lq+16)]);
                pH3 = __ldcg((const float4*)&hr[4*(lq+24)]);
                const float* wrow = (cn_ < 8)
                    ? (dec_Whh + (size_t)wn_*NH + kc)
                    : (dec_Wih + (size_t)wn_*(ND+NH) + ND + kc);
                pW0 = __ldg((const float4*)&wrow[4*lq]);
                pW1 = __ldg((const float4*)&wrow[4*(lq+8)]);
                pW2 = __ldg((const float4*)&wrow[4*(lq+16)]);
                pW3 = __ldg((const float4*)&wrow[4*(lq+24)]);
            }
            for (int kb = 0; kb < 128; kb += 16) {
                int k = kb + 4*ks;
                #pragma unroll
                for (int kk2 = 0; kk2 < 4; kk2++) {
                    float4 wv = *(const float4*)&curW[(k+kk2)*36 + 4*rq];
                    ulonglong2 hq2 = *(const ulonglong2*)&curH[(k+kk2)*36 + 4*bq];
                    ull_t d0 = dup2(wv.x), d1 = dup2(wv.y);
                    ull_t d2 = dup2(wv.z), d3 = dup2(wv.w);
                    ffma2(acc2[0][0], d0, hq2.x); ffma2(acc2[0][1], d0, hq2.y);
                    ffma2(acc2[1][0], d1, hq2.x); ffma2(acc2[1][1], d1, hq2.y);
                    ffma2(acc2[2][0], d2, hq2.x); ffma2(acc2[2][1], d2, hq2.y);
                    ffma2(acc2[3][0], d3, hq2.x); ffma2(acc2[3][1], d3, hq2.y);
                }
            }
            if (ch < 15) {
                stash4(sH + ((ch & 1) ^ 1)*(128*36), lq, lb, pH0, pH1, pH2, pH3);
                stash4(sW + ((ch & 1) ^ 1)*(128*36), lq, wr_, pW0, pW1, pW2, pW3);
            }
            __syncthreads();
        }

        #pragma unroll
        for (int i = 0; i < 4; i++) {
            float2 t0 = unpk(acc2[i][0]);
            float2 t1 = unpk(acc2[i][1]);
            float* zr = &sZ[(ks*32 + 4*rq + i)*33 + 4*bq];
            zr[0] = t0.x; zr[1] = t0.y; zr[2] = t1.x; zr[3] = t1.y;
        }
        __syncthreads();

        {
            float zg4[4] = {xg0, xg1, xg2, xg3};
            #pragma unroll
            for (int g = 0; g < 4; g++)
                #pragma unroll
                for (int q = 0; q < 4; q++) zg4[g] += sZ[(q*32 + g*8 + cu)*33 + cb];
            float cn = sigmf_(zg4[1])*creg + sigmf_(zg4[0])*tanhf(zg4[2]);
            float hn = sigmf_(zg4[3])*tanhf(cn);
            creg = cn;
            hnew[cb*NH + u0 + cu] = hn;
        }
        __syncthreads();
        gridbar();
    }

    {
        const float* hlast = g_hbuf + ((NT-1) & 1)*(NB*NH);
        dec_feat(NT-1, hlast, out_W, out_b, sH, sZ, fn0);
    }
}

// =============================================================================
extern "C" void kernel_launch(void* const* d_in, const int* in_sizes, int n_in,
                              void* d_out, int out_size)
{
    const float* embed    = (const float*)d_in[0];
    const float* enc_Wih  = (const float*)d_in[1];
    const float* enc_Whh  = (const float*)d_in[2];
    const float* enc_bih  = (const float*)d_in[3];
    const float* enc_bhh  = (const float*)d_in[4];
    const float* dec_Wih  = (const float*)d_in[5];
    const float* dec_Whh  = (const float*)d_in[6];
    const float* dec_bih  = (const float*)d_in[7];
    const float* dec_bhh  = (const float*)d_in[8];
    const float* qk_W     = (const float*)d_in[9];
    const float* qk_b     = (const float*)d_in[10];
    const float* qv_W     = (const float*)d_in[11];
    const float* qv_b     = (const float*)d_in[12];
    const float* ak_W     = (const float*)d_in[13];
    const float* ak_b     = (const float*)d_in[14];
    const float* out_W    = (const float*)d_in[15];
    const float* out_b    = (const float*)d_in[16];
    const float* wd_b     = (const float*)d_in[17];
    const float* hfc1_W   = (const float*)d_in[18];
    const float* hfc1_b   = (const float*)d_in[19];
    const float* hfc2_W   = (const float*)d_in[20];
    const float* hfc2_b   = (const float*)d_in[21];
    const float* cfc1_W   = (const float*)d_in[22];
    const float* cfc1_b   = (const float*)d_in[23];
    const float* cfc2_W   = (const float*)d_in[24];
    const float* cfc2_b   = (const float*)d_in[25];
    const int*   src_seqs = (const int*)d_in[26];
    const int*   src_len  = (const int*)d_in[27];
    const int*   trg_seqs = (const int*)d_in[28];
    float* out = (float*)d_out;

    float *d_src_embed, *d_ans_embed, *d_xproj, *d_dxe, *d_h, *d_c;
    float *d_enc_out, *d_qkey, *d_qval, *d_tmp, *d_feat;
    cudaGetSymbolAddress((void**)&d_src_embed, g_src_embed);
    cudaGetSymbolAddress((void**)&d_ans_embed, g_ans_embed);
    cudaGetSymbolAddress((void**)&d_xproj,     g_xproj);
    cudaGetSymbolAddress((void**)&d_dxe,       g_dxe);
    cudaGetSymbolAddress((void**)&d_h,         g_h);
    cudaGetSymbolAddress((void**)&d_c,         g_c);
    cudaGetSymbolAddress((void**)&d_enc_out,   g_enc_out);
    cudaGetSymbolAddress((void**)&d_qkey,      g_qkey);
    cudaGetSymbolAddress((void**)&d_qval,      g_qval);
    cudaGetSymbolAddress((void**)&d_tmp,       g_tmp);
    cudaGetSymbolAddress((void**)&d_feat,      g_feat);

    // ---- precompute ----
    k_gather<<<NS*NB, 128>>>(src_seqs, NS, embed, d_src_embed);
    k_gather<<<NT*NB, 128>>>(trg_seqs, 20, embed, d_ans_embed);

    k_sgemm<<<dim3(NG/64, (NS*NB)/128), 256>>>(NS*NB, NG, ND,
        d_src_embed, ND, enc_Wih, ND, enc_bih, enc_bhh, d_xproj, NG, 0, 2, 0);
    k_sgemm<<<dim3(NG/64, (NT*NB + 127)/128), 256>>>(NT*NB, NG, ND,
        d_ans_embed, ND, dec_Wih, ND + NH, dec_bih, dec_bhh, d_dxe, NG, 0, 2, 0);

    // ---- encoder recurrence: tensor-core persistent kernel ----
    const int enc_smem = (32*HPITCH + 8*32*33) * (int)sizeof(float);
    cudaFuncSetAttribute(k_enc_persist,
                         cudaFuncAttributeMaxDynamicSharedMemorySize, enc_smem);
    k_enc_persist<<<NBLK, 256, enc_smem>>>(enc_Whh, src_len);

    // ---- bridge MLPs ----
    k_sgemm<<<dim3(2048/64, 1), 256>>>(NB, 2048, NH, d_h, NH, hfc1_W, NH,
                                       hfc1_b, nullptr, d_tmp, 2048, 2, 0, 0);
    k_sgemm<<<dim3(NH/64, 1), 256>>>(NB, NH, 2048, d_tmp, 2048, hfc2_W, 2048,
                                     hfc2_b, nullptr, d_h, NH, 0, 0, 0);
    k_sgemm<<<dim3(2048/64, 1), 256>>>(NB, 2048, NH, d_c, NH, cfc1_W, NH,
                                       cfc1_b, nullptr, d_tmp, 2048, 2, 0, 0);
    k_sgemm<<<dim3(NH/64, 1), 256>>>(NB, NH, 2048, d_tmp, 2048, cfc2_W, 2048,
                                     cfc2_b, nullptr, d_c, NH, 0, 0, 0);

    // ---- attention precompute ----
    k_sgemm<<<dim3((NK + 63)/64, (NS*NB)/128), 256>>>(NS*NB, NK, NH,
        d_enc_out, NH, qk_W, NH, qk_b, nullptr, d_qkey, NK, 1, 0, 0);
    k_sgemm<<<dim3(NH/64, (NS*NB)/128), 256>>>(NS*NB, NH, NH,
        d_enc_out, NH, qv_W, NH, qv_b, nullptr, d_qval, NH, 0, 0, 0);

    // ---- decoder recurrence ----
    const int dec_smem = (4*128*36 + 4*32*33) * (int)sizeof(float);
    cudaFuncSetAttribute(k_dec_persist,
                         cudaFuncAttributeMaxDynamicSharedMemorySize, dec_smem);
    k_dec_persist<<<NBLK, 256, dec_smem>>>(dec_Wih, dec_Whh, ak_W, ak_b,
                                           out_W, out_b, src_len);

    // ---- final logits: swap_grid so adjacent blocks share embed n-tiles ----
    k_sgemm<<<dim3((NT*NB + 127)/128, NV/64), 256>>>(NT*NB, NV, ND,
        d_feat, ND, embed, ND, wd_b, nullptr, out, NV, 0, 1, 1);

    (void)in_sizes; (void)n_in; (void)out_size;
}